// round 2
// baseline (speedup 1.0000x reference)
#include <cuda_runtime.h>
#include <cstdint>
#include <cstddef>

// Problem constants
#define BB 8
#define TT 2048
#define CC 1024
#define HH 64

// ---------------------------------------------------------------------------
// Scratch (device globals — no allocations allowed)
// ---------------------------------------------------------------------------
__device__ float g_Q[BB * TT * HH];      // 4 MB
__device__ float g_K[BB * TT * HH];      // 4 MB
__device__ float g_V[BB * TT * HH];      // 4 MB
__device__ float g_Vp[BB * TT * HH];     // 4 MB  (V / D)
__device__ float g_D[BB * TT];           // 64 KB
__device__ float g_Dp[BB][4][TT];        // partial column sums
__device__ float g_P[33554432];          // 128 MB : exp(S) lower triangle, B*T*T

// ---------------------------------------------------------------------------
// K1: fused QKV projection.  out[m,n] = sum_c A[m,c] * W[n,c]
// A: [16384,1024] row-major, W: [64,1024] row-major (torch Linear layout)
// Grid: (16384/128, 3). 256 threads. BM=128 BN=64 BK=32, thread tile 8x4.
// ---------------------------------------------------------------------------
__global__ __launch_bounds__(256) void proj_kernel(
    const float* __restrict__ A,
    const float* __restrict__ Wk,
    const float* __restrict__ Wq,
    const float* __restrict__ Wv)
{
    __shared__ float As[32][132];   // [k][m], padded
    __shared__ float Ws[32][68];    // [k][n], padded

    const int tid = threadIdx.x;
    const int m0  = blockIdx.x * 128;

    const float* W;
    float* O;
    if (blockIdx.y == 0)      { W = Wq; O = g_Q; }
    else if (blockIdx.y == 1) { W = Wk; O = g_K; }
    else                      { W = Wv; O = g_V; }

    const int tx = tid & 15;        // n dir (4 cols each)
    const int ty = tid >> 4;        // m dir (8 rows each)
    const int lc = (tid & 7) * 4;   // load col within k-tile
    const int lr = tid >> 3;        // load row base (0..31)

    float acc[8][4];
#pragma unroll
    for (int i = 0; i < 8; ++i)
#pragma unroll
        for (int j = 0; j < 4; ++j) acc[i][j] = 0.f;

    for (int c0 = 0; c0 < CC; c0 += 32) {
        // load A tile 128x32 (transposed into smem)
#pragma unroll
        for (int p = 0; p < 4; ++p) {
            int r = lr + p * 32;
            float4 a = *reinterpret_cast<const float4*>(
                &A[(size_t)(m0 + r) * CC + c0 + lc]);
            As[lc + 0][r] = a.x; As[lc + 1][r] = a.y;
            As[lc + 2][r] = a.z; As[lc + 3][r] = a.w;
        }
        // load W tile 64x32 (transposed into smem)
#pragma unroll
        for (int p = 0; p < 2; ++p) {
            int r = lr + p * 32;
            float4 w = *reinterpret_cast<const float4*>(
                &W[(size_t)r * CC + c0 + lc]);
            Ws[lc + 0][r] = w.x; Ws[lc + 1][r] = w.y;
            Ws[lc + 2][r] = w.z; Ws[lc + 3][r] = w.w;
        }
        __syncthreads();

#pragma unroll 8
        for (int kk = 0; kk < 32; ++kk) {
            float4 a0 = *reinterpret_cast<const float4*>(&As[kk][ty * 8]);
            float4 a1 = *reinterpret_cast<const float4*>(&As[kk][ty * 8 + 4]);
            float4 w  = *reinterpret_cast<const float4*>(&Ws[kk][tx * 4]);
            float av[8] = {a0.x, a0.y, a0.z, a0.w, a1.x, a1.y, a1.z, a1.w};
            float wv[4] = {w.x, w.y, w.z, w.w};
#pragma unroll
            for (int i = 0; i < 8; ++i)
#pragma unroll
                for (int j = 0; j < 4; ++j)
                    acc[i][j] += av[i] * wv[j];
        }
        __syncthreads();
    }

#pragma unroll
    for (int i = 0; i < 8; ++i) {
        float4 o = make_float4(acc[i][0], acc[i][1], acc[i][2], acc[i][3]);
        *reinterpret_cast<float4*>(
            &O[(size_t)(m0 + ty * 8 + i) * HH + tx * 4]) = o;
    }
}

// ---------------------------------------------------------------------------
// K2: S = Q K^T tile, masked exp, write P (lower-triangular tiles only).
// Grid: (T/64, T/64, B). 256 threads, thread tile 4x4, K = H = 64 (one shot).
// Diagonal tiles write 0 where t < s; strictly-upper tiles are skipped
// (never written, never read -> stay at BSS zero).
// ---------------------------------------------------------------------------
__global__ __launch_bounds__(256) void qk_exp_kernel()
{
    const int t0 = blockIdx.x * 64;
    const int s0 = blockIdx.y * 64;
    const int b  = blockIdx.z;
    if (s0 > t0 + 63) return;   // fully masked tile

    __shared__ float Qs[64][68];  // [h][t]
    __shared__ float Ks[64][68];  // [h][s]

    const int tid = threadIdx.x;
    const int lc = (tid & 15) * 4;
    const int lr = tid >> 4;            // 0..15

    const float* Qb = g_Q + (size_t)b * TT * HH;
    const float* Kb = g_K + (size_t)b * TT * HH;

#pragma unroll
    for (int p = 0; p < 4; ++p) {
        int r = lr + p * 16;
        float4 q = *reinterpret_cast<const float4*>(
            &Qb[(size_t)(t0 + r) * HH + lc]);
        Qs[lc + 0][r] = q.x; Qs[lc + 1][r] = q.y;
        Qs[lc + 2][r] = q.z; Qs[lc + 3][r] = q.w;
        float4 k = *reinterpret_cast<const float4*>(
            &Kb[(size_t)(s0 + r) * HH + lc]);
        Ks[lc + 0][r] = k.x; Ks[lc + 1][r] = k.y;
        Ks[lc + 2][r] = k.z; Ks[lc + 3][r] = k.w;
    }
    __syncthreads();

    const int tx = tid & 15, ty = tid >> 4;
    const int tm = ty * 4, tn = tx * 4;
    float acc[4][4] = {};

#pragma unroll 8
    for (int kk = 0; kk < 64; ++kk) {
        float4 qa = *reinterpret_cast<const float4*>(&Qs[kk][tm]);
        float4 kb = *reinterpret_cast<const float4*>(&Ks[kk][tn]);
        float qv[4] = {qa.x, qa.y, qa.z, qa.w};
        float kv[4] = {kb.x, kb.y, kb.z, kb.w};
#pragma unroll
        for (int i = 0; i < 4; ++i)
#pragma unroll
            for (int j = 0; j < 4; ++j)
                acc[i][j] += qv[i] * kv[j];
    }

    float* Pb = g_P + (size_t)b * TT * TT;
#pragma unroll
    for (int i = 0; i < 4; ++i) {
        int tg = t0 + tm + i;
        int sg = s0 + tn;
        float4 o;
        o.x = (tg >= sg + 0) ? __expf(acc[i][0]) : 0.f;
        o.y = (tg >= sg + 1) ? __expf(acc[i][1]) : 0.f;
        o.z = (tg >= sg + 2) ? __expf(acc[i][2]) : 0.f;
        o.w = (tg >= sg + 3) ? __expf(acc[i][3]) : 0.f;
        *reinterpret_cast<float4*>(&Pb[(size_t)tg * TT + sg]) = o;
    }
}

// ---------------------------------------------------------------------------
// K3a: partial column sums D_s = sum_{t>=s} P[t][s], chunked over t.
// Grid: (T/128, 4, B). 256 threads: 128 cols x 2-way t interleave.
// ---------------------------------------------------------------------------
__global__ __launch_bounds__(256) void colsum_partial()
{
    const int s0  = blockIdx.x * 128;
    const int ch  = blockIdx.y;   // 0..3
    const int b   = blockIdx.z;
    const int tid = threadIdx.x;
    const int col = s0 + (tid & 127);
    const int r   = tid >> 7;     // 0..1

    const int tlo = ch * 512;
    const int thi = tlo + 512;
    int tstart = (tlo > s0) ? tlo : s0;   // rows < s0 never written (all masked)

    const float* Pb = g_P + (size_t)b * TT * TT;
    float acc = 0.f;
    for (int t = tstart + r; t < thi; t += 2)
        acc += Pb[(size_t)t * TT + col];

    __shared__ float red[256];
    red[tid] = acc;
    __syncthreads();
    if (r == 0)
        g_Dp[b][ch][col] = red[tid] + red[tid + 128];
}

// K3b: reduce the 4 partials
__global__ __launch_bounds__(256) void colsum_reduce()
{
    int i = blockIdx.x * 256 + threadIdx.x;    // < B*T
    int b = i >> 11;
    int s = i & 2047;
    g_D[i] = g_Dp[b][0][s] + g_Dp[b][1][s] + g_Dp[b][2][s] + g_Dp[b][3][s];
}

// ---------------------------------------------------------------------------
// K4: V' = V / D (fold the column normalizer into V)
// ---------------------------------------------------------------------------
__global__ __launch_bounds__(256) void vscale_kernel()
{
    int i = blockIdx.x * 256 + threadIdx.x;    // < B*T*H
    g_Vp[i] = g_V[i] / g_D[i >> 6];            // i/H gives (b*T + s)
}

// ---------------------------------------------------------------------------
// K5: out = P * V'  (per batch, M=2048, N=64, K only up to the diagonal)
// Grid: (T/64, B). 256 threads, BM=64 BN=64 BK=32, thread tile 4x4.
// ---------------------------------------------------------------------------
__global__ __launch_bounds__(256) void pv_kernel(float* __restrict__ out)
{
    const int t0 = blockIdx.x * 64;
    const int b  = blockIdx.y;

    __shared__ float Ps[32][68];  // [s][t]
    __shared__ float Vs[32][68];  // [s][h]

    const int tid = threadIdx.x;
    const float* Pb = g_P  + (size_t)b * TT * TT;
    const float* Vb = g_Vp + (size_t)b * TT * HH;

    const int tx = tid & 15, ty = tid >> 4;
    const int tm = ty * 4, tn = tx * 4;
    const int pc = (tid & 7) * 4;    // P loader col (0..31)
    const int pr = tid >> 3;         // P loader row base (0..31)
    const int vc = (tid & 15) * 4;   // V loader col (0..63)
    const int vr = tid >> 4;         // V loader row base (0..15)

    float acc[4][4] = {};

    for (int s0 = 0; s0 < t0 + 64; s0 += 32) {
#pragma unroll
        for (int p = 0; p < 2; ++p) {
            int r = pr + p * 32;
            float4 pv = *reinterpret_cast<const float4*>(
                &Pb[(size_t)(t0 + r) * TT + s0 + pc]);
            Ps[pc + 0][r] = pv.x; Ps[pc + 1][r] = pv.y;
            Ps[pc + 2][r] = pv.z; Ps[pc + 3][r] = pv.w;
        }
#pragma unroll
        for (int p = 0; p < 2; ++p) {
            int r = vr + p * 16;
            *reinterpret_cast<float4*>(&Vs[r][vc]) =
                *reinterpret_cast<const float4*>(
                    &Vb[(size_t)(s0 + r) * HH + vc]);
        }
        __syncthreads();

#pragma unroll 8
        for (int kk = 0; kk < 32; ++kk) {
            float4 pa = *reinterpret_cast<const float4*>(&Ps[kk][tm]);
            float4 vb = *reinterpret_cast<const float4*>(&Vs[kk][tn]);
            float pv4[4] = {pa.x, pa.y, pa.z, pa.w};
            float vv4[4] = {vb.x, vb.y, vb.z, vb.w};
#pragma unroll
            for (int i = 0; i < 4; ++i)
#pragma unroll
                for (int j = 0; j < 4; ++j)
                    acc[i][j] += pv4[i] * vv4[j];
        }
        __syncthreads();
    }

#pragma unroll
    for (int i = 0; i < 4; ++i) {
        float4 o = make_float4(acc[i][0], acc[i][1], acc[i][2], acc[i][3]);
        *reinterpret_cast<float4*>(
            &out[(size_t)(b * TT + t0 + tm + i) * HH + tn]) = o;
    }
}

// ---------------------------------------------------------------------------
// Launch
// ---------------------------------------------------------------------------
extern "C" void kernel_launch(void* const* d_in, const int* in_sizes, int n_in,
                              void* d_out, int out_size)
{
    (void)in_sizes; (void)n_in; (void)out_size;
    const float* idx = (const float*)d_in[0];
    const float* Wk  = (const float*)d_in[1];
    const float* Wq  = (const float*)d_in[2];
    const float* Wv  = (const float*)d_in[3];
    float* out = (float*)d_out;

    proj_kernel<<<dim3(BB * TT / 128, 3), 256>>>(idx, Wk, Wq, Wv);
    qk_exp_kernel<<<dim3(TT / 64, TT / 64, BB), 256>>>();
    colsum_partial<<<dim3(TT / 128, 4, BB), 256>>>();
    colsum_reduce<<<(BB * TT) / 256, 256>>>();
    vscale_kernel<<<(BB * TT * HH) / 256, 256>>>();
    pv_kernel<<<dim3(TT / 64, BB), 256>>>(out);
}

// round 5
// speedup vs baseline: 1.7382x; 1.7382x over previous
#include <cuda_runtime.h>
#include <cuda_bf16.h>
#include <cstdint>
#include <cstddef>

#define BB 8
#define TT 2048
#define CC 1024
#define HH 64

// ---------------------------------------------------------------------------
// Scratch (device globals; no allocations allowed)
// ---------------------------------------------------------------------------
__device__ __nv_bfloat16 g_Qhi[BB * TT * HH];
__device__ __nv_bfloat16 g_Qlo[BB * TT * HH];
__device__ __nv_bfloat16 g_Khi[BB * TT * HH];
__device__ __nv_bfloat16 g_Klo[BB * TT * HH];
__device__ float         g_V[BB * TT * HH];
__device__ __nv_bfloat16 g_VThi[BB * HH * TT];   // V' transposed [b][h][s]
__device__ __nv_bfloat16 g_VTlo[BB * HH * TT];
__device__ float         g_Dp[BB][4][TT];        // colsum partials
__device__ float         g_D[BB * TT];
__device__ float         g_O4[4][BB * TT * HH];  // 4-way split-s partial outputs

// ---------------------------------------------------------------------------
// Helpers: smem addr, swizzle, ldmatrix, mma (all plain sm_80+ PTX, no 'a')
// ---------------------------------------------------------------------------
__device__ __forceinline__ uint32_t smem_u32(const void* p) {
    uint32_t r;
    asm("{ .reg .u64 t; cvta.to.shared.u64 t, %1; cvt.u32.u64 %0, t; }"
        : "=r"(r) : "l"(p));
    return r;
}
__device__ __forceinline__ uint32_t swz(uint32_t o) { return o ^ ((o >> 3) & 0x70); }

__device__ __forceinline__ void ldsm4(uint32_t (&r)[4], uint32_t addr) {
    asm volatile("ldmatrix.sync.aligned.m8n8.x4.shared.b16 {%0,%1,%2,%3}, [%4];"
                 : "=r"(r[0]), "=r"(r[1]), "=r"(r[2]), "=r"(r[3]) : "r"(addr));
}
__device__ __forceinline__ void ldsm2(uint32_t (&r)[2], uint32_t addr) {
    asm volatile("ldmatrix.sync.aligned.m8n8.x2.shared.b16 {%0,%1}, [%2];"
                 : "=r"(r[0]), "=r"(r[1]) : "r"(addr));
}
__device__ __forceinline__ void mma16816(float (&c)[4], const uint32_t (&a)[4],
                                         const uint32_t (&b)[2]) {
    asm volatile(
        "mma.sync.aligned.m16n8k16.row.col.f32.bf16.bf16.f32 "
        "{%0,%1,%2,%3}, {%4,%5,%6,%7}, {%8,%9}, {%0,%1,%2,%3};"
        : "+f"(c[0]), "+f"(c[1]), "+f"(c[2]), "+f"(c[3])
        : "r"(a[0]), "r"(a[1]), "r"(a[2]), "r"(a[3]), "r"(b[0]), "r"(b[1]));
}

// A-fragment: 16x16 bf16, row-major tile rows = mr.., k-bytes = kb..kb+31
__device__ __forceinline__ void lda(uint32_t (&a)[4], uint32_t base, int mr,
                                    int kb, int lane) {
    ldsm4(a, base + swz(((mr + (lane & 15)) << 7) + kb + ((lane >> 4) << 4)));
}
// B-fragment: k16 x n8, from [n][k] row-major tile rows = nr.., k-bytes = kb
__device__ __forceinline__ void ldb(uint32_t (&b)[2], uint32_t base, int nr,
                                    int kb, int lane) {
    ldsm2(b, base + swz(((nr + (lane & 7)) << 7) + kb + (((lane >> 3) & 1) << 4)));
}

__device__ __forceinline__ void split_bf16(float x, __nv_bfloat16& h, __nv_bfloat16& l) {
    h = __float2bfloat16(x);
    l = __float2bfloat16(x - __bfloat162float(h));
}
__device__ __forceinline__ void splitpack2(float x, float y, uint32_t& hi, uint32_t& lo) {
    __nv_bfloat16 hx, lx, hy, ly;
    split_bf16(x, hx, lx); split_bf16(y, hy, ly);
    __nv_bfloat162 H = __halves2bfloat162(hx, hy);
    __nv_bfloat162 L = __halves2bfloat162(lx, ly);
    hi = *(uint32_t*)&H; lo = *(uint32_t*)&L;
}

// ---------------------------------------------------------------------------
// K1: QKV projection. Grid (128, 3), 256 threads (8 warps: 4m x 2n).
// Per CTA: 128 rows x 64 cols, K=1024 chunked by 64.
// smem: Ah(16K) Al(16K) Wh(8K) Wl(8K) = 49152
// ---------------------------------------------------------------------------
__global__ void __launch_bounds__(256) proj_mma(
    const float* __restrict__ A,
    const float* __restrict__ Wk,
    const float* __restrict__ Wq,
    const float* __restrict__ Wv)
{
    extern __shared__ char smem[];
    char* Ah = smem;
    char* Al = smem + 16384;
    char* Wh = smem + 32768;
    char* Wl = smem + 40960;
    const uint32_t sAh = smem_u32(Ah), sAl = sAh + 16384;
    const uint32_t sWh = sAh + 32768, sWl = sAh + 40960;

    const int tid = threadIdx.x, wid = tid >> 5, lane = tid & 31;
    const int wm = wid >> 1, wn = wid & 1;
    const int gid = lane >> 2, tig = lane & 3;
    const int m0 = blockIdx.x * 128;

    const float* W = (blockIdx.y == 0) ? Wq : (blockIdx.y == 1) ? Wk : Wv;

    float acc[2][4][4];
#pragma unroll
    for (int i = 0; i < 2; ++i)
#pragma unroll
        for (int j = 0; j < 4; ++j)
#pragma unroll
            for (int k = 0; k < 4; ++k) acc[i][j][k] = 0.f;

    for (int ch = 0; ch < 16; ++ch) {
        const int c0 = ch * 64;
#pragma unroll
        for (int i = 0; i < 16; ++i) {        // A 128x64 fp32 -> hi/lo
            int p = i * 256 + tid, r = p >> 5, cp = p & 31;
            float2 a = *(const float2*)&A[(size_t)(m0 + r) * CC + c0 + cp * 2];
            uint32_t hi, lo; splitpack2(a.x, a.y, hi, lo);
            uint32_t off = swz(r * 128 + cp * 4);
            *(uint32_t*)(Ah + off) = hi; *(uint32_t*)(Al + off) = lo;
        }
#pragma unroll
        for (int i = 0; i < 8; ++i) {         // W 64x64 fp32 -> hi/lo
            int p = i * 256 + tid, r = p >> 5, cp = p & 31;
            float2 a = *(const float2*)&W[(size_t)r * CC + c0 + cp * 2];
            uint32_t hi, lo; splitpack2(a.x, a.y, hi, lo);
            uint32_t off = swz(r * 128 + cp * 4);
            *(uint32_t*)(Wh + off) = hi; *(uint32_t*)(Wl + off) = lo;
        }
        __syncthreads();

#pragma unroll
        for (int ks = 0; ks < 4; ++ks) {
            const int kb = ks * 32;
            uint32_t ah0[4], ah1[4], al0[4], al1[4];
            lda(ah0, sAh, wm * 32, kb, lane);      lda(ah1, sAh, wm * 32 + 16, kb, lane);
            lda(al0, sAl, wm * 32, kb, lane);      lda(al1, sAl, wm * 32 + 16, kb, lane);
#pragma unroll
            for (int nf = 0; nf < 4; ++nf) {
                uint32_t bh[2], bl[2];
                ldb(bh, sWh, wn * 32 + nf * 8, kb, lane);
                ldb(bl, sWl, wn * 32 + nf * 8, kb, lane);
                mma16816(acc[0][nf], ah0, bh);
                mma16816(acc[0][nf], ah0, bl);
                mma16816(acc[0][nf], al0, bh);
                mma16816(acc[1][nf], ah1, bh);
                mma16816(acc[1][nf], ah1, bl);
                mma16816(acc[1][nf], al1, bh);
            }
        }
        __syncthreads();
    }

    // epilogue
    if (blockIdx.y == 2) {                    // V fp32
#pragma unroll
        for (int mf = 0; mf < 2; ++mf)
#pragma unroll
            for (int nf = 0; nf < 4; ++nf) {
                int m = m0 + wm * 32 + mf * 16 + gid;
                int col = wn * 32 + nf * 8 + 2 * tig;
                *(float2*)&g_V[(size_t)m * HH + col] =
                    make_float2(acc[mf][nf][0], acc[mf][nf][1]);
                *(float2*)&g_V[(size_t)(m + 8) * HH + col] =
                    make_float2(acc[mf][nf][2], acc[mf][nf][3]);
            }
    } else {
        uint32_t* oh = (blockIdx.y == 0) ? (uint32_t*)g_Qhi : (uint32_t*)g_Khi;
        uint32_t* ol = (blockIdx.y == 0) ? (uint32_t*)g_Qlo : (uint32_t*)g_Klo;
#pragma unroll
        for (int mf = 0; mf < 2; ++mf)
#pragma unroll
            for (int nf = 0; nf < 4; ++nf) {
                int m = m0 + wm * 32 + mf * 16 + gid;
                int col = wn * 32 + nf * 8 + 2 * tig;
                uint32_t hi, lo;
                splitpack2(acc[mf][nf][0], acc[mf][nf][1], hi, lo);
                size_t o = ((size_t)m * HH + col) >> 1;
                oh[o] = hi; ol[o] = lo;
                splitpack2(acc[mf][nf][2], acc[mf][nf][3], hi, lo);
                o = ((size_t)(m + 8) * HH + col) >> 1;
                oh[o] = hi; ol[o] = lo;
            }
    }
}

// ---------------------------------------------------------------------------
// K2 (pass1): D_s partials. Grid (32 s-tiles, 4 t-chunks, B), 256 threads.
// Per iter: S = Q_t K_s^T (128x64, K=64), masked exp, accumulate col sums.
// smem: Qh(16K) Ql(16K) Kh(8K) Kl(8K) red(1K) = 50176
// ---------------------------------------------------------------------------
__global__ void __launch_bounds__(256) pass1_colsum()
{
    extern __shared__ char smem[];
    char* Qh = smem;
    char* Ql = smem + 16384;
    char* Kh = smem + 32768;
    char* Kl = smem + 40960;
    float* red = (float*)(smem + 49152);      // [4][64]
    const uint32_t sQh = smem_u32(Qh), sQl = sQh + 16384;
    const uint32_t sKh = sQh + 32768, sKl = sQh + 40960;

    const int tid = threadIdx.x, wid = tid >> 5, lane = tid & 31;
    const int wm = wid >> 1, wn = wid & 1;
    const int gid = lane >> 2, tig = lane & 3;
    const int s0 = blockIdx.x * 64;
    const int ch = blockIdx.y;
    const int b  = blockIdx.z;

    // K tile (persistent)
    {
        const __nv_bfloat16* sh = g_Khi + ((size_t)b * TT + s0) * HH;
        const __nv_bfloat16* sl = g_Klo + ((size_t)b * TT + s0) * HH;
#pragma unroll
        for (int j = 0; j < 2; ++j) {
            int u = j * 256 + tid, r = u >> 3, q = u & 7;
            uint32_t off = swz(r * 128 + q * 16);
            *(uint4*)(Kh + off) = *(const uint4*)(sh + r * HH + q * 8);
            *(uint4*)(Kl + off) = *(const uint4*)(sl + r * HH + q * 8);
        }
    }

    float csum[4][2];
#pragma unroll
    for (int i = 0; i < 4; ++i) { csum[i][0] = 0.f; csum[i][1] = 0.f; }

    const int tbase = ch * 512;
    for (int t0 = tbase; t0 < tbase + 512; t0 += 128) {
        if (t0 + 128 <= s0) continue;
        {
            const __nv_bfloat16* sh = g_Qhi + ((size_t)b * TT + t0) * HH;
            const __nv_bfloat16* sl = g_Qlo + ((size_t)b * TT + t0) * HH;
#pragma unroll
            for (int j = 0; j < 4; ++j) {
                int u = j * 256 + tid, r = u >> 3, q = u & 7;
                uint32_t off = swz(r * 128 + q * 16);
                *(uint4*)(Qh + off) = *(const uint4*)(sh + r * HH + q * 8);
                *(uint4*)(Ql + off) = *(const uint4*)(sl + r * HH + q * 8);
            }
        }
        __syncthreads();

        float acc[2][4][4];
#pragma unroll
        for (int i = 0; i < 2; ++i)
#pragma unroll
            for (int j = 0; j < 4; ++j)
#pragma unroll
                for (int k = 0; k < 4; ++k) acc[i][j][k] = 0.f;

#pragma unroll
        for (int ks = 0; ks < 4; ++ks) {
            const int kb = ks * 32;
            uint32_t ah0[4], ah1[4], al0[4], al1[4];
            lda(ah0, sQh, wm * 32, kb, lane);      lda(ah1, sQh, wm * 32 + 16, kb, lane);
            lda(al0, sQl, wm * 32, kb, lane);      lda(al1, sQl, wm * 32 + 16, kb, lane);
#pragma unroll
            for (int nf = 0; nf < 4; ++nf) {
                uint32_t bh[2], bl[2];
                ldb(bh, sKh, wn * 32 + nf * 8, kb, lane);
                ldb(bl, sKl, wn * 32 + nf * 8, kb, lane);
                mma16816(acc[0][nf], ah0, bh);
                mma16816(acc[0][nf], ah0, bl);
                mma16816(acc[0][nf], al0, bh);
                mma16816(acc[1][nf], ah1, bh);
                mma16816(acc[1][nf], ah1, bl);
                mma16816(acc[1][nf], al1, bh);
            }
        }

        // masked exp + accumulate into per-thread column sums
#pragma unroll
        for (int mf = 0; mf < 2; ++mf) {
            int r0 = t0 + wm * 32 + mf * 16 + gid;
            int r1 = r0 + 8;
#pragma unroll
            for (int nf = 0; nf < 4; ++nf) {
                int c = s0 + wn * 32 + nf * 8 + 2 * tig;
                csum[nf][0] += ((r0 >= c) ? __expf(acc[mf][nf][0]) : 0.f)
                             + ((r1 >= c) ? __expf(acc[mf][nf][2]) : 0.f);
                csum[nf][1] += ((r0 >= c + 1) ? __expf(acc[mf][nf][1]) : 0.f)
                             + ((r1 >= c + 1) ? __expf(acc[mf][nf][3]) : 0.f);
            }
        }
        __syncthreads();
    }

    // reduce over gid lanes (xor 4/8/16), then over the 4 m-warps via smem
#pragma unroll
    for (int nf = 0; nf < 4; ++nf)
#pragma unroll
        for (int d = 0; d < 2; ++d) {
            float v = csum[nf][d];
            v += __shfl_xor_sync(0xffffffffu, v, 4);
            v += __shfl_xor_sync(0xffffffffu, v, 8);
            v += __shfl_xor_sync(0xffffffffu, v, 16);
            if (lane < 4)
                red[wm * 64 + wn * 32 + nf * 8 + 2 * lane + d] = v;
        }
    __syncthreads();
    if (tid < 64)
        g_Dp[b][ch][s0 + tid] =
            red[tid] + red[64 + tid] + red[128 + tid] + red[192 + tid];
}

// ---------------------------------------------------------------------------
// K3: D reduce
// ---------------------------------------------------------------------------
__global__ void __launch_bounds__(256) dreduce()
{
    int i = blockIdx.x * 256 + threadIdx.x;
    int b = i >> 11, s = i & 2047;
    g_D[i] = g_Dp[b][0][s] + g_Dp[b][1][s] + g_Dp[b][2][s] + g_Dp[b][3][s];
}

// ---------------------------------------------------------------------------
// K4: V' = V / D, transposed to [b][h][s], split hi/lo bf16.
// ---------------------------------------------------------------------------
__global__ void __launch_bounds__(256) vscale_t()
{
    __shared__ __nv_bfloat16 th[64][128];
    __shared__ __nv_bfloat16 tl[64][128];
    const int tid = threadIdx.x;
    const int s0 = blockIdx.x * 128;
    const int b  = blockIdx.y;

    for (int idx = tid; idx < 128 * 64; idx += 256) {
        int s = idx >> 6, h = idx & 63;
        float d = g_D[b * TT + s0 + s];
        float v = g_V[((size_t)b * TT + s0 + s) * HH + h] / d;
        __nv_bfloat16 hi, lo;
        split_bf16(v, hi, lo);
        th[h][s] = hi; tl[h][s] = lo;
    }
    __syncthreads();
    for (int i = tid; i < 64 * 64; i += 256) {
        int h = i >> 6, cp = i & 63;
        size_t o = ((size_t)b * HH + h) * TT + s0;
        ((__nv_bfloat162*)&g_VThi[o])[cp] = __halves2bfloat162(th[h][2 * cp], th[h][2 * cp + 1]);
        ((__nv_bfloat162*)&g_VTlo[o])[cp] = __halves2bfloat162(tl[h][2 * cp], tl[h][2 * cp + 1]);
    }
}

// ---------------------------------------------------------------------------
// K5 (pass2): fused S -> exp -> O += P V'. Grid (16 t-tiles, 4 s-splits, B).
// 256 threads (4m x 2n warps). P stays in registers (S acc frag == A frag).
// smem: Qh(16K) Ql(16K) Kh(8K) Kl(8K) Vh(8K) Vl(8K) = 65536
// (O cross-warp reduce reuses the K/V region at the end.)
// ---------------------------------------------------------------------------
__global__ void __launch_bounds__(256) pass2_fused()
{
    extern __shared__ char smem[];
    char* Qh = smem;
    char* Ql = smem + 16384;
    char* Kh = smem + 32768;
    char* Kl = smem + 40960;
    char* Vh = smem + 49152;
    char* Vl = smem + 57344;
    const uint32_t sQh = smem_u32(Qh), sQl = sQh + 16384;
    const uint32_t sKh = sQh + 32768, sKl = sQh + 40960;
    const uint32_t sVh = sQh + 49152, sVl = sQh + 57344;

    const int tid = threadIdx.x, wid = tid >> 5, lane = tid & 31;
    const int wm = wid >> 1, wn = wid & 1;
    const int gid = lane >> 2, tig = lane & 3;
    const int ti = blockIdx.x;
    const int q4 = blockIdx.y;
    const int b  = blockIdx.z;
    const int t0 = ti * 128;
    const int nS = 2 * (ti + 1);

    // Q tile (persistent)
    {
        const __nv_bfloat16* sh = g_Qhi + ((size_t)b * TT + t0) * HH;
        const __nv_bfloat16* sl = g_Qlo + ((size_t)b * TT + t0) * HH;
#pragma unroll
        for (int j = 0; j < 4; ++j) {
            int u = j * 256 + tid, r = u >> 3, q = u & 7;
            uint32_t off = swz(r * 128 + q * 16);
            *(uint4*)(Qh + off) = *(const uint4*)(sh + r * HH + q * 8);
            *(uint4*)(Ql + off) = *(const uint4*)(sl + r * HH + q * 8);
        }
    }

    float O[2][8][4];
#pragma unroll
    for (int i = 0; i < 2; ++i)
#pragma unroll
        for (int j = 0; j < 8; ++j)
#pragma unroll
            for (int k = 0; k < 4; ++k) O[i][j][k] = 0.f;

    for (int si = q4; si < nS; si += 4) {
        const int s0 = si * 64;
        {
            const __nv_bfloat16* kh = g_Khi + ((size_t)b * TT + s0) * HH;
            const __nv_bfloat16* kl = g_Klo + ((size_t)b * TT + s0) * HH;
            const __nv_bfloat16* vh = g_VThi + (size_t)b * HH * TT + s0;
            const __nv_bfloat16* vl = g_VTlo + (size_t)b * HH * TT + s0;
#pragma unroll
            for (int j = 0; j < 2; ++j) {
                int u = j * 256 + tid, r = u >> 3, q = u & 7;
                uint32_t off = swz(r * 128 + q * 16);
                *(uint4*)(Kh + off) = *(const uint4*)(kh + r * HH + q * 8);
                *(uint4*)(Kl + off) = *(const uint4*)(kl + r * HH + q * 8);
                *(uint4*)(Vh + off) = *(const uint4*)(vh + (size_t)r * TT + q * 8);
                *(uint4*)(Vl + off) = *(const uint4*)(vl + (size_t)r * TT + q * 8);
            }
        }
        __syncthreads();

        // --- S = Q K^T for this warp's 32x32 sub-tile ---
        float S[2][4][4];
#pragma unroll
        for (int i = 0; i < 2; ++i)
#pragma unroll
            for (int j = 0; j < 4; ++j)
#pragma unroll
                for (int k = 0; k < 4; ++k) S[i][j][k] = 0.f;

#pragma unroll
        for (int ks = 0; ks < 4; ++ks) {
            const int kb = ks * 32;
            uint32_t ah0[4], ah1[4], al0[4], al1[4];
            lda(ah0, sQh, wm * 32, kb, lane);      lda(ah1, sQh, wm * 32 + 16, kb, lane);
            lda(al0, sQl, wm * 32, kb, lane);      lda(al1, sQl, wm * 32 + 16, kb, lane);
#pragma unroll
            for (int nf = 0; nf < 4; ++nf) {
                uint32_t bh[2], bl[2];
                ldb(bh, sKh, wn * 32 + nf * 8, kb, lane);
                ldb(bl, sKl, wn * 32 + nf * 8, kb, lane);
                mma16816(S[0][nf], ah0, bh);
                mma16816(S[0][nf], ah0, bl);
                mma16816(S[0][nf], al0, bh);
                mma16816(S[1][nf], ah1, bh);
                mma16816(S[1][nf], ah1, bl);
                mma16816(S[1][nf], al1, bh);
            }
        }

        // --- P = masked exp(S); S acc frags ARE A-frags for the PV mma ---
#pragma unroll
        for (int kss = 0; kss < 2; ++kss) {
            uint32_t ph[2][4], pl[2][4];
#pragma unroll
            for (int mf = 0; mf < 2; ++mf) {
                int r0 = t0 + wm * 32 + mf * 16 + gid;
                int r1 = r0 + 8;
                int cA = s0 + wn * 32 + kss * 16 + 2 * tig;     // nf = 2*kss
                int cB = cA + 8;                                // nf = 2*kss+1
                float* cL = S[mf][2 * kss];
                float* cR = S[mf][2 * kss + 1];
                float e;
                float e0 = (r0 >= cA)     ? __expf(cL[0]) : 0.f;
                e        = (r0 >= cA + 1) ? __expf(cL[1]) : 0.f;
                splitpack2(e0, e, ph[mf][0], pl[mf][0]);
                e0 = (r1 >= cA)     ? __expf(cL[2]) : 0.f;
                e  = (r1 >= cA + 1) ? __expf(cL[3]) : 0.f;
                splitpack2(e0, e, ph[mf][1], pl[mf][1]);
                e0 = (r0 >= cB)     ? __expf(cR[0]) : 0.f;
                e  = (r0 >= cB + 1) ? __expf(cR[1]) : 0.f;
                splitpack2(e0, e, ph[mf][2], pl[mf][2]);
                e0 = (r1 >= cB)     ? __expf(cR[2]) : 0.f;
                e  = (r1 >= cB + 1) ? __expf(cR[3]) : 0.f;
                splitpack2(e0, e, ph[mf][3], pl[mf][3]);
            }
            const int kb = (wn * 32 + kss * 16) * 2;   // byte offset along s
#pragma unroll
            for (int nh = 0; nh < 8; ++nh) {
                uint32_t bh[2], bl[2];
                ldb(bh, sVh, nh * 8, kb, lane);
                ldb(bl, sVl, nh * 8, kb, lane);
                mma16816(O[0][nh], ph[0], bh);
                mma16816(O[0][nh], ph[0], bl);
                mma16816(O[0][nh], pl[0], bh);
                mma16816(O[1][nh], ph[1], bh);
                mma16816(O[1][nh], ph[1], bl);
                mma16816(O[1][nh], pl[1], bh);
            }
        }
        __syncthreads();
    }

    // --- epilogue: combine the two n-warps (wn 0/1) then write g_O4 ---
    float* Ob = g_O4[q4] + ((size_t)b * TT + t0) * HH;
    if (q4 < nS) {
        float* Ored = (float*)(smem + 32768);   // 128x64 floats (reuses K/V)
        if (wn == 0) {
#pragma unroll
            for (int mf = 0; mf < 2; ++mf)
#pragma unroll
                for (int nh = 0; nh < 8; ++nh) {
                    int r0 = wm * 32 + mf * 16 + gid;
                    int c  = nh * 8 + 2 * tig;
                    Ored[r0 * 64 + c]           = O[mf][nh][0];
                    Ored[r0 * 64 + c + 1]       = O[mf][nh][1];
                    Ored[(r0 + 8) * 64 + c]     = O[mf][nh][2];
                    Ored[(r0 + 8) * 64 + c + 1] = O[mf][nh][3];
                }
        }
        __syncthreads();
        if (wn == 1) {
#pragma unroll
            for (int mf = 0; mf < 2; ++mf)
#pragma unroll
                for (int nh = 0; nh < 8; ++nh) {
                    int r0 = wm * 32 + mf * 16 + gid;
                    int c  = nh * 8 + 2 * tig;
                    Ob[(size_t)r0 * HH + c]           = O[mf][nh][0] + Ored[r0 * 64 + c];
                    Ob[(size_t)r0 * HH + c + 1]       = O[mf][nh][1] + Ored[r0 * 64 + c + 1];
                    Ob[(size_t)(r0 + 8) * HH + c]     = O[mf][nh][2] + Ored[(r0 + 8) * 64 + c];
                    Ob[(size_t)(r0 + 8) * HH + c + 1] = O[mf][nh][3] + Ored[(r0 + 8) * 64 + c + 1];
                }
        }
    } else {
        for (int i = tid; i < 128 * HH; i += 256) Ob[i] = 0.f;
    }
}

// ---------------------------------------------------------------------------
// K6: final reduce of the 4 s-split partials
// ---------------------------------------------------------------------------
__global__ void __launch_bounds__(256) oreduce(float* __restrict__ out)
{
    int i = blockIdx.x * 256 + threadIdx.x;
    out[i] = g_O4[0][i] + g_O4[1][i] + g_O4[2][i] + g_O4[3][i];
}

// ---------------------------------------------------------------------------
// Launch
// ---------------------------------------------------------------------------
extern "C" void kernel_launch(void* const* d_in, const int* in_sizes, int n_in,
                              void* d_out, int out_size)
{
    (void)in_sizes; (void)n_in; (void)out_size;
    const float* idx = (const float*)d_in[0];
    const float* Wk  = (const float*)d_in[1];
    const float* Wq  = (const float*)d_in[2];
    const float* Wv  = (const float*)d_in[3];
    float* out = (float*)d_out;

    cudaFuncSetAttribute(proj_mma,     cudaFuncAttributeMaxDynamicSharedMemorySize, 49152);
    cudaFuncSetAttribute(pass1_colsum, cudaFuncAttributeMaxDynamicSharedMemorySize, 50176);
    cudaFuncSetAttribute(pass2_fused,  cudaFuncAttributeMaxDynamicSharedMemorySize, 65536);

    proj_mma<<<dim3(128, 3), 256, 49152>>>(idx, Wk, Wq, Wv);
    pass1_colsum<<<dim3(32, 4, BB), 256, 50176>>>();
    dreduce<<<(BB * TT) / 256, 256>>>();
    vscale_t<<<dim3(16, BB), 256>>>();
    pass2_fused<<<dim3(16, 4, BB), 256, 65536>>>();
    oreduce<<<(BB * TT * HH) / 256, 256>>>(out);
}

// round 6
// speedup vs baseline: 2.1417x; 1.2321x over previous
#include <cuda_runtime.h>
#include <cuda_bf16.h>
#include <cstdint>
#include <cstddef>

#define BB 8
#define TT 2048
#define CC 1024
#define HH 64

// ---------------------------------------------------------------------------
// Scratch (device globals; no allocations allowed)
// ---------------------------------------------------------------------------
__device__ __nv_bfloat16 g_Whi[3 * HH * CC];     // [Wq;Wk;Wv] stacked, hi
__device__ __nv_bfloat16 g_Wlo[3 * HH * CC];     // lo
__device__ __nv_bfloat16 g_Qhi[BB * TT * HH];
__device__ __nv_bfloat16 g_Qlo[BB * TT * HH];
__device__ __nv_bfloat16 g_Khi[BB * TT * HH];
__device__ __nv_bfloat16 g_Klo[BB * TT * HH];
__device__ float         g_V[BB * TT * HH];
__device__ __nv_bfloat16 g_VThi[BB * HH * TT];   // V' transposed [b][h][s]
__device__ __nv_bfloat16 g_VTlo[BB * HH * TT];
__device__ float         g_Dp[BB][4][TT];        // colsum partials
__device__ float         g_O4[4][BB * TT * HH];  // 4-way split-s partial outputs

// ---------------------------------------------------------------------------
// Helpers: smem addr, swizzle, ldmatrix, mma (plain sm_80+ PTX, no 'a')
// ---------------------------------------------------------------------------
__device__ __forceinline__ uint32_t smem_u32(const void* p) {
    uint32_t r;
    asm("{ .reg .u64 t; cvta.to.shared.u64 t, %1; cvt.u32.u64 %0, t; }"
        : "=r"(r) : "l"(p));
    return r;
}
__device__ __forceinline__ uint32_t swz(uint32_t o) { return o ^ ((o >> 3) & 0x70); }

__device__ __forceinline__ void ldsm4(uint32_t (&r)[4], uint32_t addr) {
    asm volatile("ldmatrix.sync.aligned.m8n8.x4.shared.b16 {%0,%1,%2,%3}, [%4];"
                 : "=r"(r[0]), "=r"(r[1]), "=r"(r[2]), "=r"(r[3]) : "r"(addr));
}
__device__ __forceinline__ void mma2(float (&c)[4], const uint32_t (&a)[4],
                                     uint32_t b0, uint32_t b1) {
    asm volatile(
        "mma.sync.aligned.m16n8k16.row.col.f32.bf16.bf16.f32 "
        "{%0,%1,%2,%3}, {%4,%5,%6,%7}, {%8,%9}, {%0,%1,%2,%3};"
        : "+f"(c[0]), "+f"(c[1]), "+f"(c[2]), "+f"(c[3])
        : "r"(a[0]), "r"(a[1]), "r"(a[2]), "r"(a[3]), "r"(b0), "r"(b1));
}

// A-fragment: 16x16 bf16, row-major tile rows = mr.., k-bytes = kb..kb+31
__device__ __forceinline__ void lda(uint32_t (&a)[4], uint32_t base, int mr,
                                    int kb, int lane) {
    ldsm4(a, base + swz(((mr + (lane & 15)) << 7) + kb + ((lane >> 4) << 4)));
}
// B-fragments for TWO n8 tiles (n16 x k16) from [n][k] row-major tile:
// {b[0],b[1]} serve rows nr..nr+7, {b[2],b[3]} rows nr+8..nr+15.
__device__ __forceinline__ void ldb4(uint32_t (&b)[4], uint32_t base, int nr,
                                     int kb, int lane) {
    int row = nr + (lane & 7) + ((lane >> 4) << 3);
    int kx  = kb + (((lane >> 3) & 1) << 4);
    ldsm4(b, base + swz((row << 7) + kx));
}

__device__ __forceinline__ void split_bf16(float x, __nv_bfloat16& h, __nv_bfloat16& l) {
    h = __float2bfloat16(x);
    l = __float2bfloat16(x - __bfloat162float(h));
}
__device__ __forceinline__ void splitpack2(float x, float y, uint32_t& hi, uint32_t& lo) {
    __nv_bfloat16 hx, lx, hy, ly;
    split_bf16(x, hx, lx); split_bf16(y, hy, ly);
    __nv_bfloat162 H = __halves2bfloat162(hx, hy);
    __nv_bfloat162 L = __halves2bfloat162(lx, ly);
    hi = *(uint32_t*)&H; lo = *(uint32_t*)&L;
}

// ---------------------------------------------------------------------------
// K0: split weights once into stacked [192][1024] hi/lo (Q,K,V order)
// ---------------------------------------------------------------------------
__global__ void __launch_bounds__(256) prep_w(
    const float* __restrict__ Wk,
    const float* __restrict__ Wq,
    const float* __restrict__ Wv)
{
    int i = blockIdx.x * 256 + threadIdx.x;          // < 196608
    int w = i >> 16;                                 // 65536 elems per matrix
    int rem = i & 65535;
    const float* src = (w == 0) ? Wq : (w == 1) ? Wk : Wv;
    __nv_bfloat16 h, l;
    split_bf16(src[rem], h, l);
    g_Whi[i] = h; g_Wlo[i] = l;
}

// ---------------------------------------------------------------------------
// K1: QKV projection, fused. Grid 256 CTAs, 256 threads (2m x 4n warps).
// Per CTA: 64 rows of A x 192 cols (Q|K|V), K=1024 chunked by 64.
// smem: Ah(8K) Al(8K) Wh(24K) Wl(24K) = 65536
// ---------------------------------------------------------------------------
__global__ void __launch_bounds__(256) proj_mma(const float* __restrict__ A)
{
    extern __shared__ char smem[];
    char* Ah = smem;
    char* Al = smem + 8192;
    char* Wh = smem + 16384;
    char* Wl = smem + 40960;
    const uint32_t sAh = smem_u32(Ah), sAl = sAh + 8192;
    const uint32_t sWh = sAh + 16384, sWl = sAh + 40960;

    const int tid = threadIdx.x, wid = tid >> 5, lane = tid & 31;
    const int wm = wid >> 2, wn = wid & 3;
    const int gid = lane >> 2, tig = lane & 3;
    const int m0 = blockIdx.x * 64;

    float acc[2][6][4];
#pragma unroll
    for (int i = 0; i < 2; ++i)
#pragma unroll
        for (int j = 0; j < 6; ++j)
#pragma unroll
            for (int k = 0; k < 4; ++k) acc[i][j][k] = 0.f;

    for (int ch = 0; ch < 16; ++ch) {
        const int c0 = ch * 64;
        // A 64x64 fp32 -> hi/lo split in smem
#pragma unroll
        for (int i = 0; i < 8; ++i) {
            int p = i * 256 + tid, r = p >> 5, cp = p & 31;
            float2 a = *(const float2*)&A[(size_t)(m0 + r) * CC + c0 + cp * 2];
            uint32_t hi, lo; splitpack2(a.x, a.y, hi, lo);
            uint32_t off = swz(r * 128 + cp * 4);
            *(uint32_t*)(Ah + off) = hi; *(uint32_t*)(Al + off) = lo;
        }
        // W chunk [192][64] bf16 hi/lo (already split)
#pragma unroll
        for (int i = 0; i < 6; ++i) {
            int u = i * 256 + tid, r = u >> 3, q = u & 7;
            uint32_t off = swz(r * 128 + q * 16);
            *(uint4*)(Wh + off) = *(const uint4*)(g_Whi + (size_t)r * CC + c0 + q * 8);
            *(uint4*)(Wl + off) = *(const uint4*)(g_Wlo + (size_t)r * CC + c0 + q * 8);
        }
        __syncthreads();

#pragma unroll
        for (int ks = 0; ks < 4; ++ks) {
            const int kb = ks * 32;
            uint32_t ah0[4], ah1[4], al0[4], al1[4];
            lda(ah0, sAh, wm * 32, kb, lane);      lda(ah1, sAh, wm * 32 + 16, kb, lane);
            lda(al0, sAl, wm * 32, kb, lane);      lda(al1, sAl, wm * 32 + 16, kb, lane);
#pragma unroll
            for (int jp = 0; jp < 3; ++jp) {
                uint32_t bh[4], bl[4];
                ldb4(bh, sWh, wn * 48 + jp * 16, kb, lane);
                ldb4(bl, sWl, wn * 48 + jp * 16, kb, lane);
                mma2(acc[0][2 * jp], ah0, bh[0], bh[1]);
                mma2(acc[0][2 * jp], ah0, bl[0], bl[1]);
                mma2(acc[0][2 * jp], al0, bh[0], bh[1]);
                mma2(acc[1][2 * jp], ah1, bh[0], bh[1]);
                mma2(acc[1][2 * jp], ah1, bl[0], bl[1]);
                mma2(acc[1][2 * jp], al1, bh[0], bh[1]);
                mma2(acc[0][2 * jp + 1], ah0, bh[2], bh[3]);
                mma2(acc[0][2 * jp + 1], ah0, bl[2], bl[3]);
                mma2(acc[0][2 * jp + 1], al0, bh[2], bh[3]);
                mma2(acc[1][2 * jp + 1], ah1, bh[2], bh[3]);
                mma2(acc[1][2 * jp + 1], ah1, bl[2], bl[3]);
                mma2(acc[1][2 * jp + 1], al1, bh[2], bh[3]);
            }
        }
        __syncthreads();
    }

    // epilogue: cols 0-63 -> Q (split), 64-127 -> K (split), 128-191 -> V fp32
#pragma unroll
    for (int mf = 0; mf < 2; ++mf)
#pragma unroll
        for (int j = 0; j < 6; ++j) {
            int base = wn * 48 + j * 8;
            int reg = base >> 6;
            int col = (base & 63) + 2 * tig;
            int m = m0 + wm * 32 + mf * 16 + gid;
            if (reg == 2) {
                *(float2*)&g_V[(size_t)m * HH + col] =
                    make_float2(acc[mf][j][0], acc[mf][j][1]);
                *(float2*)&g_V[(size_t)(m + 8) * HH + col] =
                    make_float2(acc[mf][j][2], acc[mf][j][3]);
            } else {
                uint32_t* oh = (reg == 0) ? (uint32_t*)g_Qhi : (uint32_t*)g_Khi;
                uint32_t* ol = (reg == 0) ? (uint32_t*)g_Qlo : (uint32_t*)g_Klo;
                uint32_t hi, lo;
                splitpack2(acc[mf][j][0], acc[mf][j][1], hi, lo);
                size_t o = ((size_t)m * HH + col) >> 1;
                oh[o] = hi; ol[o] = lo;
                splitpack2(acc[mf][j][2], acc[mf][j][3], hi, lo);
                o = ((size_t)(m + 8) * HH + col) >> 1;
                oh[o] = hi; ol[o] = lo;
            }
        }
}

// ---------------------------------------------------------------------------
// K2 (pass1): D_s partials. Grid (32 s-tiles, 4 t-chunks, B), 256 threads.
// smem: Qh(16K) Ql(16K) Kh(8K) Kl(8K) red(1K) = 50176
// ---------------------------------------------------------------------------
__global__ void __launch_bounds__(256) pass1_colsum()
{
    extern __shared__ char smem[];
    char* Qh = smem;
    char* Ql = smem + 16384;
    char* Kh = smem + 32768;
    char* Kl = smem + 40960;
    float* red = (float*)(smem + 49152);      // [4][64]
    const uint32_t sQh = smem_u32(Qh), sQl = sQh + 16384;
    const uint32_t sKh = sQh + 32768, sKl = sQh + 40960;

    const int tid = threadIdx.x, wid = tid >> 5, lane = tid & 31;
    const int wm = wid >> 1, wn = wid & 1;
    const int gid = lane >> 2, tig = lane & 3;
    const int s0 = blockIdx.x * 64;
    const int ch = blockIdx.y;
    const int b  = blockIdx.z;

    {   // K tile (persistent)
        const __nv_bfloat16* sh = g_Khi + ((size_t)b * TT + s0) * HH;
        const __nv_bfloat16* sl = g_Klo + ((size_t)b * TT + s0) * HH;
#pragma unroll
        for (int j = 0; j < 2; ++j) {
            int u = j * 256 + tid, r = u >> 3, q = u & 7;
            uint32_t off = swz(r * 128 + q * 16);
            *(uint4*)(Kh + off) = *(const uint4*)(sh + r * HH + q * 8);
            *(uint4*)(Kl + off) = *(const uint4*)(sl + r * HH + q * 8);
        }
    }

    float csum[4][2];
#pragma unroll
    for (int i = 0; i < 4; ++i) { csum[i][0] = 0.f; csum[i][1] = 0.f; }

    const int tbase = ch * 512;
    for (int t0 = tbase; t0 < tbase + 512; t0 += 128) {
        if (t0 + 128 <= s0) continue;
        {
            const __nv_bfloat16* sh = g_Qhi + ((size_t)b * TT + t0) * HH;
            const __nv_bfloat16* sl = g_Qlo + ((size_t)b * TT + t0) * HH;
#pragma unroll
            for (int j = 0; j < 4; ++j) {
                int u = j * 256 + tid, r = u >> 3, q = u & 7;
                uint32_t off = swz(r * 128 + q * 16);
                *(uint4*)(Qh + off) = *(const uint4*)(sh + r * HH + q * 8);
                *(uint4*)(Ql + off) = *(const uint4*)(sl + r * HH + q * 8);
            }
        }
        __syncthreads();

        float acc[2][4][4];
#pragma unroll
        for (int i = 0; i < 2; ++i)
#pragma unroll
            for (int j = 0; j < 4; ++j)
#pragma unroll
                for (int k = 0; k < 4; ++k) acc[i][j][k] = 0.f;

#pragma unroll
        for (int ks = 0; ks < 4; ++ks) {
            const int kb = ks * 32;
            uint32_t ah0[4], ah1[4], al0[4], al1[4];
            lda(ah0, sQh, wm * 32, kb, lane);      lda(ah1, sQh, wm * 32 + 16, kb, lane);
            lda(al0, sQl, wm * 32, kb, lane);      lda(al1, sQl, wm * 32 + 16, kb, lane);
#pragma unroll
            for (int jp = 0; jp < 2; ++jp) {
                uint32_t bh[4], bl[4];
                ldb4(bh, sKh, wn * 32 + jp * 16, kb, lane);
                ldb4(bl, sKl, wn * 32 + jp * 16, kb, lane);
                mma2(acc[0][2 * jp], ah0, bh[0], bh[1]);
                mma2(acc[0][2 * jp], ah0, bl[0], bl[1]);
                mma2(acc[0][2 * jp], al0, bh[0], bh[1]);
                mma2(acc[1][2 * jp], ah1, bh[0], bh[1]);
                mma2(acc[1][2 * jp], ah1, bl[0], bl[1]);
                mma2(acc[1][2 * jp], al1, bh[0], bh[1]);
                mma2(acc[0][2 * jp + 1], ah0, bh[2], bh[3]);
                mma2(acc[0][2 * jp + 1], ah0, bl[2], bl[3]);
                mma2(acc[0][2 * jp + 1], al0, bh[2], bh[3]);
                mma2(acc[1][2 * jp + 1], ah1, bh[2], bh[3]);
                mma2(acc[1][2 * jp + 1], ah1, bl[2], bl[3]);
                mma2(acc[1][2 * jp + 1], al1, bh[2], bh[3]);
            }
        }

        // masked exp + per-thread column sums
#pragma unroll
        for (int mf = 0; mf < 2; ++mf) {
            int r0 = t0 + wm * 32 + mf * 16 + gid;
            int r1 = r0 + 8;
#pragma unroll
            for (int nf = 0; nf < 4; ++nf) {
                int c = s0 + wn * 32 + nf * 8 + 2 * tig;
                csum[nf][0] += ((r0 >= c) ? __expf(acc[mf][nf][0]) : 0.f)
                             + ((r1 >= c) ? __expf(acc[mf][nf][2]) : 0.f);
                csum[nf][1] += ((r0 >= c + 1) ? __expf(acc[mf][nf][1]) : 0.f)
                             + ((r1 >= c + 1) ? __expf(acc[mf][nf][3]) : 0.f);
            }
        }
        __syncthreads();
    }

#pragma unroll
    for (int nf = 0; nf < 4; ++nf)
#pragma unroll
        for (int d = 0; d < 2; ++d) {
            float v = csum[nf][d];
            v += __shfl_xor_sync(0xffffffffu, v, 4);
            v += __shfl_xor_sync(0xffffffffu, v, 8);
            v += __shfl_xor_sync(0xffffffffu, v, 16);
            if (lane < 4)
                red[wm * 64 + wn * 32 + nf * 8 + 2 * lane + d] = v;
        }
    __syncthreads();
    if (tid < 64)
        g_Dp[b][ch][s0 + tid] =
            red[tid] + red[64 + tid] + red[128 + tid] + red[192 + tid];
}

// ---------------------------------------------------------------------------
// K4: fused D-reduce + V' = V/D transposed to [b][h][s], split hi/lo.
// Grid (16, B), 256 threads. Padded smem transpose (no bank conflicts).
// ---------------------------------------------------------------------------
__global__ void __launch_bounds__(256) vscale_t()
{
    __shared__ float Ds[128];
    __shared__ __nv_bfloat16 th[64][129];
    __shared__ __nv_bfloat16 tl[64][129];
    const int tid = threadIdx.x;
    const int s0 = blockIdx.x * 128;
    const int b  = blockIdx.y;

    if (tid < 128) {
        int s = s0 + tid;
        Ds[tid] = g_Dp[b][0][s] + g_Dp[b][1][s] + g_Dp[b][2][s] + g_Dp[b][3][s];
    }
    __syncthreads();

    for (int idx = tid; idx < 128 * 64; idx += 256) {
        int s = idx >> 6, h = idx & 63;
        float v = g_V[((size_t)b * TT + s0 + s) * HH + h] / Ds[s];
        __nv_bfloat16 hi, lo;
        split_bf16(v, hi, lo);
        th[h][s] = hi; tl[h][s] = lo;
    }
    __syncthreads();
    for (int i = tid; i < 64 * 64; i += 256) {
        int h = i >> 6, cp = i & 63;
        size_t o = ((size_t)b * HH + h) * TT + s0;
        ((__nv_bfloat162*)&g_VThi[o])[cp] = __halves2bfloat162(th[h][2 * cp], th[h][2 * cp + 1]);
        ((__nv_bfloat162*)&g_VTlo[o])[cp] = __halves2bfloat162(tl[h][2 * cp], tl[h][2 * cp + 1]);
    }
}

// ---------------------------------------------------------------------------
// K5 (pass2): fused S -> exp -> O += P V'. Grid (16 t-tiles, 4 s-splits, B).
// ti reversed so heaviest CTAs launch first. P stays in registers.
// smem: Qh(16K) Ql(16K) Kh(8K) Kl(8K) Vh(8K) Vl(8K) = 65536
// ---------------------------------------------------------------------------
__global__ void __launch_bounds__(256) pass2_fused()
{
    extern __shared__ char smem[];
    char* Qh = smem;
    char* Ql = smem + 16384;
    char* Kh = smem + 32768;
    char* Kl = smem + 40960;
    char* Vh = smem + 49152;
    char* Vl = smem + 57344;
    const uint32_t sQh = smem_u32(Qh), sQl = sQh + 16384;
    const uint32_t sKh = sQh + 32768, sKl = sQh + 40960;
    const uint32_t sVh = sQh + 49152, sVl = sQh + 57344;

    const int tid = threadIdx.x, wid = tid >> 5, lane = tid & 31;
    const int wm = wid >> 1, wn = wid & 1;
    const int gid = lane >> 2, tig = lane & 3;
    const int ti = 15 - blockIdx.x;             // heavy tiles first
    const int q4 = blockIdx.y;
    const int b  = blockIdx.z;
    const int t0 = ti * 128;
    const int nS = 2 * (ti + 1);

    {   // Q tile (persistent)
        const __nv_bfloat16* sh = g_Qhi + ((size_t)b * TT + t0) * HH;
        const __nv_bfloat16* sl = g_Qlo + ((size_t)b * TT + t0) * HH;
#pragma unroll
        for (int j = 0; j < 4; ++j) {
            int u = j * 256 + tid, r = u >> 3, q = u & 7;
            uint32_t off = swz(r * 128 + q * 16);
            *(uint4*)(Qh + off) = *(const uint4*)(sh + r * HH + q * 8);
            *(uint4*)(Ql + off) = *(const uint4*)(sl + r * HH + q * 8);
        }
    }

    float O[2][8][4];
#pragma unroll
    for (int i = 0; i < 2; ++i)
#pragma unroll
        for (int j = 0; j < 8; ++j)
#pragma unroll
            for (int k = 0; k < 4; ++k) O[i][j][k] = 0.f;

    for (int si = q4; si < nS; si += 4) {
        const int s0 = si * 64;
        {
            const __nv_bfloat16* kh = g_Khi + ((size_t)b * TT + s0) * HH;
            const __nv_bfloat16* kl = g_Klo + ((size_t)b * TT + s0) * HH;
            const __nv_bfloat16* vh = g_VThi + (size_t)b * HH * TT + s0;
            const __nv_bfloat16* vl = g_VTlo + (size_t)b * HH * TT + s0;
#pragma unroll
            for (int j = 0; j < 2; ++j) {
                int u = j * 256 + tid, r = u >> 3, q = u & 7;
                uint32_t off = swz(r * 128 + q * 16);
                *(uint4*)(Kh + off) = *(const uint4*)(kh + r * HH + q * 8);
                *(uint4*)(Kl + off) = *(const uint4*)(kl + r * HH + q * 8);
                *(uint4*)(Vh + off) = *(const uint4*)(vh + (size_t)r * TT + q * 8);
                *(uint4*)(Vl + off) = *(const uint4*)(vl + (size_t)r * TT + q * 8);
            }
        }
        __syncthreads();

        // --- S = Q K^T for this warp's 32x32 sub-tile ---
        float S[2][4][4];
#pragma unroll
        for (int i = 0; i < 2; ++i)
#pragma unroll
            for (int j = 0; j < 4; ++j)
#pragma unroll
                for (int k = 0; k < 4; ++k) S[i][j][k] = 0.f;

#pragma unroll
        for (int ks = 0; ks < 4; ++ks) {
            const int kb = ks * 32;
            uint32_t ah0[4], ah1[4], al0[4], al1[4];
            lda(ah0, sQh, wm * 32, kb, lane);      lda(ah1, sQh, wm * 32 + 16, kb, lane);
            lda(al0, sQl, wm * 32, kb, lane);      lda(al1, sQl, wm * 32 + 16, kb, lane);
#pragma unroll
            for (int jp = 0; jp < 2; ++jp) {
                uint32_t bh[4], bl[4];
                ldb4(bh, sKh, wn * 32 + jp * 16, kb, lane);
                ldb4(bl, sKl, wn * 32 + jp * 16, kb, lane);
                mma2(S[0][2 * jp], ah0, bh[0], bh[1]);
                mma2(S[0][2 * jp], ah0, bl[0], bl[1]);
                mma2(S[0][2 * jp], al0, bh[0], bh[1]);
                mma2(S[1][2 * jp], ah1, bh[0], bh[1]);
                mma2(S[1][2 * jp], ah1, bl[0], bl[1]);
                mma2(S[1][2 * jp], al1, bh[0], bh[1]);
                mma2(S[0][2 * jp + 1], ah0, bh[2], bh[3]);
                mma2(S[0][2 * jp + 1], ah0, bl[2], bl[3]);
                mma2(S[0][2 * jp + 1], al0, bh[2], bh[3]);
                mma2(S[1][2 * jp + 1], ah1, bh[2], bh[3]);
                mma2(S[1][2 * jp + 1], ah1, bl[2], bl[3]);
                mma2(S[1][2 * jp + 1], al1, bh[2], bh[3]);
            }
        }

        // --- P = masked exp(S); S acc frags ARE A-frags for the PV mma ---
#pragma unroll
        for (int kss = 0; kss < 2; ++kss) {
            uint32_t ph[2][4], pl[2][4];
#pragma unroll
            for (int mf = 0; mf < 2; ++mf) {
                int r0 = t0 + wm * 32 + mf * 16 + gid;
                int r1 = r0 + 8;
                int cA = s0 + wn * 32 + kss * 16 + 2 * tig;
                int cB = cA + 8;
                float* cL = S[mf][2 * kss];
                float* cR = S[mf][2 * kss + 1];
                float e, e0;
                e0 = (r0 >= cA)     ? __expf(cL[0]) : 0.f;
                e  = (r0 >= cA + 1) ? __expf(cL[1]) : 0.f;
                splitpack2(e0, e, ph[mf][0], pl[mf][0]);
                e0 = (r1 >= cA)     ? __expf(cL[2]) : 0.f;
                e  = (r1 >= cA + 1) ? __expf(cL[3]) : 0.f;
                splitpack2(e0, e, ph[mf][1], pl[mf][1]);
                e0 = (r0 >= cB)     ? __expf(cR[0]) : 0.f;
                e  = (r0 >= cB + 1) ? __expf(cR[1]) : 0.f;
                splitpack2(e0, e, ph[mf][2], pl[mf][2]);
                e0 = (r1 >= cB)     ? __expf(cR[2]) : 0.f;
                e  = (r1 >= cB + 1) ? __expf(cR[3]) : 0.f;
                splitpack2(e0, e, ph[mf][3], pl[mf][3]);
            }
            const int kb = (wn * 32 + kss * 16) * 2;   // byte offset along s
#pragma unroll
            for (int jp = 0; jp < 4; ++jp) {
                uint32_t bh[4], bl[4];
                ldb4(bh, sVh, jp * 16, kb, lane);
                ldb4(bl, sVl, jp * 16, kb, lane);
                mma2(O[0][2 * jp], ph[0], bh[0], bh[1]);
                mma2(O[0][2 * jp], ph[0], bl[0], bl[1]);
                mma2(O[0][2 * jp], pl[0], bh[0], bh[1]);
                mma2(O[1][2 * jp], ph[1], bh[0], bh[1]);
                mma2(O[1][2 * jp], ph[1], bl[0], bl[1]);
                mma2(O[1][2 * jp], pl[1], bh[0], bh[1]);
                mma2(O[0][2 * jp + 1], ph[0], bh[2], bh[3]);
                mma2(O[0][2 * jp + 1], ph[0], bl[2], bl[3]);
                mma2(O[0][2 * jp + 1], pl[0], bh[2], bh[3]);
                mma2(O[1][2 * jp + 1], ph[1], bh[2], bh[3]);
                mma2(O[1][2 * jp + 1], ph[1], bl[2], bl[3]);
                mma2(O[1][2 * jp + 1], pl[1], bh[2], bh[3]);
            }
        }
        __syncthreads();
    }

    // --- epilogue: combine the two n-warps (wn 0/1) then write g_O4 ---
    float* Ob = g_O4[q4] + ((size_t)b * TT + t0) * HH;
    if (q4 < nS) {
        float* Ored = (float*)(smem + 32768);   // 128x64 floats (reuses K/V)
        if (wn == 0) {
#pragma unroll
            for (int mf = 0; mf < 2; ++mf)
#pragma unroll
                for (int nh = 0; nh < 8; ++nh) {
                    int r0 = wm * 32 + mf * 16 + gid;
                    int c  = nh * 8 + 2 * tig;
                    Ored[r0 * 64 + c]           = O[mf][nh][0];
                    Ored[r0 * 64 + c + 1]       = O[mf][nh][1];
                    Ored[(r0 + 8) * 64 + c]     = O[mf][nh][2];
                    Ored[(r0 + 8) * 64 + c + 1] = O[mf][nh][3];
                }
        }
        __syncthreads();
        if (wn == 1) {
#pragma unroll
            for (int mf = 0; mf < 2; ++mf)
#pragma unroll
                for (int nh = 0; nh < 8; ++nh) {
                    int r0 = wm * 32 + mf * 16 + gid;
                    int c  = nh * 8 + 2 * tig;
                    Ob[(size_t)r0 * HH + c]           = O[mf][nh][0] + Ored[r0 * 64 + c];
                    Ob[(size_t)r0 * HH + c + 1]       = O[mf][nh][1] + Ored[r0 * 64 + c + 1];
                    Ob[(size_t)(r0 + 8) * HH + c]     = O[mf][nh][2] + Ored[(r0 + 8) * 64 + c];
                    Ob[(size_t)(r0 + 8) * HH + c + 1] = O[mf][nh][3] + Ored[(r0 + 8) * 64 + c + 1];
                }
        }
    } else {
        for (int i = tid; i < 128 * HH; i += 256) Ob[i] = 0.f;
    }
}

// ---------------------------------------------------------------------------
// K6: final reduce of the 4 s-split partials
// ---------------------------------------------------------------------------
__global__ void __launch_bounds__(256) oreduce(float* __restrict__ out)
{
    int i = blockIdx.x * 256 + threadIdx.x;
    out[i] = g_O4[0][i] + g_O4[1][i] + g_O4[2][i] + g_O4[3][i];
}

// ---------------------------------------------------------------------------
// Launch
// ---------------------------------------------------------------------------
extern "C" void kernel_launch(void* const* d_in, const int* in_sizes, int n_in,
                              void* d_out, int out_size)
{
    (void)in_sizes; (void)n_in; (void)out_size;
    const float* idx = (const float*)d_in[0];
    const float* Wk  = (const float*)d_in[1];
    const float* Wq  = (const float*)d_in[2];
    const float* Wv  = (const float*)d_in[3];
    float* out = (float*)d_out;

    cudaFuncSetAttribute(proj_mma,     cudaFuncAttributeMaxDynamicSharedMemorySize, 65536);
    cudaFuncSetAttribute(pass1_colsum, cudaFuncAttributeMaxDynamicSharedMemorySize, 50176);
    cudaFuncSetAttribute(pass2_fused,  cudaFuncAttributeMaxDynamicSharedMemorySize, 65536);

    prep_w<<<768, 256>>>(Wk, Wq, Wv);
    proj_mma<<<256, 256, 65536>>>(idx);
    pass1_colsum<<<dim3(32, 4, BB), 256, 50176>>>();
    vscale_t<<<dim3(16, BB), 256>>>();
    pass2_fused<<<dim3(16, 4, BB), 256, 65536>>>();
    oreduce<<<(BB * TT * HH) / 256, 256>>>(out);
}

// round 7
// speedup vs baseline: 2.2801x; 1.0646x over previous
#include <cuda_runtime.h>
#include <cuda_bf16.h>
#include <cstdint>
#include <cstddef>

#define BB 8
#define TT 2048
#define CC 1024
#define HH 64

// ---------------------------------------------------------------------------
// Scratch (device globals; no allocations allowed)
// ---------------------------------------------------------------------------
__device__ __nv_bfloat16 g_Whi[3 * HH * CC];     // [Wq;Wk;Wv] stacked, hi
__device__ __nv_bfloat16 g_Wlo[3 * HH * CC];     // lo
__device__ __nv_bfloat16 g_Qhi[BB * TT * HH];    // Q * log2(e), hi/lo
__device__ __nv_bfloat16 g_Qlo[BB * TT * HH];
__device__ __nv_bfloat16 g_Khi[BB * TT * HH];
__device__ __nv_bfloat16 g_Klo[BB * TT * HH];
__device__ __nv_bfloat16 g_Vhi[BB * TT * HH];    // V [s][h] hi/lo (unscaled)
__device__ __nv_bfloat16 g_Vlo[BB * TT * HH];
__device__ float         g_Dp[BB][4][TT];        // colsum partials
__device__ float         g_O4[4][BB * TT * HH];  // 4-way split-s partial outputs

// ---------------------------------------------------------------------------
// Helpers (plain sm_80+ PTX, no 'a' features)
// ---------------------------------------------------------------------------
__device__ __forceinline__ uint32_t smem_u32(const void* p) {
    uint32_t r;
    asm("{ .reg .u64 t; cvta.to.shared.u64 t, %1; cvt.u32.u64 %0, t; }"
        : "=r"(r) : "l"(p));
    return r;
}
__device__ __forceinline__ uint32_t swz(uint32_t o) { return o ^ ((o >> 3) & 0x70); }

__device__ __forceinline__ void ldsm4(uint32_t (&r)[4], uint32_t addr) {
    asm volatile("ldmatrix.sync.aligned.m8n8.x4.shared.b16 {%0,%1,%2,%3}, [%4];"
                 : "=r"(r[0]), "=r"(r[1]), "=r"(r[2]), "=r"(r[3]) : "r"(addr));
}
__device__ __forceinline__ void ldsm4t(uint32_t (&r)[4], uint32_t addr) {
    asm volatile("ldmatrix.sync.aligned.m8n8.x4.trans.shared.b16 {%0,%1,%2,%3}, [%4];"
                 : "=r"(r[0]), "=r"(r[1]), "=r"(r[2]), "=r"(r[3]) : "r"(addr));
}
__device__ __forceinline__ void mma2(float (&c)[4], const uint32_t (&a)[4],
                                     uint32_t b0, uint32_t b1) {
    asm volatile(
        "mma.sync.aligned.m16n8k16.row.col.f32.bf16.bf16.f32 "
        "{%0,%1,%2,%3}, {%4,%5,%6,%7}, {%8,%9}, {%0,%1,%2,%3};"
        : "+f"(c[0]), "+f"(c[1]), "+f"(c[2]), "+f"(c[3])
        : "r"(a[0]), "r"(a[1]), "r"(a[2]), "r"(a[3]), "r"(b0), "r"(b1));
}
__device__ __forceinline__ float ex2(float x) {
    float y;
    asm("ex2.approx.f32 %0, %1;" : "=f"(y) : "f"(x));
    return y;
}

// A-fragment: 16x16 bf16, row-major tile rows = mr.., k-bytes = kb..kb+31
__device__ __forceinline__ void lda(uint32_t (&a)[4], uint32_t base, int mr,
                                    int kb, int lane) {
    ldsm4(a, base + swz(((mr + (lane & 15)) << 7) + kb + ((lane >> 4) << 4)));
}
// B-fragments for TWO n8 tiles (n16 x k16) from [n][k] row-major tile
__device__ __forceinline__ void ldb4(uint32_t (&b)[4], uint32_t base, int nr,
                                     int kb, int lane) {
    int row = nr + (lane & 7) + ((lane >> 4) << 3);
    int kx  = kb + (((lane >> 3) & 1) << 4);
    ldsm4(b, base + swz((row << 7) + kx));
}
// B-fragments for TWO n8 tiles from a [k][n] row-major tile via trans ldmatrix
// (k = tile row index, n = byte columns). ksel = k element offset, nr = n elems.
__device__ __forceinline__ void ldb4t(uint32_t (&b)[4], uint32_t base, int nr,
                                      int ksel, int lane) {
    int row  = ksel + (lane & 7) + (((lane >> 3) & 1) << 3);
    int colb = nr * 2 + ((lane >> 4) << 4);
    ldsm4t(b, base + swz((row << 7) + colb));
}

__device__ __forceinline__ void split_bf16(float x, __nv_bfloat16& h, __nv_bfloat16& l) {
    h = __float2bfloat16(x);
    l = __float2bfloat16(x - __bfloat162float(h));
}
__device__ __forceinline__ void splitpack2(float x, float y, uint32_t& hi, uint32_t& lo) {
    __nv_bfloat16 hx, lx, hy, ly;
    split_bf16(x, hx, lx); split_bf16(y, hy, ly);
    __nv_bfloat162 H = __halves2bfloat162(hx, hy);
    __nv_bfloat162 L = __halves2bfloat162(lx, ly);
    hi = *(uint32_t*)&H; lo = *(uint32_t*)&L;
}

// ---------------------------------------------------------------------------
// K0: split weights once into stacked [192][1024] hi/lo (Q,K,V order)
// ---------------------------------------------------------------------------
__global__ void __launch_bounds__(256) prep_w(
    const float* __restrict__ Wk,
    const float* __restrict__ Wq,
    const float* __restrict__ Wv)
{
    int i = blockIdx.x * 256 + threadIdx.x;          // < 196608
    int w = i >> 16;
    int rem = i & 65535;
    const float* src = (w == 0) ? Wq : (w == 1) ? Wk : Wv;
    __nv_bfloat16 h, l;
    split_bf16(src[rem], h, l);
    g_Whi[i] = h; g_Wlo[i] = l;
}

// ---------------------------------------------------------------------------
// K1: QKV projection, fused. Grid 256 CTAs, 256 threads (2m x 4n warps).
// Q epilogue pre-scaled by log2(e); V written split hi/lo (unscaled).
// smem: Ah(8K) Al(8K) Wh(24K) Wl(24K) = 65536
// ---------------------------------------------------------------------------
__global__ void __launch_bounds__(256) proj_mma(const float* __restrict__ A)
{
    extern __shared__ char smem[];
    char* Ah = smem;
    char* Al = smem + 8192;
    char* Wh = smem + 16384;
    char* Wl = smem + 40960;
    const uint32_t sAh = smem_u32(Ah), sAl = sAh + 8192;
    const uint32_t sWh = sAh + 16384, sWl = sAh + 40960;

    const int tid = threadIdx.x, wid = tid >> 5, lane = tid & 31;
    const int wm = wid >> 2, wn = wid & 3;
    const int gid = lane >> 2, tig = lane & 3;
    const int m0 = blockIdx.x * 64;

    float acc[2][6][4];
#pragma unroll
    for (int i = 0; i < 2; ++i)
#pragma unroll
        for (int j = 0; j < 6; ++j)
#pragma unroll
            for (int k = 0; k < 4; ++k) acc[i][j][k] = 0.f;

    for (int ch = 0; ch < 16; ++ch) {
        const int c0 = ch * 64;
#pragma unroll
        for (int i = 0; i < 8; ++i) {
            int p = i * 256 + tid, r = p >> 5, cp = p & 31;
            float2 a = *(const float2*)&A[(size_t)(m0 + r) * CC + c0 + cp * 2];
            uint32_t hi, lo; splitpack2(a.x, a.y, hi, lo);
            uint32_t off = swz(r * 128 + cp * 4);
            *(uint32_t*)(Ah + off) = hi; *(uint32_t*)(Al + off) = lo;
        }
#pragma unroll
        for (int i = 0; i < 6; ++i) {
            int u = i * 256 + tid, r = u >> 3, q = u & 7;
            uint32_t off = swz(r * 128 + q * 16);
            *(uint4*)(Wh + off) = *(const uint4*)(g_Whi + (size_t)r * CC + c0 + q * 8);
            *(uint4*)(Wl + off) = *(const uint4*)(g_Wlo + (size_t)r * CC + c0 + q * 8);
        }
        __syncthreads();

#pragma unroll
        for (int ks = 0; ks < 4; ++ks) {
            const int kb = ks * 32;
            uint32_t ah0[4], ah1[4], al0[4], al1[4];
            lda(ah0, sAh, wm * 32, kb, lane);      lda(ah1, sAh, wm * 32 + 16, kb, lane);
            lda(al0, sAl, wm * 32, kb, lane);      lda(al1, sAl, wm * 32 + 16, kb, lane);
#pragma unroll
            for (int jp = 0; jp < 3; ++jp) {
                uint32_t bh[4], bl[4];
                ldb4(bh, sWh, wn * 48 + jp * 16, kb, lane);
                ldb4(bl, sWl, wn * 48 + jp * 16, kb, lane);
                mma2(acc[0][2 * jp], ah0, bh[0], bh[1]);
                mma2(acc[0][2 * jp], ah0, bl[0], bl[1]);
                mma2(acc[0][2 * jp], al0, bh[0], bh[1]);
                mma2(acc[1][2 * jp], ah1, bh[0], bh[1]);
                mma2(acc[1][2 * jp], ah1, bl[0], bl[1]);
                mma2(acc[1][2 * jp], al1, bh[0], bh[1]);
                mma2(acc[0][2 * jp + 1], ah0, bh[2], bh[3]);
                mma2(acc[0][2 * jp + 1], ah0, bl[2], bl[3]);
                mma2(acc[0][2 * jp + 1], al0, bh[2], bh[3]);
                mma2(acc[1][2 * jp + 1], ah1, bh[2], bh[3]);
                mma2(acc[1][2 * jp + 1], ah1, bl[2], bl[3]);
                mma2(acc[1][2 * jp + 1], al1, bh[2], bh[3]);
            }
        }
        __syncthreads();
    }

    // epilogue: cols 0-63 Q (x log2e), 64-127 K, 128-191 V — all split hi/lo
#pragma unroll
    for (int mf = 0; mf < 2; ++mf)
#pragma unroll
        for (int j = 0; j < 6; ++j) {
            int base = wn * 48 + j * 8;
            int reg = base >> 6;
            int col = (base & 63) + 2 * tig;
            int m = m0 + wm * 32 + mf * 16 + gid;
            uint32_t* oh = (reg == 0) ? (uint32_t*)g_Qhi
                         : (reg == 1) ? (uint32_t*)g_Khi : (uint32_t*)g_Vhi;
            uint32_t* ol = (reg == 0) ? (uint32_t*)g_Qlo
                         : (reg == 1) ? (uint32_t*)g_Klo : (uint32_t*)g_Vlo;
            float sc = (reg == 0) ? 1.44269504f : 1.f;
            uint32_t hi, lo;
            splitpack2(acc[mf][j][0] * sc, acc[mf][j][1] * sc, hi, lo);
            size_t o = ((size_t)m * HH + col) >> 1;
            oh[o] = hi; ol[o] = lo;
            splitpack2(acc[mf][j][2] * sc, acc[mf][j][3] * sc, hi, lo);
            o = ((size_t)(m + 8) * HH + col) >> 1;
            oh[o] = hi; ol[o] = lo;
        }
}

// ---------------------------------------------------------------------------
// K2 (pass1): D_s partials. Grid (32 s-tiles, 4 t-chunks, B), 256 threads.
// smem: Qh(16K) Ql(16K) Kh(8K) Kl(8K) red(1K) = 50176
// ---------------------------------------------------------------------------
__global__ void __launch_bounds__(256) pass1_colsum()
{
    extern __shared__ char smem[];
    char* Qh = smem;
    char* Ql = smem + 16384;
    char* Kh = smem + 32768;
    char* Kl = smem + 40960;
    float* red = (float*)(smem + 49152);      // [4][64]
    const uint32_t sQh = smem_u32(Qh), sQl = sQh + 16384;
    const uint32_t sKh = sQh + 32768, sKl = sQh + 40960;

    const int tid = threadIdx.x, wid = tid >> 5, lane = tid & 31;
    const int wm = wid >> 1, wn = wid & 1;
    const int gid = lane >> 2, tig = lane & 3;
    const int s0 = blockIdx.x * 64;
    const int ch = blockIdx.y;
    const int b  = blockIdx.z;

    {   // K tile (persistent)
        const __nv_bfloat16* sh = g_Khi + ((size_t)b * TT + s0) * HH;
        const __nv_bfloat16* sl = g_Klo + ((size_t)b * TT + s0) * HH;
#pragma unroll
        for (int j = 0; j < 2; ++j) {
            int u = j * 256 + tid, r = u >> 3, q = u & 7;
            uint32_t off = swz(r * 128 + q * 16);
            *(uint4*)(Kh + off) = *(const uint4*)(sh + r * HH + q * 8);
            *(uint4*)(Kl + off) = *(const uint4*)(sl + r * HH + q * 8);
        }
    }

    float csum[4][2];
#pragma unroll
    for (int i = 0; i < 4; ++i) { csum[i][0] = 0.f; csum[i][1] = 0.f; }

    const int tbase = ch * 512;
    for (int t0 = tbase; t0 < tbase + 512; t0 += 128) {
        if (t0 + 128 <= s0) continue;
        {
            const __nv_bfloat16* sh = g_Qhi + ((size_t)b * TT + t0) * HH;
            const __nv_bfloat16* sl = g_Qlo + ((size_t)b * TT + t0) * HH;
#pragma unroll
            for (int j = 0; j < 4; ++j) {
                int u = j * 256 + tid, r = u >> 3, q = u & 7;
                uint32_t off = swz(r * 128 + q * 16);
                *(uint4*)(Qh + off) = *(const uint4*)(sh + r * HH + q * 8);
                *(uint4*)(Ql + off) = *(const uint4*)(sl + r * HH + q * 8);
            }
        }
        __syncthreads();

        float acc[2][4][4];
#pragma unroll
        for (int i = 0; i < 2; ++i)
#pragma unroll
            for (int j = 0; j < 4; ++j)
#pragma unroll
                for (int k = 0; k < 4; ++k) acc[i][j][k] = 0.f;

#pragma unroll
        for (int ks = 0; ks < 4; ++ks) {
            const int kb = ks * 32;
            uint32_t ah0[4], ah1[4], al0[4], al1[4];
            lda(ah0, sQh, wm * 32, kb, lane);      lda(ah1, sQh, wm * 32 + 16, kb, lane);
            lda(al0, sQl, wm * 32, kb, lane);      lda(al1, sQl, wm * 32 + 16, kb, lane);
#pragma unroll
            for (int jp = 0; jp < 2; ++jp) {
                uint32_t bh[4], bl[4];
                ldb4(bh, sKh, wn * 32 + jp * 16, kb, lane);
                ldb4(bl, sKl, wn * 32 + jp * 16, kb, lane);
                mma2(acc[0][2 * jp], ah0, bh[0], bh[1]);
                mma2(acc[0][2 * jp], ah0, bl[0], bl[1]);
                mma2(acc[0][2 * jp], al0, bh[0], bh[1]);
                mma2(acc[1][2 * jp], ah1, bh[0], bh[1]);
                mma2(acc[1][2 * jp], ah1, bl[0], bl[1]);
                mma2(acc[1][2 * jp], al1, bh[0], bh[1]);
                mma2(acc[0][2 * jp + 1], ah0, bh[2], bh[3]);
                mma2(acc[0][2 * jp + 1], ah0, bl[2], bl[3]);
                mma2(acc[0][2 * jp + 1], al0, bh[2], bh[3]);
                mma2(acc[1][2 * jp + 1], ah1, bh[2], bh[3]);
                mma2(acc[1][2 * jp + 1], ah1, bl[2], bl[3]);
                mma2(acc[1][2 * jp + 1], al1, bh[2], bh[3]);
            }
        }

        // exp2 + (optional mask) + per-thread column sums
        if (t0 >= s0 + 64) {                 // fully unmasked tile
#pragma unroll
            for (int mf = 0; mf < 2; ++mf)
#pragma unroll
                for (int nf = 0; nf < 4; ++nf) {
                    csum[nf][0] += ex2(acc[mf][nf][0]) + ex2(acc[mf][nf][2]);
                    csum[nf][1] += ex2(acc[mf][nf][1]) + ex2(acc[mf][nf][3]);
                }
        } else {
#pragma unroll
            for (int mf = 0; mf < 2; ++mf) {
                int r0 = t0 + wm * 32 + mf * 16 + gid;
                int r1 = r0 + 8;
#pragma unroll
                for (int nf = 0; nf < 4; ++nf) {
                    int c = s0 + wn * 32 + nf * 8 + 2 * tig;
                    csum[nf][0] += ((r0 >= c) ? ex2(acc[mf][nf][0]) : 0.f)
                                 + ((r1 >= c) ? ex2(acc[mf][nf][2]) : 0.f);
                    csum[nf][1] += ((r0 >= c + 1) ? ex2(acc[mf][nf][1]) : 0.f)
                                 + ((r1 >= c + 1) ? ex2(acc[mf][nf][3]) : 0.f);
                }
            }
        }
        __syncthreads();
    }

#pragma unroll
    for (int nf = 0; nf < 4; ++nf)
#pragma unroll
        for (int d = 0; d < 2; ++d) {
            float v = csum[nf][d];
            v += __shfl_xor_sync(0xffffffffu, v, 4);
            v += __shfl_xor_sync(0xffffffffu, v, 8);
            v += __shfl_xor_sync(0xffffffffu, v, 16);
            if (lane < 4)
                red[wm * 64 + wn * 32 + nf * 8 + 2 * lane + d] = v;
        }
    __syncthreads();
    if (tid < 64)
        g_Dp[b][ch][s0 + tid] =
            red[tid] + red[64 + tid] + red[128 + tid] + red[192 + tid];
}

// ---------------------------------------------------------------------------
// K5 (pass2): fused S -> exp*rD -> O += P V. Grid (16 t-tiles, 4 s-splits, B).
// rD computed inline from g_Dp; V B-frags via ldmatrix.trans on [s][h] tiles.
// smem: Qh(16K) Ql(16K) Kh(8K) Kl(8K) Vh(8K) Vl(8K) rds(256B) = 65792
// ---------------------------------------------------------------------------
__global__ void __launch_bounds__(256) pass2_fused()
{
    extern __shared__ char smem[];
    char* Qh = smem;
    char* Ql = smem + 16384;
    char* Kh = smem + 32768;
    char* Kl = smem + 40960;
    char* Vh = smem + 49152;
    char* Vl = smem + 57344;
    float* rds = (float*)(smem + 65536);    // [64]
    const uint32_t sQh = smem_u32(Qh), sQl = sQh + 16384;
    const uint32_t sKh = sQh + 32768, sKl = sQh + 40960;
    const uint32_t sVh = sQh + 49152, sVl = sQh + 57344;

    const int tid = threadIdx.x, wid = tid >> 5, lane = tid & 31;
    const int wm = wid >> 1, wn = wid & 1;
    const int gid = lane >> 2, tig = lane & 3;
    const int ti = 15 - blockIdx.x;             // heavy tiles first
    const int q4 = blockIdx.y;
    const int b  = blockIdx.z;
    const int t0 = ti * 128;
    const int nS = 2 * (ti + 1);

    {   // Q tile (persistent)
        const __nv_bfloat16* sh = g_Qhi + ((size_t)b * TT + t0) * HH;
        const __nv_bfloat16* sl = g_Qlo + ((size_t)b * TT + t0) * HH;
#pragma unroll
        for (int j = 0; j < 4; ++j) {
            int u = j * 256 + tid, r = u >> 3, q = u & 7;
            uint32_t off = swz(r * 128 + q * 16);
            *(uint4*)(Qh + off) = *(const uint4*)(sh + r * HH + q * 8);
            *(uint4*)(Ql + off) = *(const uint4*)(sl + r * HH + q * 8);
        }
    }

    float O[2][8][4];
#pragma unroll
    for (int i = 0; i < 2; ++i)
#pragma unroll
        for (int j = 0; j < 8; ++j)
#pragma unroll
            for (int k = 0; k < 4; ++k) O[i][j][k] = 0.f;

    for (int si = q4; si < nS; si += 4) {
        const int s0 = si * 64;
        {
            const __nv_bfloat16* kh = g_Khi + ((size_t)b * TT + s0) * HH;
            const __nv_bfloat16* kl = g_Klo + ((size_t)b * TT + s0) * HH;
            const __nv_bfloat16* vh = g_Vhi + ((size_t)b * TT + s0) * HH;
            const __nv_bfloat16* vl = g_Vlo + ((size_t)b * TT + s0) * HH;
#pragma unroll
            for (int j = 0; j < 2; ++j) {
                int u = j * 256 + tid, r = u >> 3, q = u & 7;
                uint32_t off = swz(r * 128 + q * 16);
                *(uint4*)(Kh + off) = *(const uint4*)(kh + r * HH + q * 8);
                *(uint4*)(Kl + off) = *(const uint4*)(kl + r * HH + q * 8);
                *(uint4*)(Vh + off) = *(const uint4*)(vh + r * HH + q * 8);
                *(uint4*)(Vl + off) = *(const uint4*)(vl + r * HH + q * 8);
            }
        }
        if (tid < 64) {
            int s = s0 + tid;
            float d = g_Dp[b][0][s] + g_Dp[b][1][s] + g_Dp[b][2][s] + g_Dp[b][3][s];
            rds[tid] = 1.f / d;
        }
        __syncthreads();

        // --- S = Q K^T for this warp's 32x32 sub-tile ---
        float S[2][4][4];
#pragma unroll
        for (int i = 0; i < 2; ++i)
#pragma unroll
            for (int j = 0; j < 4; ++j)
#pragma unroll
                for (int k = 0; k < 4; ++k) S[i][j][k] = 0.f;

#pragma unroll
        for (int ks = 0; ks < 4; ++ks) {
            const int kb = ks * 32;
            uint32_t ah0[4], ah1[4], al0[4], al1[4];
            lda(ah0, sQh, wm * 32, kb, lane);      lda(ah1, sQh, wm * 32 + 16, kb, lane);
            lda(al0, sQl, wm * 32, kb, lane);      lda(al1, sQl, wm * 32 + 16, kb, lane);
#pragma unroll
            for (int jp = 0; jp < 2; ++jp) {
                uint32_t bh[4], bl[4];
                ldb4(bh, sKh, wn * 32 + jp * 16, kb, lane);
                ldb4(bl, sKl, wn * 32 + jp * 16, kb, lane);
                mma2(S[0][2 * jp], ah0, bh[0], bh[1]);
                mma2(S[0][2 * jp], ah0, bl[0], bl[1]);
                mma2(S[0][2 * jp], al0, bh[0], bh[1]);
                mma2(S[1][2 * jp], ah1, bh[0], bh[1]);
                mma2(S[1][2 * jp], ah1, bl[0], bl[1]);
                mma2(S[1][2 * jp], al1, bh[0], bh[1]);
                mma2(S[0][2 * jp + 1], ah0, bh[2], bh[3]);
                mma2(S[0][2 * jp + 1], ah0, bl[2], bl[3]);
                mma2(S[0][2 * jp + 1], al0, bh[2], bh[3]);
                mma2(S[1][2 * jp + 1], ah1, bh[2], bh[3]);
                mma2(S[1][2 * jp + 1], ah1, bl[2], bl[3]);
                mma2(S[1][2 * jp + 1], al1, bh[2], bh[3]);
            }
        }

        // --- P = exp2(S)*rD (masked on diagonal tiles); regs feed PV mma ---
        const bool nomask = (si < 2 * ti);
#pragma unroll
        for (int kss = 0; kss < 2; ++kss) {
            uint32_t ph[2][4], pl[2][4];
            const int cb = wn * 32 + kss * 16 + 2 * tig;   // local col
            const float rA0 = rds[cb], rA1 = rds[cb + 1];
            const float rB0 = rds[cb + 8], rB1 = rds[cb + 9];
#pragma unroll
            for (int mf = 0; mf < 2; ++mf) {
                float* cL = S[mf][2 * kss];
                float* cR = S[mf][2 * kss + 1];
                float e0, e1;
                if (nomask) {
                    e0 = ex2(cL[0]) * rA0; e1 = ex2(cL[1]) * rA1;
                    splitpack2(e0, e1, ph[mf][0], pl[mf][0]);
                    e0 = ex2(cL[2]) * rA0; e1 = ex2(cL[3]) * rA1;
                    splitpack2(e0, e1, ph[mf][1], pl[mf][1]);
                    e0 = ex2(cR[0]) * rB0; e1 = ex2(cR[1]) * rB1;
                    splitpack2(e0, e1, ph[mf][2], pl[mf][2]);
                    e0 = ex2(cR[2]) * rB0; e1 = ex2(cR[3]) * rB1;
                    splitpack2(e0, e1, ph[mf][3], pl[mf][3]);
                } else {
                    int r0 = t0 + wm * 32 + mf * 16 + gid;
                    int r1 = r0 + 8;
                    int cA = s0 + cb;
                    int cB = cA + 8;
                    e0 = (r0 >= cA)     ? ex2(cL[0]) * rA0 : 0.f;
                    e1 = (r0 >= cA + 1) ? ex2(cL[1]) * rA1 : 0.f;
                    splitpack2(e0, e1, ph[mf][0], pl[mf][0]);
                    e0 = (r1 >= cA)     ? ex2(cL[2]) * rA0 : 0.f;
                    e1 = (r1 >= cA + 1) ? ex2(cL[3]) * rA1 : 0.f;
                    splitpack2(e0, e1, ph[mf][1], pl[mf][1]);
                    e0 = (r0 >= cB)     ? ex2(cR[0]) * rB0 : 0.f;
                    e1 = (r0 >= cB + 1) ? ex2(cR[1]) * rB1 : 0.f;
                    splitpack2(e0, e1, ph[mf][2], pl[mf][2]);
                    e0 = (r1 >= cB)     ? ex2(cR[2]) * rB0 : 0.f;
                    e1 = (r1 >= cB + 1) ? ex2(cR[3]) * rB1 : 0.f;
                    splitpack2(e0, e1, ph[mf][3], pl[mf][3]);
                }
            }
            const int ksel = wn * 32 + kss * 16;   // k (=s) element offset in V tile
#pragma unroll
            for (int jp = 0; jp < 4; ++jp) {
                uint32_t bh[4], bl[4];
                ldb4t(bh, sVh, jp * 16, ksel, lane);
                ldb4t(bl, sVl, jp * 16, ksel, lane);
                mma2(O[0][2 * jp], ph[0], bh[0], bh[1]);
                mma2(O[0][2 * jp], ph[0], bl[0], bl[1]);
                mma2(O[0][2 * jp], pl[0], bh[0], bh[1]);
                mma2(O[1][2 * jp], ph[1], bh[0], bh[1]);
                mma2(O[1][2 * jp], ph[1], bl[0], bl[1]);
                mma2(O[1][2 * jp], pl[1], bh[0], bh[1]);
                mma2(O[0][2 * jp + 1], ph[0], bh[2], bh[3]);
                mma2(O[0][2 * jp + 1], ph[0], bl[2], bl[3]);
                mma2(O[0][2 * jp + 1], pl[0], bh[2], bh[3]);
                mma2(O[1][2 * jp + 1], ph[1], bh[2], bh[3]);
                mma2(O[1][2 * jp + 1], ph[1], bl[2], bl[3]);
                mma2(O[1][2 * jp + 1], pl[1], bh[2], bh[3]);
            }
        }
        __syncthreads();
    }

    // --- epilogue: combine the two n-warps (wn 0/1) then write g_O4 ---
    float* Ob = g_O4[q4] + ((size_t)b * TT + t0) * HH;
    if (q4 < nS) {
        float* Ored = (float*)(smem + 32768);   // 128x64 floats (reuses K/V)
        if (wn == 0) {
#pragma unroll
            for (int mf = 0; mf < 2; ++mf)
#pragma unroll
                for (int nh = 0; nh < 8; ++nh) {
                    int r0 = wm * 32 + mf * 16 + gid;
                    int c  = nh * 8 + 2 * tig;
                    Ored[r0 * 64 + c]           = O[mf][nh][0];
                    Ored[r0 * 64 + c + 1]       = O[mf][nh][1];
                    Ored[(r0 + 8) * 64 + c]     = O[mf][nh][2];
                    Ored[(r0 + 8) * 64 + c + 1] = O[mf][nh][3];
                }
        }
        __syncthreads();
        if (wn == 1) {
#pragma unroll
            for (int mf = 0; mf < 2; ++mf)
#pragma unroll
                for (int nh = 0; nh < 8; ++nh) {
                    int r0 = wm * 32 + mf * 16 + gid;
                    int c  = nh * 8 + 2 * tig;
                    Ob[(size_t)r0 * HH + c]           = O[mf][nh][0] + Ored[r0 * 64 + c];
                    Ob[(size_t)r0 * HH + c + 1]       = O[mf][nh][1] + Ored[r0 * 64 + c + 1];
                    Ob[(size_t)(r0 + 8) * HH + c]     = O[mf][nh][2] + Ored[(r0 + 8) * 64 + c];
                    Ob[(size_t)(r0 + 8) * HH + c + 1] = O[mf][nh][3] + Ored[(r0 + 8) * 64 + c + 1];
                }
        }
    } else {
        for (int i = tid; i < 128 * HH; i += 256) Ob[i] = 0.f;
    }
}

// ---------------------------------------------------------------------------
// K6: final reduce of the 4 s-split partials
// ---------------------------------------------------------------------------
__global__ void __launch_bounds__(256) oreduce(float* __restrict__ out)
{
    int i = blockIdx.x * 256 + threadIdx.x;
    out[i] = g_O4[0][i] + g_O4[1][i] + g_O4[2][i] + g_O4[3][i];
}

// ---------------------------------------------------------------------------
// Launch
// ---------------------------------------------------------------------------
extern "C" void kernel_launch(void* const* d_in, const int* in_sizes, int n_in,
                              void* d_out, int out_size)
{
    (void)in_sizes; (void)n_in; (void)out_size;
    const float* idx = (const float*)d_in[0];
    const float* Wk  = (const float*)d_in[1];
    const float* Wq  = (const float*)d_in[2];
    const float* Wv  = (const float*)d_in[3];
    float* out = (float*)d_out;

    cudaFuncSetAttribute(proj_mma,     cudaFuncAttributeMaxDynamicSharedMemorySize, 65536);
    cudaFuncSetAttribute(pass1_colsum, cudaFuncAttributeMaxDynamicSharedMemorySize, 50176);
    cudaFuncSetAttribute(pass2_fused,  cudaFuncAttributeMaxDynamicSharedMemorySize, 65792);

    prep_w<<<768, 256>>>(Wk, Wq, Wv);
    proj_mma<<<256, 256, 65536>>>(idx);
    pass1_colsum<<<dim3(32, 4, BB), 256, 50176>>>();
    pass2_fused<<<dim3(16, 4, BB), 256, 65792>>>();
    oreduce<<<(BB * TT * HH) / 256, 256>>>(out);
}

// round 8
// speedup vs baseline: 2.4376x; 1.0691x over previous
#include <cuda_runtime.h>
#include <cuda_bf16.h>
#include <cstdint>
#include <cstddef>

#define BB 8
#define TT 2048
#define CC 1024
#define HH 64

// ---------------------------------------------------------------------------
// Scratch (device globals; no allocations allowed)
// ---------------------------------------------------------------------------
__device__ __nv_bfloat16 g_Whi[3 * HH * CC];     // [Wq;Wk;Wv] stacked, hi
__device__ __nv_bfloat16 g_Wlo[3 * HH * CC];     // lo
__device__ __nv_bfloat16 g_Qhi[BB * TT * HH];    // Q * log2(e), hi/lo
__device__ __nv_bfloat16 g_Qlo[BB * TT * HH];
__device__ __nv_bfloat16 g_Khi[BB * TT * HH];
__device__ __nv_bfloat16 g_Klo[BB * TT * HH];
__device__ __nv_bfloat16 g_Vhi[BB * TT * HH];    // V [s][h] hi/lo (unscaled)
__device__ __nv_bfloat16 g_Vlo[BB * TT * HH];
__device__ float         g_Dp[BB][4][TT];        // colsum partials
__device__ float         g_O4[4][BB * TT * HH];  // 4-way split-s partial outputs

// ---------------------------------------------------------------------------
// Helpers (plain sm_80+ PTX, no 'a' features)
// ---------------------------------------------------------------------------
__device__ __forceinline__ uint32_t smem_u32(const void* p) {
    uint32_t r;
    asm("{ .reg .u64 t; cvta.to.shared.u64 t, %1; cvt.u32.u64 %0, t; }"
        : "=r"(r) : "l"(p));
    return r;
}
__device__ __forceinline__ uint32_t swz(uint32_t o) { return o ^ ((o >> 3) & 0x70); }

__device__ __forceinline__ void ldsm4(uint32_t (&r)[4], uint32_t addr) {
    asm volatile("ldmatrix.sync.aligned.m8n8.x4.shared.b16 {%0,%1,%2,%3}, [%4];"
                 : "=r"(r[0]), "=r"(r[1]), "=r"(r[2]), "=r"(r[3]) : "r"(addr));
}
__device__ __forceinline__ void ldsm4t(uint32_t (&r)[4], uint32_t addr) {
    asm volatile("ldmatrix.sync.aligned.m8n8.x4.trans.shared.b16 {%0,%1,%2,%3}, [%4];"
                 : "=r"(r[0]), "=r"(r[1]), "=r"(r[2]), "=r"(r[3]) : "r"(addr));
}
__device__ __forceinline__ void mma2(float (&c)[4], const uint32_t (&a)[4],
                                     uint32_t b0, uint32_t b1) {
    asm volatile(
        "mma.sync.aligned.m16n8k16.row.col.f32.bf16.bf16.f32 "
        "{%0,%1,%2,%3}, {%4,%5,%6,%7}, {%8,%9}, {%0,%1,%2,%3};"
        : "+f"(c[0]), "+f"(c[1]), "+f"(c[2]), "+f"(c[3])
        : "r"(a[0]), "r"(a[1]), "r"(a[2]), "r"(a[3]), "r"(b0), "r"(b1));
}
__device__ __forceinline__ float ex2(float x) {
    float y;
    asm("ex2.approx.f32 %0, %1;" : "=f"(y) : "f"(x));
    return y;
}

// A-fragment: 16x16 bf16, row-major tile rows = mr.., k-bytes = kb..kb+31
__device__ __forceinline__ void lda(uint32_t (&a)[4], uint32_t base, int mr,
                                    int kb, int lane) {
    ldsm4(a, base + swz(((mr + (lane & 15)) << 7) + kb + ((lane >> 4) << 4)));
}
// B-fragments for TWO n8 tiles (n16 x k16) from [n][k] row-major tile
__device__ __forceinline__ void ldb4(uint32_t (&b)[4], uint32_t base, int nr,
                                     int kb, int lane) {
    int row = nr + (lane & 7) + ((lane >> 4) << 3);
    int kx  = kb + (((lane >> 3) & 1) << 4);
    ldsm4(b, base + swz((row << 7) + kx));
}
// B-fragments for TWO n8 tiles from a [k][n] row-major tile via trans ldmatrix
__device__ __forceinline__ void ldb4t(uint32_t (&b)[4], uint32_t base, int nr,
                                      int ksel, int lane) {
    int row  = ksel + (lane & 7) + (((lane >> 3) & 1) << 3);
    int colb = nr * 2 + ((lane >> 4) << 4);
    ldsm4t(b, base + swz((row << 7) + colb));
}

__device__ __forceinline__ void split_bf16(float x, __nv_bfloat16& h, __nv_bfloat16& l) {
    h = __float2bfloat16(x);
    l = __float2bfloat16(x - __bfloat162float(h));
}
__device__ __forceinline__ void splitpack2(float x, float y, uint32_t& hi, uint32_t& lo) {
    __nv_bfloat16 hx, lx, hy, ly;
    split_bf16(x, hx, lx); split_bf16(y, hy, ly);
    __nv_bfloat162 H = __halves2bfloat162(hx, hy);
    __nv_bfloat162 L = __halves2bfloat162(lx, ly);
    hi = *(uint32_t*)&H; lo = *(uint32_t*)&L;
}

// ---------------------------------------------------------------------------
// K0: split weights once into stacked [192][1024] hi/lo (Q,K,V order)
// ---------------------------------------------------------------------------
__global__ void __launch_bounds__(256) prep_w(
    const float* __restrict__ Wk,
    const float* __restrict__ Wq,
    const float* __restrict__ Wv)
{
    int i = blockIdx.x * 256 + threadIdx.x;          // < 196608
    int w = i >> 16;
    int rem = i & 65535;
    const float* src = (w == 0) ? Wq : (w == 1) ? Wk : Wv;
    __nv_bfloat16 h, l;
    split_bf16(src[rem], h, l);
    g_Whi[i] = h; g_Wlo[i] = l;
}

// ---------------------------------------------------------------------------
// K1: QKV projection, fused. Grid 256 CTAs, 256 threads (2m x 4n warps).
// smem: Ah(8K) Al(8K) Wh(24K) Wl(24K) = 65536
// ---------------------------------------------------------------------------
__global__ void __launch_bounds__(256) proj_mma(const float* __restrict__ A)
{
    extern __shared__ char smem[];
    char* Ah = smem;
    char* Al = smem + 8192;
    char* Wh = smem + 16384;
    char* Wl = smem + 40960;
    const uint32_t sAh = smem_u32(Ah), sAl = sAh + 8192;
    const uint32_t sWh = sAh + 16384, sWl = sAh + 40960;

    const int tid = threadIdx.x, wid = tid >> 5, lane = tid & 31;
    const int wm = wid >> 2, wn = wid & 3;
    const int gid = lane >> 2, tig = lane & 3;
    const int m0 = blockIdx.x * 64;

    float acc[2][6][4];
#pragma unroll
    for (int i = 0; i < 2; ++i)
#pragma unroll
        for (int j = 0; j < 6; ++j)
#pragma unroll
            for (int k = 0; k < 4; ++k) acc[i][j][k] = 0.f;

    for (int ch = 0; ch < 16; ++ch) {
        const int c0 = ch * 64;
#pragma unroll
        for (int i = 0; i < 8; ++i) {
            int p = i * 256 + tid, r = p >> 5, cp = p & 31;
            float2 a = *(const float2*)&A[(size_t)(m0 + r) * CC + c0 + cp * 2];
            uint32_t hi, lo; splitpack2(a.x, a.y, hi, lo);
            uint32_t off = swz(r * 128 + cp * 4);
            *(uint32_t*)(Ah + off) = hi; *(uint32_t*)(Al + off) = lo;
        }
#pragma unroll
        for (int i = 0; i < 6; ++i) {
            int u = i * 256 + tid, r = u >> 3, q = u & 7;
            uint32_t off = swz(r * 128 + q * 16);
            *(uint4*)(Wh + off) = *(const uint4*)(g_Whi + (size_t)r * CC + c0 + q * 8);
            *(uint4*)(Wl + off) = *(const uint4*)(g_Wlo + (size_t)r * CC + c0 + q * 8);
        }
        __syncthreads();

#pragma unroll
        for (int ks = 0; ks < 4; ++ks) {
            const int kb = ks * 32;
            uint32_t ah0[4], ah1[4], al0[4], al1[4];
            lda(ah0, sAh, wm * 32, kb, lane);      lda(ah1, sAh, wm * 32 + 16, kb, lane);
            lda(al0, sAl, wm * 32, kb, lane);      lda(al1, sAl, wm * 32 + 16, kb, lane);
#pragma unroll
            for (int jp = 0; jp < 3; ++jp) {
                uint32_t bh[4], bl[4];
                ldb4(bh, sWh, wn * 48 + jp * 16, kb, lane);
                ldb4(bl, sWl, wn * 48 + jp * 16, kb, lane);
                mma2(acc[0][2 * jp], ah0, bh[0], bh[1]);
                mma2(acc[0][2 * jp], ah0, bl[0], bl[1]);
                mma2(acc[0][2 * jp], al0, bh[0], bh[1]);
                mma2(acc[1][2 * jp], ah1, bh[0], bh[1]);
                mma2(acc[1][2 * jp], ah1, bl[0], bl[1]);
                mma2(acc[1][2 * jp], al1, bh[0], bh[1]);
                mma2(acc[0][2 * jp + 1], ah0, bh[2], bh[3]);
                mma2(acc[0][2 * jp + 1], ah0, bl[2], bl[3]);
                mma2(acc[0][2 * jp + 1], al0, bh[2], bh[3]);
                mma2(acc[1][2 * jp + 1], ah1, bh[2], bh[3]);
                mma2(acc[1][2 * jp + 1], ah1, bl[2], bl[3]);
                mma2(acc[1][2 * jp + 1], al1, bh[2], bh[3]);
            }
        }
        __syncthreads();
    }

    // epilogue: cols 0-63 Q (x log2e), 64-127 K, 128-191 V — all split hi/lo
#pragma unroll
    for (int mf = 0; mf < 2; ++mf)
#pragma unroll
        for (int j = 0; j < 6; ++j) {
            int base = wn * 48 + j * 8;
            int reg = base >> 6;
            int col = (base & 63) + 2 * tig;
            int m = m0 + wm * 32 + mf * 16 + gid;
            uint32_t* oh = (reg == 0) ? (uint32_t*)g_Qhi
                         : (reg == 1) ? (uint32_t*)g_Khi : (uint32_t*)g_Vhi;
            uint32_t* ol = (reg == 0) ? (uint32_t*)g_Qlo
                         : (reg == 1) ? (uint32_t*)g_Klo : (uint32_t*)g_Vlo;
            float sc = (reg == 0) ? 1.44269504f : 1.f;
            uint32_t hi, lo;
            splitpack2(acc[mf][j][0] * sc, acc[mf][j][1] * sc, hi, lo);
            size_t o = ((size_t)m * HH + col) >> 1;
            oh[o] = hi; ol[o] = lo;
            splitpack2(acc[mf][j][2] * sc, acc[mf][j][3] * sc, hi, lo);
            o = ((size_t)(m + 8) * HH + col) >> 1;
            oh[o] = hi; ol[o] = lo;
        }
}

// ---------------------------------------------------------------------------
// K2 (pass1): D_s partials. Grid (32 s-tiles, 4 t-chunks, B), 256 threads
// (4m x 2n warps, warp tile 16x32, t-chunk 64). 2 CTAs/SM.
// smem: Qh(8K) Ql(8K) Kh(8K) Kl(8K) red(1K) = 33792
// ---------------------------------------------------------------------------
__global__ void __launch_bounds__(256, 2) pass1_colsum()
{
    extern __shared__ char smem[];
    char* Qh = smem;
    char* Ql = smem + 8192;
    char* Kh = smem + 16384;
    char* Kl = smem + 24576;
    float* red = (float*)(smem + 32768);      // [4][64]
    const uint32_t sQh = smem_u32(Qh), sQl = sQh + 8192;
    const uint32_t sKh = sQh + 16384, sKl = sQh + 24576;

    const int tid = threadIdx.x, wid = tid >> 5, lane = tid & 31;
    const int wm = wid >> 1, wn = wid & 1;
    const int gid = lane >> 2, tig = lane & 3;
    const int s0 = blockIdx.x * 64;
    const int ch = blockIdx.y;
    const int b  = blockIdx.z;

    {   // K tile (persistent) 64x64 hi/lo
        const __nv_bfloat16* sh = g_Khi + ((size_t)b * TT + s0) * HH;
        const __nv_bfloat16* sl = g_Klo + ((size_t)b * TT + s0) * HH;
#pragma unroll
        for (int j = 0; j < 2; ++j) {
            int u = j * 256 + tid, r = u >> 3, q = u & 7;
            uint32_t off = swz(r * 128 + q * 16);
            *(uint4*)(Kh + off) = *(const uint4*)(sh + r * HH + q * 8);
            *(uint4*)(Kl + off) = *(const uint4*)(sl + r * HH + q * 8);
        }
    }

    float csum[4][2];
#pragma unroll
    for (int i = 0; i < 4; ++i) { csum[i][0] = 0.f; csum[i][1] = 0.f; }

    const int tbase = ch * 512;
    for (int t0 = tbase; t0 < tbase + 512; t0 += 64) {
        if (t0 + 64 <= s0) continue;
        {   // Q chunk 64x64 hi/lo
            const __nv_bfloat16* sh = g_Qhi + ((size_t)b * TT + t0) * HH;
            const __nv_bfloat16* sl = g_Qlo + ((size_t)b * TT + t0) * HH;
#pragma unroll
            for (int j = 0; j < 2; ++j) {
                int u = j * 256 + tid, r = u >> 3, q = u & 7;
                uint32_t off = swz(r * 128 + q * 16);
                *(uint4*)(Qh + off) = *(const uint4*)(sh + r * HH + q * 8);
                *(uint4*)(Ql + off) = *(const uint4*)(sl + r * HH + q * 8);
            }
        }
        __syncthreads();

        float acc[4][4];
#pragma unroll
        for (int j = 0; j < 4; ++j)
#pragma unroll
            for (int k = 0; k < 4; ++k) acc[j][k] = 0.f;

#pragma unroll
        for (int ks = 0; ks < 4; ++ks) {
            const int kb = ks * 32;
            uint32_t ah[4], al[4];
            lda(ah, sQh, wm * 16, kb, lane);
            lda(al, sQl, wm * 16, kb, lane);
#pragma unroll
            for (int jp = 0; jp < 2; ++jp) {
                uint32_t bh[4], bl[4];
                ldb4(bh, sKh, wn * 32 + jp * 16, kb, lane);
                ldb4(bl, sKl, wn * 32 + jp * 16, kb, lane);
                mma2(acc[2 * jp], ah, bh[0], bh[1]);
                mma2(acc[2 * jp], ah, bl[0], bl[1]);
                mma2(acc[2 * jp], al, bh[0], bh[1]);
                mma2(acc[2 * jp + 1], ah, bh[2], bh[3]);
                mma2(acc[2 * jp + 1], ah, bl[2], bl[3]);
                mma2(acc[2 * jp + 1], al, bh[2], bh[3]);
            }
        }

        // exp2 + (mask only on diagonal tile) + per-thread column sums
        if (t0 >= s0 + 64) {                 // fully unmasked tile
#pragma unroll
            for (int nf = 0; nf < 4; ++nf) {
                csum[nf][0] += ex2(acc[nf][0]) + ex2(acc[nf][2]);
                csum[nf][1] += ex2(acc[nf][1]) + ex2(acc[nf][3]);
            }
        } else {
            int r0 = t0 + wm * 16 + gid;
            int r1 = r0 + 8;
#pragma unroll
            for (int nf = 0; nf < 4; ++nf) {
                int c = s0 + wn * 32 + nf * 8 + 2 * tig;
                csum[nf][0] += ((r0 >= c) ? ex2(acc[nf][0]) : 0.f)
                             + ((r1 >= c) ? ex2(acc[nf][2]) : 0.f);
                csum[nf][1] += ((r0 >= c + 1) ? ex2(acc[nf][1]) : 0.f)
                             + ((r1 >= c + 1) ? ex2(acc[nf][3]) : 0.f);
            }
        }
        __syncthreads();
    }

#pragma unroll
    for (int nf = 0; nf < 4; ++nf)
#pragma unroll
        for (int d = 0; d < 2; ++d) {
            float v = csum[nf][d];
            v += __shfl_xor_sync(0xffffffffu, v, 4);
            v += __shfl_xor_sync(0xffffffffu, v, 8);
            v += __shfl_xor_sync(0xffffffffu, v, 16);
            if (lane < 4)
                red[wm * 64 + wn * 32 + nf * 8 + 2 * lane + d] = v;
        }
    __syncthreads();
    if (tid < 64)
        g_Dp[b][ch][s0 + tid] =
            red[tid] + red[64 + tid] + red[128 + tid] + red[192 + tid];
}

// ---------------------------------------------------------------------------
// K5 (pass2): fused S -> exp*rD -> O += P V. Grid (32 t-tiles, 4 s-splits, B).
// 256 threads (4m x 2n warps, warp tile 16x32, t-tile 64). 2 CTAs/SM.
// smem: Qh(8K) Ql(8K) Kh(8K) Kl(8K) Vh(8K) Vl(8K) rds(256B) = 49408
// ---------------------------------------------------------------------------
__global__ void __launch_bounds__(256, 2) pass2_fused()
{
    extern __shared__ char smem[];
    char* Qh = smem;
    char* Ql = smem + 8192;
    char* Kh = smem + 16384;
    char* Kl = smem + 24576;
    char* Vh = smem + 32768;
    char* Vl = smem + 40960;
    float* rds = (float*)(smem + 49152);    // [64]
    const uint32_t sQh = smem_u32(Qh), sQl = sQh + 8192;
    const uint32_t sKh = sQh + 16384, sKl = sQh + 24576;
    const uint32_t sVh = sQh + 32768, sVl = sQh + 40960;

    const int tid = threadIdx.x, wid = tid >> 5, lane = tid & 31;
    const int wm = wid >> 1, wn = wid & 1;
    const int gid = lane >> 2, tig = lane & 3;
    const int ti = 31 - blockIdx.x;             // heavy tiles first
    const int q4 = blockIdx.y;
    const int b  = blockIdx.z;
    const int t0 = ti * 64;
    const int nS = ti + 1;

    {   // Q tile (persistent) 64x64 hi/lo
        const __nv_bfloat16* sh = g_Qhi + ((size_t)b * TT + t0) * HH;
        const __nv_bfloat16* sl = g_Qlo + ((size_t)b * TT + t0) * HH;
#pragma unroll
        for (int j = 0; j < 2; ++j) {
            int u = j * 256 + tid, r = u >> 3, q = u & 7;
            uint32_t off = swz(r * 128 + q * 16);
            *(uint4*)(Qh + off) = *(const uint4*)(sh + r * HH + q * 8);
            *(uint4*)(Ql + off) = *(const uint4*)(sl + r * HH + q * 8);
        }
    }

    float O[8][4];
#pragma unroll
    for (int j = 0; j < 8; ++j)
#pragma unroll
        for (int k = 0; k < 4; ++k) O[j][k] = 0.f;

    for (int si = q4; si < nS; si += 4) {
        const int s0 = si * 64;
        {
            const __nv_bfloat16* kh = g_Khi + ((size_t)b * TT + s0) * HH;
            const __nv_bfloat16* kl = g_Klo + ((size_t)b * TT + s0) * HH;
            const __nv_bfloat16* vh = g_Vhi + ((size_t)b * TT + s0) * HH;
            const __nv_bfloat16* vl = g_Vlo + ((size_t)b * TT + s0) * HH;
            int u = tid, r = u >> 3, q = u & 7;
            uint32_t off = swz(r * 128 + q * 16);
            *(uint4*)(Kh + off) = *(const uint4*)(kh + r * HH + q * 8);
            *(uint4*)(Kl + off) = *(const uint4*)(kl + r * HH + q * 8);
            *(uint4*)(Vh + off) = *(const uint4*)(vh + r * HH + q * 8);
            *(uint4*)(Vl + off) = *(const uint4*)(vl + r * HH + q * 8);
            u = tid + 256; r = u >> 3; q = u & 7;
            off = swz(r * 128 + q * 16);
            *(uint4*)(Kh + off) = *(const uint4*)(kh + r * HH + q * 8);
            *(uint4*)(Kl + off) = *(const uint4*)(kl + r * HH + q * 8);
            *(uint4*)(Vh + off) = *(const uint4*)(vh + r * HH + q * 8);
            *(uint4*)(Vl + off) = *(const uint4*)(vl + r * HH + q * 8);
        }
        if (tid < 64) {
            int s = s0 + tid;
            float d = g_Dp[b][0][s] + g_Dp[b][1][s] + g_Dp[b][2][s] + g_Dp[b][3][s];
            rds[tid] = 1.f / d;
        }
        __syncthreads();

        // --- S = Q K^T for this warp's 16x32 sub-tile ---
        float S[4][4];
#pragma unroll
        for (int j = 0; j < 4; ++j)
#pragma unroll
            for (int k = 0; k < 4; ++k) S[j][k] = 0.f;

#pragma unroll
        for (int ks = 0; ks < 4; ++ks) {
            const int kb = ks * 32;
            uint32_t ah[4], al[4];
            lda(ah, sQh, wm * 16, kb, lane);
            lda(al, sQl, wm * 16, kb, lane);
#pragma unroll
            for (int jp = 0; jp < 2; ++jp) {
                uint32_t bh[4], bl[4];
                ldb4(bh, sKh, wn * 32 + jp * 16, kb, lane);
                ldb4(bl, sKl, wn * 32 + jp * 16, kb, lane);
                mma2(S[2 * jp], ah, bh[0], bh[1]);
                mma2(S[2 * jp], ah, bl[0], bl[1]);
                mma2(S[2 * jp], al, bh[0], bh[1]);
                mma2(S[2 * jp + 1], ah, bh[2], bh[3]);
                mma2(S[2 * jp + 1], ah, bl[2], bl[3]);
                mma2(S[2 * jp + 1], al, bh[2], bh[3]);
            }
        }

        // --- P = exp2(S)*rD (masked on diagonal tile); regs feed PV mma ---
        const bool nomask = (si < ti);
#pragma unroll
        for (int kss = 0; kss < 2; ++kss) {
            uint32_t ph[4], pl[4];
            const int cb = wn * 32 + kss * 16 + 2 * tig;   // local col
            const float rA0 = rds[cb], rA1 = rds[cb + 1];
            const float rB0 = rds[cb + 8], rB1 = rds[cb + 9];
            float* cL = S[2 * kss];
            float* cR = S[2 * kss + 1];
            float e0, e1;
            if (nomask) {
                e0 = ex2(cL[0]) * rA0; e1 = ex2(cL[1]) * rA1;
                splitpack2(e0, e1, ph[0], pl[0]);
                e0 = ex2(cL[2]) * rA0; e1 = ex2(cL[3]) * rA1;
                splitpack2(e0, e1, ph[1], pl[1]);
                e0 = ex2(cR[0]) * rB0; e1 = ex2(cR[1]) * rB1;
                splitpack2(e0, e1, ph[2], pl[2]);
                e0 = ex2(cR[2]) * rB0; e1 = ex2(cR[3]) * rB1;
                splitpack2(e0, e1, ph[3], pl[3]);
            } else {
                int r0 = t0 + wm * 16 + gid;
                int r1 = r0 + 8;
                int cA = s0 + cb;
                int cB = cA + 8;
                e0 = (r0 >= cA)     ? ex2(cL[0]) * rA0 : 0.f;
                e1 = (r0 >= cA + 1) ? ex2(cL[1]) * rA1 : 0.f;
                splitpack2(e0, e1, ph[0], pl[0]);
                e0 = (r1 >= cA)     ? ex2(cL[2]) * rA0 : 0.f;
                e1 = (r1 >= cA + 1) ? ex2(cL[3]) * rA1 : 0.f;
                splitpack2(e0, e1, ph[1], pl[1]);
                e0 = (r0 >= cB)     ? ex2(cR[0]) * rB0 : 0.f;
                e1 = (r0 >= cB + 1) ? ex2(cR[1]) * rB1 : 0.f;
                splitpack2(e0, e1, ph[2], pl[2]);
                e0 = (r1 >= cB)     ? ex2(cR[2]) * rB0 : 0.f;
                e1 = (r1 >= cB + 1) ? ex2(cR[3]) * rB1 : 0.f;
                splitpack2(e0, e1, ph[3], pl[3]);
            }
            const int ksel = wn * 32 + kss * 16;   // k (=s) element offset in V
#pragma unroll
            for (int jp = 0; jp < 4; ++jp) {
                uint32_t bh[4], bl[4];
                ldb4t(bh, sVh, jp * 16, ksel, lane);
                ldb4t(bl, sVl, jp * 16, ksel, lane);
                mma2(O[2 * jp], ph, bh[0], bh[1]);
                mma2(O[2 * jp], ph, bl[0], bl[1]);
                mma2(O[2 * jp], pl, bh[0], bh[1]);
                mma2(O[2 * jp + 1], ph, bh[2], bh[3]);
                mma2(O[2 * jp + 1], ph, bl[2], bl[3]);
                mma2(O[2 * jp + 1], pl, bh[2], bh[3]);
            }
        }
        __syncthreads();
    }

    // --- epilogue: combine the two n-warps (wn 0/1) then write g_O4 ---
    float* Ob = g_O4[q4] + ((size_t)b * TT + t0) * HH;
    if (q4 < nS) {
        float* Ored = (float*)(smem + 16384);   // 64x64 floats (reuses K/V)
        if (wn == 0) {
#pragma unroll
            for (int nh = 0; nh < 8; ++nh) {
                int r0 = wm * 16 + gid;
                int c  = nh * 8 + 2 * tig;
                Ored[r0 * 64 + c]           = O[nh][0];
                Ored[r0 * 64 + c + 1]       = O[nh][1];
                Ored[(r0 + 8) * 64 + c]     = O[nh][2];
                Ored[(r0 + 8) * 64 + c + 1] = O[nh][3];
            }
        }
        __syncthreads();
        if (wn == 1) {
#pragma unroll
            for (int nh = 0; nh < 8; ++nh) {
                int r0 = wm * 16 + gid;
                int c  = nh * 8 + 2 * tig;
                Ob[(size_t)r0 * HH + c]           = O[nh][0] + Ored[r0 * 64 + c];
                Ob[(size_t)r0 * HH + c + 1]       = O[nh][1] + Ored[r0 * 64 + c + 1];
                Ob[(size_t)(r0 + 8) * HH + c]     = O[nh][2] + Ored[(r0 + 8) * 64 + c];
                Ob[(size_t)(r0 + 8) * HH + c + 1] = O[nh][3] + Ored[(r0 + 8) * 64 + c + 1];
            }
        }
    } else {
        for (int i = tid; i < 64 * HH; i += 256) Ob[i] = 0.f;
    }
}

// ---------------------------------------------------------------------------
// K6: final reduce of the 4 s-split partials
// ---------------------------------------------------------------------------
__global__ void __launch_bounds__(256) oreduce(float* __restrict__ out)
{
    int i = blockIdx.x * 256 + threadIdx.x;
    out[i] = g_O4[0][i] + g_O4[1][i] + g_O4[2][i] + g_O4[3][i];
}

// ---------------------------------------------------------------------------
// Launch
// ---------------------------------------------------------------------------
extern "C" void kernel_launch(void* const* d_in, const int* in_sizes, int n_in,
                              void* d_out, int out_size)
{
    (void)in_sizes; (void)n_in; (void)out_size;
    const float* idx = (const float*)d_in[0];
    const float* Wk  = (const float*)d_in[1];
    const float* Wq  = (const float*)d_in[2];
    const float* Wv  = (const float*)d_in[3];
    float* out = (float*)d_out;

    cudaFuncSetAttribute(proj_mma,     cudaFuncAttributeMaxDynamicSharedMemorySize, 65536);
    cudaFuncSetAttribute(pass1_colsum, cudaFuncAttributeMaxDynamicSharedMemorySize, 33792);
    cudaFuncSetAttribute(pass2_fused,  cudaFuncAttributeMaxDynamicSharedMemorySize, 49408);

    prep_w<<<768, 256>>>(Wk, Wq, Wv);
    proj_mma<<<256, 256, 65536>>>(idx);
    pass1_colsum<<<dim3(32, 4, BB), 256, 33792>>>();
    pass2_fused<<<dim3(32, 4, BB), 256, 49408>>>();
    oreduce<<<(BB * TT * HH) / 256, 256>>>(out);
}

// round 9
// speedup vs baseline: 2.4555x; 1.0073x over previous
#include <cuda_runtime.h>
#include <cuda_bf16.h>
#include <cstdint>
#include <cstddef>

#define BB 8
#define TT 2048
#define CC 1024
#define HH 64

// ---------------------------------------------------------------------------
// Scratch (device globals; no allocations allowed)
// ---------------------------------------------------------------------------
__device__ __nv_bfloat16 g_Whi[3 * HH * CC];     // [Wq;Wk;Wv] stacked, hi
__device__ __nv_bfloat16 g_Wlo[3 * HH * CC];     // lo
__device__ __nv_bfloat16 g_Qhi[BB * TT * HH];    // Q * log2(e), hi/lo
__device__ __nv_bfloat16 g_Qlo[BB * TT * HH];
__device__ __nv_bfloat16 g_Khi[BB * TT * HH];
__device__ __nv_bfloat16 g_Klo[BB * TT * HH];
__device__ __nv_bfloat16 g_Vhi[BB * TT * HH];    // V [s][h] hi/lo (unscaled)
__device__ __nv_bfloat16 g_Vlo[BB * TT * HH];
__device__ float         g_Dp[BB][4][TT];        // colsum partials
__device__ float         g_O4[4][BB * TT * HH];  // 4-way split-s partial outputs

// ---------------------------------------------------------------------------
// Helpers (plain sm_80+ PTX, no 'a' features)
// ---------------------------------------------------------------------------
__device__ __forceinline__ uint32_t smem_u32(const void* p) {
    uint32_t r;
    asm("{ .reg .u64 t; cvta.to.shared.u64 t, %1; cvt.u32.u64 %0, t; }"
        : "=r"(r) : "l"(p));
    return r;
}
__device__ __forceinline__ uint32_t swz(uint32_t o) { return o ^ ((o >> 3) & 0x70); }

__device__ __forceinline__ void ldsm4(uint32_t (&r)[4], uint32_t addr) {
    asm volatile("ldmatrix.sync.aligned.m8n8.x4.shared.b16 {%0,%1,%2,%3}, [%4];"
                 : "=r"(r[0]), "=r"(r[1]), "=r"(r[2]), "=r"(r[3]) : "r"(addr));
}
__device__ __forceinline__ void ldsm4t(uint32_t (&r)[4], uint32_t addr) {
    asm volatile("ldmatrix.sync.aligned.m8n8.x4.trans.shared.b16 {%0,%1,%2,%3}, [%4];"
                 : "=r"(r[0]), "=r"(r[1]), "=r"(r[2]), "=r"(r[3]) : "r"(addr));
}
__device__ __forceinline__ void mma2(float (&c)[4], const uint32_t (&a)[4],
                                     uint32_t b0, uint32_t b1) {
    asm volatile(
        "mma.sync.aligned.m16n8k16.row.col.f32.bf16.bf16.f32 "
        "{%0,%1,%2,%3}, {%4,%5,%6,%7}, {%8,%9}, {%0,%1,%2,%3};"
        : "+f"(c[0]), "+f"(c[1]), "+f"(c[2]), "+f"(c[3])
        : "r"(a[0]), "r"(a[1]), "r"(a[2]), "r"(a[3]), "r"(b0), "r"(b1));
}
__device__ __forceinline__ float ex2(float x) {
    float y;
    asm("ex2.approx.f32 %0, %1;" : "=f"(y) : "f"(x));
    return y;
}

// A-fragment: 16x16 bf16, row-major tile rows = mr.., k-bytes = kb..kb+31
__device__ __forceinline__ void lda(uint32_t (&a)[4], uint32_t base, int mr,
                                    int kb, int lane) {
    ldsm4(a, base + swz(((mr + (lane & 15)) << 7) + kb + ((lane >> 4) << 4)));
}
// B-fragments for TWO n8 tiles (n16 x k16) from [n][k] row-major tile
__device__ __forceinline__ void ldb4(uint32_t (&b)[4], uint32_t base, int nr,
                                     int kb, int lane) {
    int row = nr + (lane & 7) + ((lane >> 4) << 3);
    int kx  = kb + (((lane >> 3) & 1) << 4);
    ldsm4(b, base + swz((row << 7) + kx));
}
// B-fragments for TWO n8 tiles from a [k][n] row-major tile via trans ldmatrix
__device__ __forceinline__ void ldb4t(uint32_t (&b)[4], uint32_t base, int nr,
                                      int ksel, int lane) {
    int row  = ksel + (lane & 7) + (((lane >> 3) & 1) << 3);
    int colb = nr * 2 + ((lane >> 4) << 4);
    ldsm4t(b, base + swz((row << 7) + colb));
}

__device__ __forceinline__ void split_bf16(float x, __nv_bfloat16& h, __nv_bfloat16& l) {
    h = __float2bfloat16(x);
    l = __float2bfloat16(x - __bfloat162float(h));
}
__device__ __forceinline__ void splitpack2(float x, float y, uint32_t& hi, uint32_t& lo) {
    __nv_bfloat16 hx, lx, hy, ly;
    split_bf16(x, hx, lx); split_bf16(y, hy, ly);
    __nv_bfloat162 H = __halves2bfloat162(hx, hy);
    __nv_bfloat162 L = __halves2bfloat162(lx, ly);
    hi = *(uint32_t*)&H; lo = *(uint32_t*)&L;
}

// ---------------------------------------------------------------------------
// K0: split weights once into stacked [192][1024] hi/lo (Q,K,V order)
// ---------------------------------------------------------------------------
__global__ void __launch_bounds__(256) prep_w(
    const float* __restrict__ Wk,
    const float* __restrict__ Wq,
    const float* __restrict__ Wv)
{
    int i = blockIdx.x * 256 + threadIdx.x;          // < 196608
    int w = i >> 16;
    int rem = i & 65535;
    const float* src = (w == 0) ? Wq : (w == 1) ? Wk : Wv;
    __nv_bfloat16 h, l;
    split_bf16(src[rem], h, l);
    g_Whi[i] = h; g_Wlo[i] = l;
}

// ---------------------------------------------------------------------------
// K1: QKV projection, fused. Grid 256 CTAs, 256 threads (2m x 4n warps).
// smem: Ah(8K) Al(8K) Wh(24K) Wl(24K) = 65536
// ---------------------------------------------------------------------------
__global__ void __launch_bounds__(256) proj_mma(const float* __restrict__ A)
{
    extern __shared__ char smem[];
    char* Ah = smem;
    char* Al = smem + 8192;
    char* Wh = smem + 16384;
    char* Wl = smem + 40960;
    const uint32_t sAh = smem_u32(Ah), sAl = sAh + 8192;
    const uint32_t sWh = sAh + 16384, sWl = sAh + 40960;

    const int tid = threadIdx.x, wid = tid >> 5, lane = tid & 31;
    const int wm = wid >> 2, wn = wid & 3;
    const int gid = lane >> 2, tig = lane & 3;
    const int m0 = blockIdx.x * 64;

    float acc[2][6][4];
#pragma unroll
    for (int i = 0; i < 2; ++i)
#pragma unroll
        for (int j = 0; j < 6; ++j)
#pragma unroll
            for (int k = 0; k < 4; ++k) acc[i][j][k] = 0.f;

    for (int ch = 0; ch < 16; ++ch) {
        const int c0 = ch * 64;
#pragma unroll
        for (int i = 0; i < 8; ++i) {
            int p = i * 256 + tid, r = p >> 5, cp = p & 31;
            float2 a = *(const float2*)&A[(size_t)(m0 + r) * CC + c0 + cp * 2];
            uint32_t hi, lo; splitpack2(a.x, a.y, hi, lo);
            uint32_t off = swz(r * 128 + cp * 4);
            *(uint32_t*)(Ah + off) = hi; *(uint32_t*)(Al + off) = lo;
        }
#pragma unroll
        for (int i = 0; i < 6; ++i) {
            int u = i * 256 + tid, r = u >> 3, q = u & 7;
            uint32_t off = swz(r * 128 + q * 16);
            *(uint4*)(Wh + off) = *(const uint4*)(g_Whi + (size_t)r * CC + c0 + q * 8);
            *(uint4*)(Wl + off) = *(const uint4*)(g_Wlo + (size_t)r * CC + c0 + q * 8);
        }
        __syncthreads();

#pragma unroll
        for (int ks = 0; ks < 4; ++ks) {
            const int kb = ks * 32;
            uint32_t ah0[4], ah1[4], al0[4], al1[4];
            lda(ah0, sAh, wm * 32, kb, lane);      lda(ah1, sAh, wm * 32 + 16, kb, lane);
            lda(al0, sAl, wm * 32, kb, lane);      lda(al1, sAl, wm * 32 + 16, kb, lane);
#pragma unroll
            for (int jp = 0; jp < 3; ++jp) {
                uint32_t bh[4], bl[4];
                ldb4(bh, sWh, wn * 48 + jp * 16, kb, lane);
                ldb4(bl, sWl, wn * 48 + jp * 16, kb, lane);
                mma2(acc[0][2 * jp], ah0, bh[0], bh[1]);
                mma2(acc[0][2 * jp], ah0, bl[0], bl[1]);
                mma2(acc[0][2 * jp], al0, bh[0], bh[1]);
                mma2(acc[1][2 * jp], ah1, bh[0], bh[1]);
                mma2(acc[1][2 * jp], ah1, bl[0], bl[1]);
                mma2(acc[1][2 * jp], al1, bh[0], bh[1]);
                mma2(acc[0][2 * jp + 1], ah0, bh[2], bh[3]);
                mma2(acc[0][2 * jp + 1], ah0, bl[2], bl[3]);
                mma2(acc[0][2 * jp + 1], al0, bh[2], bh[3]);
                mma2(acc[1][2 * jp + 1], ah1, bh[2], bh[3]);
                mma2(acc[1][2 * jp + 1], ah1, bl[2], bl[3]);
                mma2(acc[1][2 * jp + 1], al1, bh[2], bh[3]);
            }
        }
        __syncthreads();
    }

    // epilogue: cols 0-63 Q (x log2e), 64-127 K, 128-191 V — all split hi/lo
#pragma unroll
    for (int mf = 0; mf < 2; ++mf)
#pragma unroll
        for (int j = 0; j < 6; ++j) {
            int base = wn * 48 + j * 8;
            int reg = base >> 6;
            int col = (base & 63) + 2 * tig;
            int m = m0 + wm * 32 + mf * 16 + gid;
            uint32_t* oh = (reg == 0) ? (uint32_t*)g_Qhi
                         : (reg == 1) ? (uint32_t*)g_Khi : (uint32_t*)g_Vhi;
            uint32_t* ol = (reg == 0) ? (uint32_t*)g_Qlo
                         : (reg == 1) ? (uint32_t*)g_Klo : (uint32_t*)g_Vlo;
            float sc = (reg == 0) ? 1.44269504f : 1.f;
            uint32_t hi, lo;
            splitpack2(acc[mf][j][0] * sc, acc[mf][j][1] * sc, hi, lo);
            size_t o = ((size_t)m * HH + col) >> 1;
            oh[o] = hi; ol[o] = lo;
            splitpack2(acc[mf][j][2] * sc, acc[mf][j][3] * sc, hi, lo);
            o = ((size_t)(m + 8) * HH + col) >> 1;
            oh[o] = hi; ol[o] = lo;
        }
}

// ---------------------------------------------------------------------------
// K2 (pass1): D_s partials. Grid (32 s-tiles, 4 t-chunks, B), 128 threads
// (2m x 2n warps, warp tile 32x32, t-chunk step 64). 3 CTAs/SM.
// smem: Qh(8K) Ql(8K) Kh(8K) Kl(8K) red(512B) = 33280
// ---------------------------------------------------------------------------
__global__ void __launch_bounds__(128, 3) pass1_colsum()
{
    extern __shared__ char smem[];
    char* Qh = smem;
    char* Ql = smem + 8192;
    char* Kh = smem + 16384;
    char* Kl = smem + 24576;
    float* red = (float*)(smem + 32768);      // [2][64]
    const uint32_t sQh = smem_u32(Qh), sQl = sQh + 8192;
    const uint32_t sKh = sQh + 16384, sKl = sQh + 24576;

    const int tid = threadIdx.x, wid = tid >> 5, lane = tid & 31;
    const int wm = wid >> 1, wn = wid & 1;
    const int gid = lane >> 2, tig = lane & 3;
    const int s0 = blockIdx.x * 64;
    const int ch = blockIdx.y;
    const int b  = blockIdx.z;

    {   // K tile (persistent) 64x64 hi/lo
        const __nv_bfloat16* sh = g_Khi + ((size_t)b * TT + s0) * HH;
        const __nv_bfloat16* sl = g_Klo + ((size_t)b * TT + s0) * HH;
#pragma unroll
        for (int j = 0; j < 4; ++j) {
            int u = j * 128 + tid, r = u >> 3, q = u & 7;
            uint32_t off = swz(r * 128 + q * 16);
            *(uint4*)(Kh + off) = *(const uint4*)(sh + r * HH + q * 8);
            *(uint4*)(Kl + off) = *(const uint4*)(sl + r * HH + q * 8);
        }
    }

    float csum[4][2];
#pragma unroll
    for (int i = 0; i < 4; ++i) { csum[i][0] = 0.f; csum[i][1] = 0.f; }

    const int tbase = ch * 512;
    for (int t0 = tbase; t0 < tbase + 512; t0 += 64) {
        if (t0 + 64 <= s0) continue;
        {   // Q chunk 64x64 hi/lo
            const __nv_bfloat16* sh = g_Qhi + ((size_t)b * TT + t0) * HH;
            const __nv_bfloat16* sl = g_Qlo + ((size_t)b * TT + t0) * HH;
#pragma unroll
            for (int j = 0; j < 4; ++j) {
                int u = j * 128 + tid, r = u >> 3, q = u & 7;
                uint32_t off = swz(r * 128 + q * 16);
                *(uint4*)(Qh + off) = *(const uint4*)(sh + r * HH + q * 8);
                *(uint4*)(Ql + off) = *(const uint4*)(sl + r * HH + q * 8);
            }
        }
        __syncthreads();

        float acc[2][4][4];
#pragma unroll
        for (int i = 0; i < 2; ++i)
#pragma unroll
            for (int j = 0; j < 4; ++j)
#pragma unroll
                for (int k = 0; k < 4; ++k) acc[i][j][k] = 0.f;

#pragma unroll
        for (int ks = 0; ks < 4; ++ks) {
            const int kb = ks * 32;
            uint32_t ah0[4], ah1[4], al0[4], al1[4];
            lda(ah0, sQh, wm * 32, kb, lane);      lda(ah1, sQh, wm * 32 + 16, kb, lane);
            lda(al0, sQl, wm * 32, kb, lane);      lda(al1, sQl, wm * 32 + 16, kb, lane);
#pragma unroll
            for (int jp = 0; jp < 2; ++jp) {
                uint32_t bh[4], bl[4];
                ldb4(bh, sKh, wn * 32 + jp * 16, kb, lane);
                ldb4(bl, sKl, wn * 32 + jp * 16, kb, lane);
                mma2(acc[0][2 * jp], ah0, bh[0], bh[1]);
                mma2(acc[0][2 * jp], ah0, bl[0], bl[1]);
                mma2(acc[0][2 * jp], al0, bh[0], bh[1]);
                mma2(acc[1][2 * jp], ah1, bh[0], bh[1]);
                mma2(acc[1][2 * jp], ah1, bl[0], bl[1]);
                mma2(acc[1][2 * jp], al1, bh[0], bh[1]);
                mma2(acc[0][2 * jp + 1], ah0, bh[2], bh[3]);
                mma2(acc[0][2 * jp + 1], ah0, bl[2], bl[3]);
                mma2(acc[0][2 * jp + 1], al0, bh[2], bh[3]);
                mma2(acc[1][2 * jp + 1], ah1, bh[2], bh[3]);
                mma2(acc[1][2 * jp + 1], ah1, bl[2], bl[3]);
                mma2(acc[1][2 * jp + 1], al1, bh[2], bh[3]);
            }
        }

        // exp2 + (mask only on diagonal tile) + per-thread column sums
        if (t0 >= s0 + 64) {                 // fully unmasked tile
#pragma unroll
            for (int mf = 0; mf < 2; ++mf)
#pragma unroll
                for (int nf = 0; nf < 4; ++nf) {
                    csum[nf][0] += ex2(acc[mf][nf][0]) + ex2(acc[mf][nf][2]);
                    csum[nf][1] += ex2(acc[mf][nf][1]) + ex2(acc[mf][nf][3]);
                }
        } else {
#pragma unroll
            for (int mf = 0; mf < 2; ++mf) {
                int r0 = t0 + wm * 32 + mf * 16 + gid;
                int r1 = r0 + 8;
#pragma unroll
                for (int nf = 0; nf < 4; ++nf) {
                    int c = s0 + wn * 32 + nf * 8 + 2 * tig;
                    csum[nf][0] += ((r0 >= c) ? ex2(acc[mf][nf][0]) : 0.f)
                                 + ((r1 >= c) ? ex2(acc[mf][nf][2]) : 0.f);
                    csum[nf][1] += ((r0 >= c + 1) ? ex2(acc[mf][nf][1]) : 0.f)
                                 + ((r1 >= c + 1) ? ex2(acc[mf][nf][3]) : 0.f);
                }
            }
        }
        __syncthreads();
    }

#pragma unroll
    for (int nf = 0; nf < 4; ++nf)
#pragma unroll
        for (int d = 0; d < 2; ++d) {
            float v = csum[nf][d];
            v += __shfl_xor_sync(0xffffffffu, v, 4);
            v += __shfl_xor_sync(0xffffffffu, v, 8);
            v += __shfl_xor_sync(0xffffffffu, v, 16);
            if (lane < 4)
                red[wm * 64 + wn * 32 + nf * 8 + 2 * lane + d] = v;
        }
    __syncthreads();
    if (tid < 64)
        g_Dp[b][ch][s0 + tid] = red[tid] + red[64 + tid];
}

// ---------------------------------------------------------------------------
// K5 (pass2): fused S -> exp*rD -> O += P V. Grid (32 t-tiles, 4 s-splits, B).
// 128 threads (2m x 2n warps, warp tile 32x32, t-tile 64). 3 CTAs/SM.
// smem: Qh(8K) Ql(8K) Kh(8K) Kl(8K) Vh(8K) Vl(8K) rds(256B) = 49408
// ---------------------------------------------------------------------------
__global__ void __launch_bounds__(128, 3) pass2_fused()
{
    extern __shared__ char smem[];
    char* Qh = smem;
    char* Ql = smem + 8192;
    char* Kh = smem + 16384;
    char* Kl = smem + 24576;
    char* Vh = smem + 32768;
    char* Vl = smem + 40960;
    float* rds = (float*)(smem + 49152);    // [64]
    const uint32_t sQh = smem_u32(Qh), sQl = sQh + 8192;
    const uint32_t sKh = sQh + 16384, sKl = sQh + 24576;
    const uint32_t sVh = sQh + 32768, sVl = sQh + 40960;

    const int tid = threadIdx.x, wid = tid >> 5, lane = tid & 31;
    const int wm = wid >> 1, wn = wid & 1;
    const int gid = lane >> 2, tig = lane & 3;
    const int ti = 31 - blockIdx.x;             // heavy tiles first
    const int q4 = blockIdx.y;
    const int b  = blockIdx.z;
    const int t0 = ti * 64;
    const int nS = ti + 1;

    {   // Q tile (persistent) 64x64 hi/lo
        const __nv_bfloat16* sh = g_Qhi + ((size_t)b * TT + t0) * HH;
        const __nv_bfloat16* sl = g_Qlo + ((size_t)b * TT + t0) * HH;
#pragma unroll
        for (int j = 0; j < 4; ++j) {
            int u = j * 128 + tid, r = u >> 3, q = u & 7;
            uint32_t off = swz(r * 128 + q * 16);
            *(uint4*)(Qh + off) = *(const uint4*)(sh + r * HH + q * 8);
            *(uint4*)(Ql + off) = *(const uint4*)(sl + r * HH + q * 8);
        }
    }

    float O[2][8][4];
#pragma unroll
    for (int i = 0; i < 2; ++i)
#pragma unroll
        for (int j = 0; j < 8; ++j)
#pragma unroll
            for (int k = 0; k < 4; ++k) O[i][j][k] = 0.f;

    for (int si = q4; si < nS; si += 4) {
        const int s0 = si * 64;
        {
            const __nv_bfloat16* kh = g_Khi + ((size_t)b * TT + s0) * HH;
            const __nv_bfloat16* kl = g_Klo + ((size_t)b * TT + s0) * HH;
            const __nv_bfloat16* vh = g_Vhi + ((size_t)b * TT + s0) * HH;
            const __nv_bfloat16* vl = g_Vlo + ((size_t)b * TT + s0) * HH;
#pragma unroll
            for (int j = 0; j < 4; ++j) {
                int u = j * 128 + tid, r = u >> 3, q = u & 7;
                uint32_t off = swz(r * 128 + q * 16);
                *(uint4*)(Kh + off) = *(const uint4*)(kh + r * HH + q * 8);
                *(uint4*)(Kl + off) = *(const uint4*)(kl + r * HH + q * 8);
                *(uint4*)(Vh + off) = *(const uint4*)(vh + r * HH + q * 8);
                *(uint4*)(Vl + off) = *(const uint4*)(vl + r * HH + q * 8);
            }
        }
        if (tid < 64) {
            int s = s0 + tid;
            float d = g_Dp[b][0][s] + g_Dp[b][1][s] + g_Dp[b][2][s] + g_Dp[b][3][s];
            rds[tid] = 1.f / d;
        }
        __syncthreads();

        // --- S = Q K^T for this warp's 32x32 sub-tile ---
        float S[2][4][4];
#pragma unroll
        for (int i = 0; i < 2; ++i)
#pragma unroll
            for (int j = 0; j < 4; ++j)
#pragma unroll
                for (int k = 0; k < 4; ++k) S[i][j][k] = 0.f;

#pragma unroll
        for (int ks = 0; ks < 4; ++ks) {
            const int kb = ks * 32;
            uint32_t ah0[4], ah1[4], al0[4], al1[4];
            lda(ah0, sQh, wm * 32, kb, lane);      lda(ah1, sQh, wm * 32 + 16, kb, lane);
            lda(al0, sQl, wm * 32, kb, lane);      lda(al1, sQl, wm * 32 + 16, kb, lane);
#pragma unroll
            for (int jp = 0; jp < 2; ++jp) {
                uint32_t bh[4], bl[4];
                ldb4(bh, sKh, wn * 32 + jp * 16, kb, lane);
                ldb4(bl, sKl, wn * 32 + jp * 16, kb, lane);
                mma2(S[0][2 * jp], ah0, bh[0], bh[1]);
                mma2(S[0][2 * jp], ah0, bl[0], bl[1]);
                mma2(S[0][2 * jp], al0, bh[0], bh[1]);
                mma2(S[1][2 * jp], ah1, bh[0], bh[1]);
                mma2(S[1][2 * jp], ah1, bl[0], bl[1]);
                mma2(S[1][2 * jp], al1, bh[0], bh[1]);
                mma2(S[0][2 * jp + 1], ah0, bh[2], bh[3]);
                mma2(S[0][2 * jp + 1], ah0, bl[2], bl[3]);
                mma2(S[0][2 * jp + 1], al0, bh[2], bh[3]);
                mma2(S[1][2 * jp + 1], ah1, bh[2], bh[3]);
                mma2(S[1][2 * jp + 1], ah1, bl[2], bl[3]);
                mma2(S[1][2 * jp + 1], al1, bh[2], bh[3]);
            }
        }

        // --- P = exp2(S)*rD (masked on diagonal tile); regs feed PV mma ---
        const bool nomask = (si < ti);
#pragma unroll
        for (int kss = 0; kss < 2; ++kss) {
            uint32_t ph[2][4], pl[2][4];
            const int cb = wn * 32 + kss * 16 + 2 * tig;   // local col
            const float rA0 = rds[cb], rA1 = rds[cb + 1];
            const float rB0 = rds[cb + 8], rB1 = rds[cb + 9];
#pragma unroll
            for (int mf = 0; mf < 2; ++mf) {
                float* cL = S[mf][2 * kss];
                float* cR = S[mf][2 * kss + 1];
                float e0, e1;
                if (nomask) {
                    e0 = ex2(cL[0]) * rA0; e1 = ex2(cL[1]) * rA1;
                    splitpack2(e0, e1, ph[mf][0], pl[mf][0]);
                    e0 = ex2(cL[2]) * rA0; e1 = ex2(cL[3]) * rA1;
                    splitpack2(e0, e1, ph[mf][1], pl[mf][1]);
                    e0 = ex2(cR[0]) * rB0; e1 = ex2(cR[1]) * rB1;
                    splitpack2(e0, e1, ph[mf][2], pl[mf][2]);
                    e0 = ex2(cR[2]) * rB0; e1 = ex2(cR[3]) * rB1;
                    splitpack2(e0, e1, ph[mf][3], pl[mf][3]);
                } else {
                    int r0 = t0 + wm * 32 + mf * 16 + gid;
                    int r1 = r0 + 8;
                    int cA = s0 + cb;
                    int cB = cA + 8;
                    e0 = (r0 >= cA)     ? ex2(cL[0]) * rA0 : 0.f;
                    e1 = (r0 >= cA + 1) ? ex2(cL[1]) * rA1 : 0.f;
                    splitpack2(e0, e1, ph[mf][0], pl[mf][0]);
                    e0 = (r1 >= cA)     ? ex2(cL[2]) * rA0 : 0.f;
                    e1 = (r1 >= cA + 1) ? ex2(cL[3]) * rA1 : 0.f;
                    splitpack2(e0, e1, ph[mf][1], pl[mf][1]);
                    e0 = (r0 >= cB)     ? ex2(cR[0]) * rB0 : 0.f;
                    e1 = (r0 >= cB + 1) ? ex2(cR[1]) * rB1 : 0.f;
                    splitpack2(e0, e1, ph[mf][2], pl[mf][2]);
                    e0 = (r1 >= cB)     ? ex2(cR[2]) * rB0 : 0.f;
                    e1 = (r1 >= cB + 1) ? ex2(cR[3]) * rB1 : 0.f;
                    splitpack2(e0, e1, ph[mf][3], pl[mf][3]);
                }
            }
            const int ksel = wn * 32 + kss * 16;   // k (=s) element offset in V
#pragma unroll
            for (int jp = 0; jp < 4; ++jp) {
                uint32_t bh[4], bl[4];
                ldb4t(bh, sVh, jp * 16, ksel, lane);
                ldb4t(bl, sVl, jp * 16, ksel, lane);
                mma2(O[0][2 * jp], ph[0], bh[0], bh[1]);
                mma2(O[0][2 * jp], ph[0], bl[0], bl[1]);
                mma2(O[0][2 * jp], pl[0], bh[0], bh[1]);
                mma2(O[1][2 * jp], ph[1], bh[0], bh[1]);
                mma2(O[1][2 * jp], ph[1], bl[0], bl[1]);
                mma2(O[1][2 * jp], pl[1], bh[0], bh[1]);
                mma2(O[0][2 * jp + 1], ph[0], bh[2], bh[3]);
                mma2(O[0][2 * jp + 1], ph[0], bl[2], bl[3]);
                mma2(O[0][2 * jp + 1], pl[0], bh[2], bh[3]);
                mma2(O[1][2 * jp + 1], ph[1], bh[2], bh[3]);
                mma2(O[1][2 * jp + 1], ph[1], bl[2], bl[3]);
                mma2(O[1][2 * jp + 1], pl[1], bh[2], bh[3]);
            }
        }
        __syncthreads();
    }

    // --- epilogue: combine the two n-warps (wn 0/1) then write g_O4 ---
    float* Ob = g_O4[q4] + ((size_t)b * TT + t0) * HH;
    if (q4 < nS) {
        float* Ored = (float*)(smem + 16384);   // 64x64 floats (reuses K/V)
        if (wn == 0) {
#pragma unroll
            for (int mf = 0; mf < 2; ++mf)
#pragma unroll
                for (int nh = 0; nh < 8; ++nh) {
                    int r0 = wm * 32 + mf * 16 + gid;
                    int c  = nh * 8 + 2 * tig;
                    Ored[r0 * 64 + c]           = O[mf][nh][0];
                    Ored[r0 * 64 + c + 1]       = O[mf][nh][1];
                    Ored[(r0 + 8) * 64 + c]     = O[mf][nh][2];
                    Ored[(r0 + 8) * 64 + c + 1] = O[mf][nh][3];
                }
        }
        __syncthreads();
        if (wn == 1) {
#pragma unroll
            for (int mf = 0; mf < 2; ++mf)
#pragma unroll
                for (int nh = 0; nh < 8; ++nh) {
                    int r0 = wm * 32 + mf * 16 + gid;
                    int c  = nh * 8 + 2 * tig;
                    Ob[(size_t)r0 * HH + c]           = O[mf][nh][0] + Ored[r0 * 64 + c];
                    Ob[(size_t)r0 * HH + c + 1]       = O[mf][nh][1] + Ored[r0 * 64 + c + 1];
                    Ob[(size_t)(r0 + 8) * HH + c]     = O[mf][nh][2] + Ored[(r0 + 8) * 64 + c];
                    Ob[(size_t)(r0 + 8) * HH + c + 1] = O[mf][nh][3] + Ored[(r0 + 8) * 64 + c + 1];
                }
        }
    } else {
        for (int i = tid; i < 64 * HH; i += 128) Ob[i] = 0.f;
    }
}

// ---------------------------------------------------------------------------
// K6: final reduce of the 4 s-split partials
// ---------------------------------------------------------------------------
__global__ void __launch_bounds__(256) oreduce(float* __restrict__ out)
{
    int i = blockIdx.x * 256 + threadIdx.x;
    out[i] = g_O4[0][i] + g_O4[1][i] + g_O4[2][i] + g_O4[3][i];
}

// ---------------------------------------------------------------------------
// Launch
// ---------------------------------------------------------------------------
extern "C" void kernel_launch(void* const* d_in, const int* in_sizes, int n_in,
                              void* d_out, int out_size)
{
    (void)in_sizes; (void)n_in; (void)out_size;
    const float* idx = (const float*)d_in[0];
    const float* Wk  = (const float*)d_in[1];
    const float* Wq  = (const float*)d_in[2];
    const float* Wv  = (const float*)d_in[3];
    float* out = (float*)d_out;

    cudaFuncSetAttribute(proj_mma,     cudaFuncAttributeMaxDynamicSharedMemorySize, 65536);
    cudaFuncSetAttribute(pass1_colsum, cudaFuncAttributeMaxDynamicSharedMemorySize, 33280);
    cudaFuncSetAttribute(pass2_fused,  cudaFuncAttributeMaxDynamicSharedMemorySize, 49408);

    prep_w<<<768, 256>>>(Wk, Wq, Wv);
    proj_mma<<<256, 256, 65536>>>(idx);
    pass1_colsum<<<dim3(32, 4, BB), 128, 33280>>>();
    pass2_fused<<<dim3(32, 4, BB), 128, 49408>>>();
    oreduce<<<(BB * TT * HH) / 256, 256>>>(out);
}

// round 10
// speedup vs baseline: 2.5394x; 1.0342x over previous
#include <cuda_runtime.h>
#include <cuda_bf16.h>
#include <cstdint>
#include <cstddef>

#define BB 8
#define TT 2048
#define CC 1024
#define HH 64

// ---------------------------------------------------------------------------
// Scratch (device globals; no allocations allowed)
// ---------------------------------------------------------------------------
__device__ __nv_bfloat16 g_Whi[3 * HH * CC];     // [Wq;Wk;Wv] stacked, hi
__device__ __nv_bfloat16 g_Wlo[3 * HH * CC];     // lo
__device__ __nv_bfloat16 g_Qhi[BB * TT * HH];    // Q * log2(e), hi/lo
__device__ __nv_bfloat16 g_Qlo[BB * TT * HH];
__device__ __nv_bfloat16 g_Khi[BB * TT * HH];
__device__ __nv_bfloat16 g_Klo[BB * TT * HH];
__device__ __nv_bfloat16 g_Vhi[BB * TT * HH];    // V [s][h] hi/lo (unscaled)
__device__ __nv_bfloat16 g_Vlo[BB * TT * HH];
__device__ __nv_bfloat16 g_Vphi[BB * TT * HH];   // V' = V*rD [s][h] hi/lo
__device__ __nv_bfloat16 g_Vplo[BB * TT * HH];
__device__ __nv_bfloat16 g_Phi[(size_t)BB * TT * TT];  // P = exp2(S), hi (64MB)
__device__ __nv_bfloat16 g_Plo[(size_t)BB * TT * TT];  // lo (64MB)
__device__ float         g_Dp[BB][4][TT];        // colsum partials
__device__ float         g_O4[4][BB * TT * HH];  // 4-way split-s partial outputs

// ---------------------------------------------------------------------------
// Helpers (plain sm_80+ PTX, no 'a' features)
// ---------------------------------------------------------------------------
__device__ __forceinline__ uint32_t smem_u32(const void* p) {
    uint32_t r;
    asm("{ .reg .u64 t; cvta.to.shared.u64 t, %1; cvt.u32.u64 %0, t; }"
        : "=r"(r) : "l"(p));
    return r;
}
__device__ __forceinline__ uint32_t swz(uint32_t o) { return o ^ ((o >> 3) & 0x70); }

__device__ __forceinline__ void ldsm4(uint32_t (&r)[4], uint32_t addr) {
    asm volatile("ldmatrix.sync.aligned.m8n8.x4.shared.b16 {%0,%1,%2,%3}, [%4];"
                 : "=r"(r[0]), "=r"(r[1]), "=r"(r[2]), "=r"(r[3]) : "r"(addr));
}
__device__ __forceinline__ void ldsm4t(uint32_t (&r)[4], uint32_t addr) {
    asm volatile("ldmatrix.sync.aligned.m8n8.x4.trans.shared.b16 {%0,%1,%2,%3}, [%4];"
                 : "=r"(r[0]), "=r"(r[1]), "=r"(r[2]), "=r"(r[3]) : "r"(addr));
}
__device__ __forceinline__ void mma2(float (&c)[4], const uint32_t (&a)[4],
                                     uint32_t b0, uint32_t b1) {
    asm volatile(
        "mma.sync.aligned.m16n8k16.row.col.f32.bf16.bf16.f32 "
        "{%0,%1,%2,%3}, {%4,%5,%6,%7}, {%8,%9}, {%0,%1,%2,%3};"
        : "+f"(c[0]), "+f"(c[1]), "+f"(c[2]), "+f"(c[3])
        : "r"(a[0]), "r"(a[1]), "r"(a[2]), "r"(a[3]), "r"(b0), "r"(b1));
}
__device__ __forceinline__ float ex2(float x) {
    float y;
    asm("ex2.approx.f32 %0, %1;" : "=f"(y) : "f"(x));
    return y;
}

// A-fragment: 16x16 bf16, row-major tile rows = mr.., k-bytes = kb..kb+31
__device__ __forceinline__ void lda(uint32_t (&a)[4], uint32_t base, int mr,
                                    int kb, int lane) {
    ldsm4(a, base + swz(((mr + (lane & 15)) << 7) + kb + ((lane >> 4) << 4)));
}
// B-fragments for TWO n8 tiles (n16 x k16) from [n][k] row-major tile
__device__ __forceinline__ void ldb4(uint32_t (&b)[4], uint32_t base, int nr,
                                     int kb, int lane) {
    int row = nr + (lane & 7) + ((lane >> 4) << 3);
    int kx  = kb + (((lane >> 3) & 1) << 4);
    ldsm4(b, base + swz((row << 7) + kx));
}
// B-fragments for TWO n8 tiles from a [k][n] row-major tile via trans ldmatrix
__device__ __forceinline__ void ldb4t(uint32_t (&b)[4], uint32_t base, int nr,
                                      int ksel, int lane) {
    int row  = ksel + (lane & 7) + (((lane >> 3) & 1) << 3);
    int colb = nr * 2 + ((lane >> 4) << 4);
    ldsm4t(b, base + swz((row << 7) + colb));
}

__device__ __forceinline__ void split_bf16(float x, __nv_bfloat16& h, __nv_bfloat16& l) {
    h = __float2bfloat16(x);
    l = __float2bfloat16(x - __bfloat162float(h));
}
__device__ __forceinline__ void splitpack2(float x, float y, uint32_t& hi, uint32_t& lo) {
    __nv_bfloat16 hx, lx, hy, ly;
    split_bf16(x, hx, lx); split_bf16(y, hy, ly);
    __nv_bfloat162 H = __halves2bfloat162(hx, hy);
    __nv_bfloat162 L = __halves2bfloat162(lx, ly);
    hi = *(uint32_t*)&H; lo = *(uint32_t*)&L;
}

// ---------------------------------------------------------------------------
// K0: split weights once into stacked [192][1024] hi/lo (Q,K,V order)
// ---------------------------------------------------------------------------
__global__ void __launch_bounds__(256) prep_w(
    const float* __restrict__ Wk,
    const float* __restrict__ Wq,
    const float* __restrict__ Wv)
{
    int i = blockIdx.x * 256 + threadIdx.x;          // < 196608
    int w = i >> 16;
    int rem = i & 65535;
    const float* src = (w == 0) ? Wq : (w == 1) ? Wk : Wv;
    __nv_bfloat16 h, l;
    split_bf16(src[rem], h, l);
    g_Whi[i] = h; g_Wlo[i] = l;
}

// ---------------------------------------------------------------------------
// K1: QKV projection, fused. Grid 256 CTAs, 256 threads (2m x 4n warps).
// smem: Ah(8K) Al(8K) Wh(24K) Wl(24K) = 65536
// ---------------------------------------------------------------------------
__global__ void __launch_bounds__(256) proj_mma(const float* __restrict__ A)
{
    extern __shared__ char smem[];
    char* Ah = smem;
    char* Al = smem + 8192;
    char* Wh = smem + 16384;
    char* Wl = smem + 40960;
    const uint32_t sAh = smem_u32(Ah), sAl = sAh + 8192;
    const uint32_t sWh = sAh + 16384, sWl = sAh + 40960;

    const int tid = threadIdx.x, wid = tid >> 5, lane = tid & 31;
    const int wm = wid >> 2, wn = wid & 3;
    const int gid = lane >> 2, tig = lane & 3;
    const int m0 = blockIdx.x * 64;

    float acc[2][6][4];
#pragma unroll
    for (int i = 0; i < 2; ++i)
#pragma unroll
        for (int j = 0; j < 6; ++j)
#pragma unroll
            for (int k = 0; k < 4; ++k) acc[i][j][k] = 0.f;

    for (int ch = 0; ch < 16; ++ch) {
        const int c0 = ch * 64;
#pragma unroll
        for (int i = 0; i < 8; ++i) {
            int p = i * 256 + tid, r = p >> 5, cp = p & 31;
            float2 a = *(const float2*)&A[(size_t)(m0 + r) * CC + c0 + cp * 2];
            uint32_t hi, lo; splitpack2(a.x, a.y, hi, lo);
            uint32_t off = swz(r * 128 + cp * 4);
            *(uint32_t*)(Ah + off) = hi; *(uint32_t*)(Al + off) = lo;
        }
#pragma unroll
        for (int i = 0; i < 6; ++i) {
            int u = i * 256 + tid, r = u >> 3, q = u & 7;
            uint32_t off = swz(r * 128 + q * 16);
            *(uint4*)(Wh + off) = *(const uint4*)(g_Whi + (size_t)r * CC + c0 + q * 8);
            *(uint4*)(Wl + off) = *(const uint4*)(g_Wlo + (size_t)r * CC + c0 + q * 8);
        }
        __syncthreads();

#pragma unroll
        for (int ks = 0; ks < 4; ++ks) {
            const int kb = ks * 32;
            uint32_t ah0[4], ah1[4], al0[4], al1[4];
            lda(ah0, sAh, wm * 32, kb, lane);      lda(ah1, sAh, wm * 32 + 16, kb, lane);
            lda(al0, sAl, wm * 32, kb, lane);      lda(al1, sAl, wm * 32 + 16, kb, lane);
#pragma unroll
            for (int jp = 0; jp < 3; ++jp) {
                uint32_t bh[4], bl[4];
                ldb4(bh, sWh, wn * 48 + jp * 16, kb, lane);
                ldb4(bl, sWl, wn * 48 + jp * 16, kb, lane);
                mma2(acc[0][2 * jp], ah0, bh[0], bh[1]);
                mma2(acc[0][2 * jp], ah0, bl[0], bl[1]);
                mma2(acc[0][2 * jp], al0, bh[0], bh[1]);
                mma2(acc[1][2 * jp], ah1, bh[0], bh[1]);
                mma2(acc[1][2 * jp], ah1, bl[0], bl[1]);
                mma2(acc[1][2 * jp], al1, bh[0], bh[1]);
                mma2(acc[0][2 * jp + 1], ah0, bh[2], bh[3]);
                mma2(acc[0][2 * jp + 1], ah0, bl[2], bl[3]);
                mma2(acc[0][2 * jp + 1], al0, bh[2], bh[3]);
                mma2(acc[1][2 * jp + 1], ah1, bh[2], bh[3]);
                mma2(acc[1][2 * jp + 1], ah1, bl[2], bl[3]);
                mma2(acc[1][2 * jp + 1], al1, bh[2], bh[3]);
            }
        }
        __syncthreads();
    }

    // epilogue: cols 0-63 Q (x log2e), 64-127 K, 128-191 V — all split hi/lo
#pragma unroll
    for (int mf = 0; mf < 2; ++mf)
#pragma unroll
        for (int j = 0; j < 6; ++j) {
            int base = wn * 48 + j * 8;
            int reg = base >> 6;
            int col = (base & 63) + 2 * tig;
            int m = m0 + wm * 32 + mf * 16 + gid;
            uint32_t* oh = (reg == 0) ? (uint32_t*)g_Qhi
                         : (reg == 1) ? (uint32_t*)g_Khi : (uint32_t*)g_Vhi;
            uint32_t* ol = (reg == 0) ? (uint32_t*)g_Qlo
                         : (reg == 1) ? (uint32_t*)g_Klo : (uint32_t*)g_Vlo;
            float sc = (reg == 0) ? 1.44269504f : 1.f;
            uint32_t hi, lo;
            splitpack2(acc[mf][j][0] * sc, acc[mf][j][1] * sc, hi, lo);
            size_t o = ((size_t)m * HH + col) >> 1;
            oh[o] = hi; ol[o] = lo;
            splitpack2(acc[mf][j][2] * sc, acc[mf][j][3] * sc, hi, lo);
            o = ((size_t)(m + 8) * HH + col) >> 1;
            oh[o] = hi; ol[o] = lo;
        }
}

// ---------------------------------------------------------------------------
// K2 (pass1): S = QK^T once; P = exp2(S) stored hi/lo to gmem; colsum D
// partials. Grid (32 s-tiles, 4 t-chunks, B), 128 threads (2m x 2n warps,
// warp tile 32x32, t-chunk step 64). 3 CTAs/SM.
// smem: Qh(8K) Ql(8K) Kh(8K) Kl(8K) red(512B) Psh(8K) Psl(8K) = 49664
// ---------------------------------------------------------------------------
__global__ void __launch_bounds__(128, 3) pass1_colsum()
{
    extern __shared__ char smem[];
    char* Qh = smem;
    char* Ql = smem + 8192;
    char* Kh = smem + 16384;
    char* Kl = smem + 24576;
    float* red = (float*)(smem + 32768);      // [2][64]
    char* Psh = smem + 33280;
    char* Psl = smem + 41472;
    const uint32_t sQh = smem_u32(Qh), sQl = sQh + 8192;
    const uint32_t sKh = sQh + 16384, sKl = sQh + 24576;

    const int tid = threadIdx.x, wid = tid >> 5, lane = tid & 31;
    const int wm = wid >> 1, wn = wid & 1;
    const int gid = lane >> 2, tig = lane & 3;
    const int s0 = blockIdx.x * 64;
    const int ch = blockIdx.y;
    const int b  = blockIdx.z;

    {   // K tile (persistent) 64x64 hi/lo
        const __nv_bfloat16* sh = g_Khi + ((size_t)b * TT + s0) * HH;
        const __nv_bfloat16* sl = g_Klo + ((size_t)b * TT + s0) * HH;
#pragma unroll
        for (int j = 0; j < 4; ++j) {
            int u = j * 128 + tid, r = u >> 3, q = u & 7;
            uint32_t off = swz(r * 128 + q * 16);
            *(uint4*)(Kh + off) = *(const uint4*)(sh + r * HH + q * 8);
            *(uint4*)(Kl + off) = *(const uint4*)(sl + r * HH + q * 8);
        }
    }

    float csum[4][2];
#pragma unroll
    for (int i = 0; i < 4; ++i) { csum[i][0] = 0.f; csum[i][1] = 0.f; }

    const int tbase = ch * 512;
    for (int t0 = tbase; t0 < tbase + 512; t0 += 64) {
        if (t0 + 64 <= s0) continue;
        {   // Q chunk 64x64 hi/lo
            const __nv_bfloat16* sh = g_Qhi + ((size_t)b * TT + t0) * HH;
            const __nv_bfloat16* sl = g_Qlo + ((size_t)b * TT + t0) * HH;
#pragma unroll
            for (int j = 0; j < 4; ++j) {
                int u = j * 128 + tid, r = u >> 3, q = u & 7;
                uint32_t off = swz(r * 128 + q * 16);
                *(uint4*)(Qh + off) = *(const uint4*)(sh + r * HH + q * 8);
                *(uint4*)(Ql + off) = *(const uint4*)(sl + r * HH + q * 8);
            }
        }
        __syncthreads();

        float acc[2][4][4];
#pragma unroll
        for (int i = 0; i < 2; ++i)
#pragma unroll
            for (int j = 0; j < 4; ++j)
#pragma unroll
                for (int k = 0; k < 4; ++k) acc[i][j][k] = 0.f;

#pragma unroll
        for (int ks = 0; ks < 4; ++ks) {
            const int kb = ks * 32;
            uint32_t ah0[4], ah1[4], al0[4], al1[4];
            lda(ah0, sQh, wm * 32, kb, lane);      lda(ah1, sQh, wm * 32 + 16, kb, lane);
            lda(al0, sQl, wm * 32, kb, lane);      lda(al1, sQl, wm * 32 + 16, kb, lane);
#pragma unroll
            for (int jp = 0; jp < 2; ++jp) {
                uint32_t bh[4], bl[4];
                ldb4(bh, sKh, wn * 32 + jp * 16, kb, lane);
                ldb4(bl, sKl, wn * 32 + jp * 16, kb, lane);
                mma2(acc[0][2 * jp], ah0, bh[0], bh[1]);
                mma2(acc[0][2 * jp], ah0, bl[0], bl[1]);
                mma2(acc[0][2 * jp], al0, bh[0], bh[1]);
                mma2(acc[1][2 * jp], ah1, bh[0], bh[1]);
                mma2(acc[1][2 * jp], ah1, bl[0], bl[1]);
                mma2(acc[1][2 * jp], al1, bh[0], bh[1]);
                mma2(acc[0][2 * jp + 1], ah0, bh[2], bh[3]);
                mma2(acc[0][2 * jp + 1], ah0, bl[2], bl[3]);
                mma2(acc[0][2 * jp + 1], al0, bh[2], bh[3]);
                mma2(acc[1][2 * jp + 1], ah1, bh[2], bh[3]);
                mma2(acc[1][2 * jp + 1], ah1, bl[2], bl[3]);
                mma2(acc[1][2 * jp + 1], al1, bh[2], bh[3]);
            }
        }

        // exp2 + (mask only on diagonal tile) -> e; colsums
        float e[2][4][4];
        if (t0 >= s0 + 64) {
#pragma unroll
            for (int mf = 0; mf < 2; ++mf)
#pragma unroll
                for (int nf = 0; nf < 4; ++nf) {
                    e[mf][nf][0] = ex2(acc[mf][nf][0]);
                    e[mf][nf][1] = ex2(acc[mf][nf][1]);
                    e[mf][nf][2] = ex2(acc[mf][nf][2]);
                    e[mf][nf][3] = ex2(acc[mf][nf][3]);
                }
        } else {
#pragma unroll
            for (int mf = 0; mf < 2; ++mf) {
                int r0 = t0 + wm * 32 + mf * 16 + gid;
                int r1 = r0 + 8;
#pragma unroll
                for (int nf = 0; nf < 4; ++nf) {
                    int c = s0 + wn * 32 + nf * 8 + 2 * tig;
                    e[mf][nf][0] = (r0 >= c)     ? ex2(acc[mf][nf][0]) : 0.f;
                    e[mf][nf][1] = (r0 >= c + 1) ? ex2(acc[mf][nf][1]) : 0.f;
                    e[mf][nf][2] = (r1 >= c)     ? ex2(acc[mf][nf][2]) : 0.f;
                    e[mf][nf][3] = (r1 >= c + 1) ? ex2(acc[mf][nf][3]) : 0.f;
                }
            }
        }
#pragma unroll
        for (int mf = 0; mf < 2; ++mf)
#pragma unroll
            for (int nf = 0; nf < 4; ++nf) {
                csum[nf][0] += e[mf][nf][0] + e[mf][nf][2];
                csum[nf][1] += e[mf][nf][1] + e[mf][nf][3];
            }

        // stage P hi/lo into swizzled smem tile
        {
            int rloc = wm * 32 + gid;
#pragma unroll
            for (int mf = 0; mf < 2; ++mf)
#pragma unroll
                for (int nf = 0; nf < 4; ++nf) {
                    int c = wn * 32 + nf * 8 + 2 * tig;
                    uint32_t hi, lo;
                    splitpack2(e[mf][nf][0], e[mf][nf][1], hi, lo);
                    uint32_t off = swz((rloc + mf * 16) * 128 + c * 2);
                    *(uint32_t*)(Psh + off) = hi; *(uint32_t*)(Psl + off) = lo;
                    splitpack2(e[mf][nf][2], e[mf][nf][3], hi, lo);
                    off = swz((rloc + mf * 16 + 8) * 128 + c * 2);
                    *(uint32_t*)(Psh + off) = hi; *(uint32_t*)(Psl + off) = lo;
                }
        }
        __syncthreads();

        // coalesced copy-out to gmem
        {
            __nv_bfloat16* ph = g_Phi + ((size_t)b * TT + t0) * TT + s0;
            __nv_bfloat16* pl = g_Plo + ((size_t)b * TT + t0) * TT + s0;
#pragma unroll
            for (int j = 0; j < 4; ++j) {
                int u = j * 128 + tid, r = u >> 3, q = u & 7;
                uint32_t off = swz(r * 128 + q * 16);
                *(uint4*)(ph + (size_t)r * TT + q * 8) = *(const uint4*)(Psh + off);
                *(uint4*)(pl + (size_t)r * TT + q * 8) = *(const uint4*)(Psl + off);
            }
        }
    }

    __syncthreads();
#pragma unroll
    for (int nf = 0; nf < 4; ++nf)
#pragma unroll
        for (int d = 0; d < 2; ++d) {
            float v = csum[nf][d];
            v += __shfl_xor_sync(0xffffffffu, v, 4);
            v += __shfl_xor_sync(0xffffffffu, v, 8);
            v += __shfl_xor_sync(0xffffffffu, v, 16);
            if (lane < 4)
                red[wm * 64 + wn * 32 + nf * 8 + 2 * lane + d] = v;
        }
    __syncthreads();
    if (tid < 64)
        g_Dp[b][ch][s0 + tid] = red[tid] + red[64 + tid];
}

// ---------------------------------------------------------------------------
// K3: V' = V * rD, split hi/lo (folds the column normalizer into V)
// ---------------------------------------------------------------------------
__global__ void __launch_bounds__(256) vscale()
{
    int p = blockIdx.x * 256 + threadIdx.x;        // pair index < BB*TT*32
    int row = p >> 5;                              // b*TT + s
    int b = row >> 11, s = row & 2047;
    float d = g_Dp[b][0][s] + g_Dp[b][1][s] + g_Dp[b][2][s] + g_Dp[b][3][s];
    float rd = 1.f / d;
    uint32_t H = ((const uint32_t*)g_Vhi)[p];
    uint32_t L = ((const uint32_t*)g_Vlo)[p];
    __nv_bfloat162 h2 = *(__nv_bfloat162*)&H;
    __nv_bfloat162 l2 = *(__nv_bfloat162*)&L;
    float v0 = (__bfloat162float(h2.x) + __bfloat162float(l2.x)) * rd;
    float v1 = (__bfloat162float(h2.y) + __bfloat162float(l2.y)) * rd;
    uint32_t oh, ol; splitpack2(v0, v1, oh, ol);
    ((uint32_t*)g_Vphi)[p] = oh;
    ((uint32_t*)g_Vplo)[p] = ol;
}

// ---------------------------------------------------------------------------
// K4 (pass2): pure GEMM O += P V'. Grid (32 t-tiles, 4 s-splits, B).
// 128 threads (2m x 2n warps, warp tile 32x32 over t x h, k = s full 64).
// Each warp owns an exclusive output tile -> direct epilogue stores.
// smem: Ph(8K) Pl(8K) Vh(8K) Vl(8K) = 32768. 4 CTAs/SM.
// ---------------------------------------------------------------------------
__global__ void __launch_bounds__(128, 4) pass2_pv()
{
    extern __shared__ char smem[];
    char* Ph = smem;
    char* Pl = smem + 8192;
    char* Vh = smem + 16384;
    char* Vl = smem + 24576;
    const uint32_t sPh = smem_u32(Ph), sPl = sPh + 8192;
    const uint32_t sVh = sPh + 16384, sVl = sPh + 24576;

    const int tid = threadIdx.x, wid = tid >> 5, lane = tid & 31;
    const int wm = wid >> 1, wn = wid & 1;
    const int gid = lane >> 2, tig = lane & 3;
    const int ti = 31 - blockIdx.x;             // heavy tiles first
    const int q4 = blockIdx.y;
    const int b  = blockIdx.z;
    const int t0 = ti * 64;
    const int nS = ti + 1;

    float O[2][4][4];
#pragma unroll
    for (int i = 0; i < 2; ++i)
#pragma unroll
        for (int j = 0; j < 4; ++j)
#pragma unroll
            for (int k = 0; k < 4; ++k) O[i][j][k] = 0.f;

    for (int si = q4; si < nS; si += 4) {
        const int s0 = si * 64;
        {
            const __nv_bfloat16* ph = g_Phi + ((size_t)b * TT + t0) * TT + s0;
            const __nv_bfloat16* pl = g_Plo + ((size_t)b * TT + t0) * TT + s0;
            const __nv_bfloat16* vh = g_Vphi + ((size_t)b * TT + s0) * HH;
            const __nv_bfloat16* vl = g_Vplo + ((size_t)b * TT + s0) * HH;
#pragma unroll
            for (int j = 0; j < 4; ++j) {
                int u = j * 128 + tid, r = u >> 3, q = u & 7;
                uint32_t off = swz(r * 128 + q * 16);
                *(uint4*)(Ph + off) = *(const uint4*)(ph + (size_t)r * TT + q * 8);
                *(uint4*)(Pl + off) = *(const uint4*)(pl + (size_t)r * TT + q * 8);
                *(uint4*)(Vh + off) = *(const uint4*)(vh + r * HH + q * 8);
                *(uint4*)(Vl + off) = *(const uint4*)(vl + r * HH + q * 8);
            }
        }
        __syncthreads();

#pragma unroll
        for (int ks = 0; ks < 4; ++ks) {
            const int kb = ks * 32;
            uint32_t ah0[4], ah1[4], al0[4], al1[4];
            lda(ah0, sPh, wm * 32, kb, lane);      lda(ah1, sPh, wm * 32 + 16, kb, lane);
            lda(al0, sPl, wm * 32, kb, lane);      lda(al1, sPl, wm * 32 + 16, kb, lane);
#pragma unroll
            for (int jp = 0; jp < 2; ++jp) {
                uint32_t bh[4], bl[4];
                ldb4t(bh, sVh, wn * 32 + jp * 16, ks * 16, lane);
                ldb4t(bl, sVl, wn * 32 + jp * 16, ks * 16, lane);
                mma2(O[0][2 * jp], ah0, bh[0], bh[1]);
                mma2(O[0][2 * jp], ah0, bl[0], bl[1]);
                mma2(O[0][2 * jp], al0, bh[0], bh[1]);
                mma2(O[1][2 * jp], ah1, bh[0], bh[1]);
                mma2(O[1][2 * jp], ah1, bl[0], bl[1]);
                mma2(O[1][2 * jp], al1, bh[0], bh[1]);
                mma2(O[0][2 * jp + 1], ah0, bh[2], bh[3]);
                mma2(O[0][2 * jp + 1], ah0, bl[2], bl[3]);
                mma2(O[0][2 * jp + 1], al0, bh[2], bh[3]);
                mma2(O[1][2 * jp + 1], ah1, bh[2], bh[3]);
                mma2(O[1][2 * jp + 1], ah1, bl[2], bl[3]);
                mma2(O[1][2 * jp + 1], al1, bh[2], bh[3]);
            }
        }
        __syncthreads();
    }

    // epilogue: each warp owns rows (wm*32..+31) x cols (wn*32..+31)
    float* Ob = g_O4[q4] + ((size_t)b * TT + t0) * HH;
    if (q4 < nS) {
#pragma unroll
        for (int mf = 0; mf < 2; ++mf)
#pragma unroll
            for (int nh = 0; nh < 4; ++nh) {
                int r = wm * 32 + mf * 16 + gid;
                int c = wn * 32 + nh * 8 + 2 * tig;
                *(float2*)&Ob[(size_t)r * HH + c] =
                    make_float2(O[mf][nh][0], O[mf][nh][1]);
                *(float2*)&Ob[(size_t)(r + 8) * HH + c] =
                    make_float2(O[mf][nh][2], O[mf][nh][3]);
            }
    } else {
        for (int i = tid; i < 64 * HH; i += 128) Ob[i] = 0.f;
    }
}

// ---------------------------------------------------------------------------
// K6: final reduce of the 4 s-split partials
// ---------------------------------------------------------------------------
__global__ void __launch_bounds__(256) oreduce(float* __restrict__ out)
{
    int i = blockIdx.x * 256 + threadIdx.x;
    out[i] = g_O4[0][i] + g_O4[1][i] + g_O4[2][i] + g_O4[3][i];
}

// ---------------------------------------------------------------------------
// Launch
// ---------------------------------------------------------------------------
extern "C" void kernel_launch(void* const* d_in, const int* in_sizes, int n_in,
                              void* d_out, int out_size)
{
    (void)in_sizes; (void)n_in; (void)out_size;
    const float* idx = (const float*)d_in[0];
    const float* Wk  = (const float*)d_in[1];
    const float* Wq  = (const float*)d_in[2];
    const float* Wv  = (const float*)d_in[3];
    float* out = (float*)d_out;

    cudaFuncSetAttribute(proj_mma,     cudaFuncAttributeMaxDynamicSharedMemorySize, 65536);
    cudaFuncSetAttribute(pass1_colsum, cudaFuncAttributeMaxDynamicSharedMemorySize, 49664);
    cudaFuncSetAttribute(pass2_pv,     cudaFuncAttributeMaxDynamicSharedMemorySize, 32768);

    prep_w<<<768, 256>>>(Wk, Wq, Wv);
    proj_mma<<<256, 256, 65536>>>(idx);
    pass1_colsum<<<dim3(32, 4, BB), 128, 49664>>>();
    vscale<<<(BB * TT * HH / 2) / 256, 256>>>();
    pass2_pv<<<dim3(32, 4, BB), 128, 32768>>>();
    oreduce<<<(BB * TT * HH) / 256, 256>>>(out);
}

// round 11
// speedup vs baseline: 2.7471x; 1.0818x over previous
#include <cuda_runtime.h>
#include <cuda_bf16.h>
#include <cstdint>
#include <cstddef>

#define BB 8
#define TT 2048
#define CC 1024
#define HH 64

// ---------------------------------------------------------------------------
// Scratch (device globals; no allocations allowed)
// ---------------------------------------------------------------------------
__device__ __nv_bfloat16 g_Whi[3 * HH * CC];     // [Wq;Wk;Wv] stacked, hi
__device__ __nv_bfloat16 g_Wlo[3 * HH * CC];     // lo
__device__ __nv_bfloat16 g_Qhi[BB * TT * HH];    // Q * log2(e), hi/lo
__device__ __nv_bfloat16 g_Qlo[BB * TT * HH];
__device__ __nv_bfloat16 g_Khi[BB * TT * HH];
__device__ __nv_bfloat16 g_Klo[BB * TT * HH];
__device__ __nv_bfloat16 g_Vhi[BB * TT * HH];    // V [s][h] hi/lo (unscaled)
__device__ __nv_bfloat16 g_Vlo[BB * TT * HH];
__device__ __nv_bfloat16 g_Vphi[BB * TT * HH];   // V' = V*rD [s][h] hi/lo
__device__ __nv_bfloat16 g_Vplo[BB * TT * HH];
__device__ __nv_bfloat16 g_Phi[(size_t)BB * TT * TT];  // P = exp2(S), hi (64MB)
__device__ __nv_bfloat16 g_Plo[(size_t)BB * TT * TT];  // lo (64MB)
__device__ float         g_Dp[BB][4][TT];        // colsum partials
__device__ float         g_O4[4][BB * TT * HH];  // 4-way split-s partial outputs

// ---------------------------------------------------------------------------
// Helpers (plain sm_80+ PTX, no 'a' features)
// ---------------------------------------------------------------------------
__device__ __forceinline__ uint32_t smem_u32(const void* p) {
    uint32_t r;
    asm("{ .reg .u64 t; cvta.to.shared.u64 t, %1; cvt.u32.u64 %0, t; }"
        : "=r"(r) : "l"(p));
    return r;
}
__device__ __forceinline__ uint32_t swz(uint32_t o) { return o ^ ((o >> 3) & 0x70); }

__device__ __forceinline__ void ldsm4(uint32_t (&r)[4], uint32_t addr) {
    asm volatile("ldmatrix.sync.aligned.m8n8.x4.shared.b16 {%0,%1,%2,%3}, [%4];"
                 : "=r"(r[0]), "=r"(r[1]), "=r"(r[2]), "=r"(r[3]) : "r"(addr));
}
__device__ __forceinline__ void ldsm4t(uint32_t (&r)[4], uint32_t addr) {
    asm volatile("ldmatrix.sync.aligned.m8n8.x4.trans.shared.b16 {%0,%1,%2,%3}, [%4];"
                 : "=r"(r[0]), "=r"(r[1]), "=r"(r[2]), "=r"(r[3]) : "r"(addr));
}
__device__ __forceinline__ void mma2(float (&c)[4], const uint32_t (&a)[4],
                                     uint32_t b0, uint32_t b1) {
    asm volatile(
        "mma.sync.aligned.m16n8k16.row.col.f32.bf16.bf16.f32 "
        "{%0,%1,%2,%3}, {%4,%5,%6,%7}, {%8,%9}, {%0,%1,%2,%3};"
        : "+f"(c[0]), "+f"(c[1]), "+f"(c[2]), "+f"(c[3])
        : "r"(a[0]), "r"(a[1]), "r"(a[2]), "r"(a[3]), "r"(b0), "r"(b1));
}
__device__ __forceinline__ float ex2(float x) {
    float y;
    asm("ex2.approx.f32 %0, %1;" : "=f"(y) : "f"(x));
    return y;
}
__device__ __forceinline__ void cp16(uint32_t dst, const void* src) {
    asm volatile("cp.async.cg.shared.global [%0], [%1], 16;"
                 :: "r"(dst), "l"(src));
}
#define CP_COMMIT() asm volatile("cp.async.commit_group;" ::: "memory")
#define CP_WAIT1()  asm volatile("cp.async.wait_group 1;" ::: "memory")

// A-fragment: 16x16 bf16, row-major tile rows = mr.., k-bytes = kb..kb+31
__device__ __forceinline__ void lda(uint32_t (&a)[4], uint32_t base, int mr,
                                    int kb, int lane) {
    ldsm4(a, base + swz(((mr + (lane & 15)) << 7) + kb + ((lane >> 4) << 4)));
}
// B-fragments for TWO n8 tiles (n16 x k16) from [n][k] row-major tile
__device__ __forceinline__ void ldb4(uint32_t (&b)[4], uint32_t base, int nr,
                                     int kb, int lane) {
    int row = nr + (lane & 7) + ((lane >> 4) << 3);
    int kx  = kb + (((lane >> 3) & 1) << 4);
    ldsm4(b, base + swz((row << 7) + kx));
}
// B-fragments for TWO n8 tiles from a [k][n] row-major tile via trans ldmatrix
__device__ __forceinline__ void ldb4t(uint32_t (&b)[4], uint32_t base, int nr,
                                      int ksel, int lane) {
    int row  = ksel + (lane & 7) + (((lane >> 3) & 1) << 3);
    int colb = nr * 2 + ((lane >> 4) << 4);
    ldsm4t(b, base + swz((row << 7) + colb));
}

__device__ __forceinline__ void split_bf16(float x, __nv_bfloat16& h, __nv_bfloat16& l) {
    h = __float2bfloat16(x);
    l = __float2bfloat16(x - __bfloat162float(h));
}
__device__ __forceinline__ void splitpack2(float x, float y, uint32_t& hi, uint32_t& lo) {
    __nv_bfloat16 hx, lx, hy, ly;
    split_bf16(x, hx, lx); split_bf16(y, hy, ly);
    __nv_bfloat162 H = __halves2bfloat162(hx, hy);
    __nv_bfloat162 L = __halves2bfloat162(lx, ly);
    hi = *(uint32_t*)&H; lo = *(uint32_t*)&L;
}

// ---------------------------------------------------------------------------
// K0: split weights once into stacked [192][1024] hi/lo (Q,K,V order)
// ---------------------------------------------------------------------------
__global__ void __launch_bounds__(256) prep_w(
    const float* __restrict__ Wk,
    const float* __restrict__ Wq,
    const float* __restrict__ Wv)
{
    int i = blockIdx.x * 256 + threadIdx.x;          // < 196608
    int w = i >> 16;
    int rem = i & 65535;
    const float* src = (w == 0) ? Wq : (w == 1) ? Wk : Wv;
    __nv_bfloat16 h, l;
    split_bf16(src[rem], h, l);
    g_Whi[i] = h; g_Wlo[i] = l;
}

// ---------------------------------------------------------------------------
// K1: QKV projection, fused. Grid 256 CTAs, 256 threads (2m x 4n warps).
// smem: Ah(8K) Al(8K) Wh(24K) Wl(24K) = 65536
// ---------------------------------------------------------------------------
__global__ void __launch_bounds__(256) proj_mma(const float* __restrict__ A)
{
    extern __shared__ char smem[];
    char* Ah = smem;
    char* Al = smem + 8192;
    char* Wh = smem + 16384;
    char* Wl = smem + 40960;
    const uint32_t sAh = smem_u32(Ah), sAl = sAh + 8192;
    const uint32_t sWh = sAh + 16384, sWl = sAh + 40960;

    const int tid = threadIdx.x, wid = tid >> 5, lane = tid & 31;
    const int wm = wid >> 2, wn = wid & 3;
    const int gid = lane >> 2, tig = lane & 3;
    const int m0 = blockIdx.x * 64;

    float acc[2][6][4];
#pragma unroll
    for (int i = 0; i < 2; ++i)
#pragma unroll
        for (int j = 0; j < 6; ++j)
#pragma unroll
            for (int k = 0; k < 4; ++k) acc[i][j][k] = 0.f;

    for (int ch = 0; ch < 16; ++ch) {
        const int c0 = ch * 64;
#pragma unroll
        for (int i = 0; i < 8; ++i) {
            int p = i * 256 + tid, r = p >> 5, cp = p & 31;
            float2 a = *(const float2*)&A[(size_t)(m0 + r) * CC + c0 + cp * 2];
            uint32_t hi, lo; splitpack2(a.x, a.y, hi, lo);
            uint32_t off = swz(r * 128 + cp * 4);
            *(uint32_t*)(Ah + off) = hi; *(uint32_t*)(Al + off) = lo;
        }
#pragma unroll
        for (int i = 0; i < 6; ++i) {
            int u = i * 256 + tid, r = u >> 3, q = u & 7;
            uint32_t off = swz(r * 128 + q * 16);
            *(uint4*)(Wh + off) = *(const uint4*)(g_Whi + (size_t)r * CC + c0 + q * 8);
            *(uint4*)(Wl + off) = *(const uint4*)(g_Wlo + (size_t)r * CC + c0 + q * 8);
        }
        __syncthreads();

#pragma unroll
        for (int ks = 0; ks < 4; ++ks) {
            const int kb = ks * 32;
            uint32_t ah0[4], ah1[4], al0[4], al1[4];
            lda(ah0, sAh, wm * 32, kb, lane);      lda(ah1, sAh, wm * 32 + 16, kb, lane);
            lda(al0, sAl, wm * 32, kb, lane);      lda(al1, sAl, wm * 32 + 16, kb, lane);
#pragma unroll
            for (int jp = 0; jp < 3; ++jp) {
                uint32_t bh[4], bl[4];
                ldb4(bh, sWh, wn * 48 + jp * 16, kb, lane);
                ldb4(bl, sWl, wn * 48 + jp * 16, kb, lane);
                mma2(acc[0][2 * jp], ah0, bh[0], bh[1]);
                mma2(acc[0][2 * jp], ah0, bl[0], bl[1]);
                mma2(acc[0][2 * jp], al0, bh[0], bh[1]);
                mma2(acc[1][2 * jp], ah1, bh[0], bh[1]);
                mma2(acc[1][2 * jp], ah1, bl[0], bl[1]);
                mma2(acc[1][2 * jp], al1, bh[0], bh[1]);
                mma2(acc[0][2 * jp + 1], ah0, bh[2], bh[3]);
                mma2(acc[0][2 * jp + 1], ah0, bl[2], bl[3]);
                mma2(acc[0][2 * jp + 1], al0, bh[2], bh[3]);
                mma2(acc[1][2 * jp + 1], ah1, bh[2], bh[3]);
                mma2(acc[1][2 * jp + 1], ah1, bl[2], bl[3]);
                mma2(acc[1][2 * jp + 1], al1, bh[2], bh[3]);
            }
        }
        __syncthreads();
    }

    // epilogue: cols 0-63 Q (x log2e), 64-127 K, 128-191 V — all split hi/lo
#pragma unroll
    for (int mf = 0; mf < 2; ++mf)
#pragma unroll
        for (int j = 0; j < 6; ++j) {
            int base = wn * 48 + j * 8;
            int reg = base >> 6;
            int col = (base & 63) + 2 * tig;
            int m = m0 + wm * 32 + mf * 16 + gid;
            uint32_t* oh = (reg == 0) ? (uint32_t*)g_Qhi
                         : (reg == 1) ? (uint32_t*)g_Khi : (uint32_t*)g_Vhi;
            uint32_t* ol = (reg == 0) ? (uint32_t*)g_Qlo
                         : (reg == 1) ? (uint32_t*)g_Klo : (uint32_t*)g_Vlo;
            float sc = (reg == 0) ? 1.44269504f : 1.f;
            uint32_t hi, lo;
            splitpack2(acc[mf][j][0] * sc, acc[mf][j][1] * sc, hi, lo);
            size_t o = ((size_t)m * HH + col) >> 1;
            oh[o] = hi; ol[o] = lo;
            splitpack2(acc[mf][j][2] * sc, acc[mf][j][3] * sc, hi, lo);
            o = ((size_t)(m + 8) * HH + col) >> 1;
            oh[o] = hi; ol[o] = lo;
        }
}

// ---------------------------------------------------------------------------
// K2 (pass1): S = QK^T once; P = exp2(S) stored hi/lo to gmem; colsum D
// partials. Grid (32 s-tiles, 4 t-chunks, B), 128 threads (2m x 2n warps).
// cp.async double-buffered Q chunks. 3 CTAs/SM.
// smem: Kh/Kl(16K) Qstage0(16K) Qstage1(16K) Ps(16K) red(512B) = 66048
// ---------------------------------------------------------------------------
__global__ void __launch_bounds__(128, 3) pass1_colsum()
{
    extern __shared__ char smem[];
    char* Kh = smem;                          // 8K
    char* Kl = smem + 8192;                   // 8K
    char* Psh = smem + 49152;                 // 8K
    char* Psl = smem + 57344;                 // 8K
    float* red = (float*)(smem + 65536);      // [2][64]
    const uint32_t sb = smem_u32(smem);
    const uint32_t sKh = sb, sKl = sb + 8192;

    const int tid = threadIdx.x, wid = tid >> 5, lane = tid & 31;
    const int wm = wid >> 1, wn = wid & 1;
    const int gid = lane >> 2, tig = lane & 3;
    const int s0 = blockIdx.x * 64;
    const int ch = blockIdx.y;
    const int b  = blockIdx.z;

    {   // K tile (persistent) 64x64 hi/lo
        const __nv_bfloat16* sh = g_Khi + ((size_t)b * TT + s0) * HH;
        const __nv_bfloat16* sl = g_Klo + ((size_t)b * TT + s0) * HH;
#pragma unroll
        for (int j = 0; j < 4; ++j) {
            int u = j * 128 + tid, r = u >> 3, q = u & 7;
            uint32_t off = swz(r * 128 + q * 16);
            *(uint4*)(Kh + off) = *(const uint4*)(sh + r * HH + q * 8);
            *(uint4*)(Kl + off) = *(const uint4*)(sl + r * HH + q * 8);
        }
    }

    float csum[4][2];
#pragma unroll
    for (int i = 0; i < 4; ++i) { csum[i][0] = 0.f; csum[i][1] = 0.f; }

    const int tbase  = ch * 512;
    const int t_end  = tbase + 512;
    const int t_first = (tbase > s0) ? tbase : s0;

    auto issueQ = [&](int t0, int st) {
        const __nv_bfloat16* sh = g_Qhi + ((size_t)b * TT + t0) * HH;
        const __nv_bfloat16* sl = g_Qlo + ((size_t)b * TT + t0) * HH;
        uint32_t qb = sb + 16384 + st * 16384;
#pragma unroll
        for (int j = 0; j < 4; ++j) {
            int u = j * 128 + tid, r = u >> 3, q = u & 7;
            uint32_t off = swz(r * 128 + q * 16);
            cp16(qb + off,        sh + r * HH + q * 8);
            cp16(qb + 8192 + off, sl + r * HH + q * 8);
        }
    };

    if (t_first < t_end) issueQ(t_first, 0);
    CP_COMMIT();
    int stage = 0;

    for (int t0 = t_first; t0 < t_end; t0 += 64) {
        if (t0 + 64 < t_end) issueQ(t0 + 64, stage ^ 1);
        CP_COMMIT();
        CP_WAIT1();
        __syncthreads();

        const uint32_t sQh = sb + 16384 + stage * 16384;
        const uint32_t sQl = sQh + 8192;

        float acc[2][4][4];
#pragma unroll
        for (int i = 0; i < 2; ++i)
#pragma unroll
            for (int j = 0; j < 4; ++j)
#pragma unroll
                for (int k = 0; k < 4; ++k) acc[i][j][k] = 0.f;

#pragma unroll
        for (int ks = 0; ks < 4; ++ks) {
            const int kb = ks * 32;
            uint32_t ah0[4], ah1[4], al0[4], al1[4];
            lda(ah0, sQh, wm * 32, kb, lane);      lda(ah1, sQh, wm * 32 + 16, kb, lane);
            lda(al0, sQl, wm * 32, kb, lane);      lda(al1, sQl, wm * 32 + 16, kb, lane);
#pragma unroll
            for (int jp = 0; jp < 2; ++jp) {
                uint32_t bh[4], bl[4];
                ldb4(bh, sKh, wn * 32 + jp * 16, kb, lane);
                ldb4(bl, sKl, wn * 32 + jp * 16, kb, lane);
                mma2(acc[0][2 * jp], ah0, bh[0], bh[1]);
                mma2(acc[0][2 * jp], ah0, bl[0], bl[1]);
                mma2(acc[0][2 * jp], al0, bh[0], bh[1]);
                mma2(acc[1][2 * jp], ah1, bh[0], bh[1]);
                mma2(acc[1][2 * jp], ah1, bl[0], bl[1]);
                mma2(acc[1][2 * jp], al1, bh[0], bh[1]);
                mma2(acc[0][2 * jp + 1], ah0, bh[2], bh[3]);
                mma2(acc[0][2 * jp + 1], ah0, bl[2], bl[3]);
                mma2(acc[0][2 * jp + 1], al0, bh[2], bh[3]);
                mma2(acc[1][2 * jp + 1], ah1, bh[2], bh[3]);
                mma2(acc[1][2 * jp + 1], ah1, bl[2], bl[3]);
                mma2(acc[1][2 * jp + 1], al1, bh[2], bh[3]);
            }
        }

        // exp2 + (mask only on diagonal tile) -> e; colsums
        float e[2][4][4];
        if (t0 >= s0 + 64) {
#pragma unroll
            for (int mf = 0; mf < 2; ++mf)
#pragma unroll
                for (int nf = 0; nf < 4; ++nf) {
                    e[mf][nf][0] = ex2(acc[mf][nf][0]);
                    e[mf][nf][1] = ex2(acc[mf][nf][1]);
                    e[mf][nf][2] = ex2(acc[mf][nf][2]);
                    e[mf][nf][3] = ex2(acc[mf][nf][3]);
                }
        } else {
#pragma unroll
            for (int mf = 0; mf < 2; ++mf) {
                int r0 = t0 + wm * 32 + mf * 16 + gid;
                int r1 = r0 + 8;
#pragma unroll
                for (int nf = 0; nf < 4; ++nf) {
                    int c = s0 + wn * 32 + nf * 8 + 2 * tig;
                    e[mf][nf][0] = (r0 >= c)     ? ex2(acc[mf][nf][0]) : 0.f;
                    e[mf][nf][1] = (r0 >= c + 1) ? ex2(acc[mf][nf][1]) : 0.f;
                    e[mf][nf][2] = (r1 >= c)     ? ex2(acc[mf][nf][2]) : 0.f;
                    e[mf][nf][3] = (r1 >= c + 1) ? ex2(acc[mf][nf][3]) : 0.f;
                }
            }
        }
#pragma unroll
        for (int mf = 0; mf < 2; ++mf)
#pragma unroll
            for (int nf = 0; nf < 4; ++nf) {
                csum[nf][0] += e[mf][nf][0] + e[mf][nf][2];
                csum[nf][1] += e[mf][nf][1] + e[mf][nf][3];
            }

        // stage P hi/lo into swizzled smem tile
        {
            int rloc = wm * 32 + gid;
#pragma unroll
            for (int mf = 0; mf < 2; ++mf)
#pragma unroll
                for (int nf = 0; nf < 4; ++nf) {
                    int c = wn * 32 + nf * 8 + 2 * tig;
                    uint32_t hi, lo;
                    splitpack2(e[mf][nf][0], e[mf][nf][1], hi, lo);
                    uint32_t off = swz((rloc + mf * 16) * 128 + c * 2);
                    *(uint32_t*)(Psh + off) = hi; *(uint32_t*)(Psl + off) = lo;
                    splitpack2(e[mf][nf][2], e[mf][nf][3], hi, lo);
                    off = swz((rloc + mf * 16 + 8) * 128 + c * 2);
                    *(uint32_t*)(Psh + off) = hi; *(uint32_t*)(Psl + off) = lo;
                }
        }
        __syncthreads();

        // coalesced copy-out to gmem
        {
            __nv_bfloat16* ph = g_Phi + ((size_t)b * TT + t0) * TT + s0;
            __nv_bfloat16* pl = g_Plo + ((size_t)b * TT + t0) * TT + s0;
#pragma unroll
            for (int j = 0; j < 4; ++j) {
                int u = j * 128 + tid, r = u >> 3, q = u & 7;
                uint32_t off = swz(r * 128 + q * 16);
                *(uint4*)(ph + (size_t)r * TT + q * 8) = *(const uint4*)(Psh + off);
                *(uint4*)(pl + (size_t)r * TT + q * 8) = *(const uint4*)(Psl + off);
            }
        }
        stage ^= 1;
    }

    __syncthreads();
#pragma unroll
    for (int nf = 0; nf < 4; ++nf)
#pragma unroll
        for (int d = 0; d < 2; ++d) {
            float v = csum[nf][d];
            v += __shfl_xor_sync(0xffffffffu, v, 4);
            v += __shfl_xor_sync(0xffffffffu, v, 8);
            v += __shfl_xor_sync(0xffffffffu, v, 16);
            if (lane < 4)
                red[wm * 64 + wn * 32 + nf * 8 + 2 * lane + d] = v;
        }
    __syncthreads();
    if (tid < 64)
        g_Dp[b][ch][s0 + tid] = red[tid] + red[64 + tid];
}

// ---------------------------------------------------------------------------
// K3: V' = V * rD, split hi/lo (folds the column normalizer into V)
// ---------------------------------------------------------------------------
__global__ void __launch_bounds__(256) vscale()
{
    int p = blockIdx.x * 256 + threadIdx.x;        // pair index < BB*TT*32
    int row = p >> 5;                              // b*TT + s
    int b = row >> 11, s = row & 2047;
    float d = g_Dp[b][0][s] + g_Dp[b][1][s] + g_Dp[b][2][s] + g_Dp[b][3][s];
    float rd = 1.f / d;
    uint32_t H = ((const uint32_t*)g_Vhi)[p];
    uint32_t L = ((const uint32_t*)g_Vlo)[p];
    __nv_bfloat162 h2 = *(__nv_bfloat162*)&H;
    __nv_bfloat162 l2 = *(__nv_bfloat162*)&L;
    float v0 = (__bfloat162float(h2.x) + __bfloat162float(l2.x)) * rd;
    float v1 = (__bfloat162float(h2.y) + __bfloat162float(l2.y)) * rd;
    uint32_t oh, ol; splitpack2(v0, v1, oh, ol);
    ((uint32_t*)g_Vphi)[p] = oh;
    ((uint32_t*)g_Vplo)[p] = ol;
}

// ---------------------------------------------------------------------------
// K4 (pass2): pure GEMM O += P V'. Grid (32 t-tiles, 4 s-splits, B).
// 128 threads (2m x 2n warps, warp tile 32x32 over t x h, k = s full 64).
// cp.async double-buffered P+V tiles (32KB/stage x 2). 3 CTAs/SM.
// ---------------------------------------------------------------------------
__global__ void __launch_bounds__(128, 3) pass2_pv()
{
    extern __shared__ char smem[];
    const uint32_t sb = smem_u32(smem);

    const int tid = threadIdx.x, wid = tid >> 5, lane = tid & 31;
    const int wm = wid >> 1, wn = wid & 1;
    const int gid = lane >> 2, tig = lane & 3;
    const int ti = 31 - blockIdx.x;             // heavy tiles first
    const int q4 = blockIdx.y;
    const int b  = blockIdx.z;
    const int t0 = ti * 64;
    const int nS = ti + 1;

    auto issue = [&](int si, int st) {
        const int s0 = si * 64;
        const __nv_bfloat16* ph = g_Phi + ((size_t)b * TT + t0) * TT + s0;
        const __nv_bfloat16* pl = g_Plo + ((size_t)b * TT + t0) * TT + s0;
        const __nv_bfloat16* vh = g_Vphi + ((size_t)b * TT + s0) * HH;
        const __nv_bfloat16* vl = g_Vplo + ((size_t)b * TT + s0) * HH;
        uint32_t base = sb + st * 32768;
#pragma unroll
        for (int j = 0; j < 4; ++j) {
            int u = j * 128 + tid, r = u >> 3, q = u & 7;
            uint32_t off = swz(r * 128 + q * 16);
            cp16(base + off,         ph + (size_t)r * TT + q * 8);
            cp16(base + 8192 + off,  pl + (size_t)r * TT + q * 8);
            cp16(base + 16384 + off, vh + r * HH + q * 8);
            cp16(base + 24576 + off, vl + r * HH + q * 8);
        }
    };

    float O[2][4][4];
#pragma unroll
    for (int i = 0; i < 2; ++i)
#pragma unroll
        for (int j = 0; j < 4; ++j)
#pragma unroll
            for (int k = 0; k < 4; ++k) O[i][j][k] = 0.f;

    if (q4 < nS) issue(q4, 0);
    CP_COMMIT();
    int stage = 0;

    for (int si = q4; si < nS; si += 4) {
        if (si + 4 < nS) issue(si + 4, stage ^ 1);
        CP_COMMIT();
        CP_WAIT1();
        __syncthreads();

        const uint32_t sPh = sb + stage * 32768;
        const uint32_t sPl = sPh + 8192;
        const uint32_t sVh = sPh + 16384;
        const uint32_t sVl = sPh + 24576;

#pragma unroll
        for (int ks = 0; ks < 4; ++ks) {
            const int kb = ks * 32;
            uint32_t ah0[4], ah1[4], al0[4], al1[4];
            lda(ah0, sPh, wm * 32, kb, lane);      lda(ah1, sPh, wm * 32 + 16, kb, lane);
            lda(al0, sPl, wm * 32, kb, lane);      lda(al1, sPl, wm * 32 + 16, kb, lane);
#pragma unroll
            for (int jp = 0; jp < 2; ++jp) {
                uint32_t bh[4], bl[4];
                ldb4t(bh, sVh, wn * 32 + jp * 16, ks * 16, lane);
                ldb4t(bl, sVl, wn * 32 + jp * 16, ks * 16, lane);
                mma2(O[0][2 * jp], ah0, bh[0], bh[1]);
                mma2(O[0][2 * jp], ah0, bl[0], bl[1]);
                mma2(O[0][2 * jp], al0, bh[0], bh[1]);
                mma2(O[1][2 * jp], ah1, bh[0], bh[1]);
                mma2(O[1][2 * jp], ah1, bl[0], bl[1]);
                mma2(O[1][2 * jp], al1, bh[0], bh[1]);
                mma2(O[0][2 * jp + 1], ah0, bh[2], bh[3]);
                mma2(O[0][2 * jp + 1], ah0, bl[2], bl[3]);
                mma2(O[0][2 * jp + 1], al0, bh[2], bh[3]);
                mma2(O[1][2 * jp + 1], ah1, bh[2], bh[3]);
                mma2(O[1][2 * jp + 1], ah1, bl[2], bl[3]);
                mma2(O[1][2 * jp + 1], al1, bh[2], bh[3]);
            }
        }
        __syncthreads();
        stage ^= 1;
    }

    // epilogue: each warp owns rows (wm*32..+31) x cols (wn*32..+31)
    float* Ob = g_O4[q4] + ((size_t)b * TT + t0) * HH;
    if (q4 < nS) {
#pragma unroll
        for (int mf = 0; mf < 2; ++mf)
#pragma unroll
            for (int nh = 0; nh < 4; ++nh) {
                int r = wm * 32 + mf * 16 + gid;
                int c = wn * 32 + nh * 8 + 2 * tig;
                *(float2*)&Ob[(size_t)r * HH + c] =
                    make_float2(O[mf][nh][0], O[mf][nh][1]);
                *(float2*)&Ob[(size_t)(r + 8) * HH + c] =
                    make_float2(O[mf][nh][2], O[mf][nh][3]);
            }
    } else {
        for (int i = tid; i < 64 * HH; i += 128) Ob[i] = 0.f;
    }
}

// ---------------------------------------------------------------------------
// K6: final reduce of the 4 s-split partials
// ---------------------------------------------------------------------------
__global__ void __launch_bounds__(256) oreduce(float* __restrict__ out)
{
    int i = blockIdx.x * 256 + threadIdx.x;
    out[i] = g_O4[0][i] + g_O4[1][i] + g_O4[2][i] + g_O4[3][i];
}

// ---------------------------------------------------------------------------
// Launch
// ---------------------------------------------------------------------------
extern "C" void kernel_launch(void* const* d_in, const int* in_sizes, int n_in,
                              void* d_out, int out_size)
{
    (void)in_sizes; (void)n_in; (void)out_size;
    const float* idx = (const float*)d_in[0];
    const float* Wk  = (const float*)d_in[1];
    const float* Wq  = (const float*)d_in[2];
    const float* Wv  = (const float*)d_in[3];
    float* out = (float*)d_out;

    cudaFuncSetAttribute(proj_mma,     cudaFuncAttributeMaxDynamicSharedMemorySize, 65536);
    cudaFuncSetAttribute(pass1_colsum, cudaFuncAttributeMaxDynamicSharedMemorySize, 66048);
    cudaFuncSetAttribute(pass2_pv,     cudaFuncAttributeMaxDynamicSharedMemorySize, 65536);

    prep_w<<<768, 256>>>(Wk, Wq, Wv);
    proj_mma<<<256, 256, 65536>>>(idx);
    pass1_colsum<<<dim3(32, 4, BB), 128, 66048>>>();
    vscale<<<(BB * TT * HH / 2) / 256, 256>>>();
    pass2_pv<<<dim3(32, 4, BB), 128, 65536>>>();
    oreduce<<<(BB * TT * HH) / 256, 256>>>(out);
}

// round 13
// speedup vs baseline: 3.3144x; 1.2065x over previous
#include <cuda_runtime.h>
#include <cuda_bf16.h>
#include <cstdint>
#include <cstddef>

#define BB 8
#define TT 2048
#define CC 1024
#define HH 64

// ---------------------------------------------------------------------------
// Scratch (device globals; no allocations allowed)
// ---------------------------------------------------------------------------
__device__ __nv_bfloat16 g_Whi[3 * HH * CC];     // [Wq;Wk;Wv] stacked, hi
__device__ __nv_bfloat16 g_Wlo[3 * HH * CC];     // lo
__device__ __nv_bfloat16 g_Qhi[BB * TT * HH];    // Q * log2(e), hi/lo
__device__ __nv_bfloat16 g_Qlo[BB * TT * HH];
__device__ __nv_bfloat16 g_Khi[BB * TT * HH];
__device__ __nv_bfloat16 g_Klo[BB * TT * HH];
__device__ __nv_bfloat16 g_Vhi[BB * TT * HH];    // V [s][h] hi/lo (unscaled)
__device__ __nv_bfloat16 g_Vlo[BB * TT * HH];
__device__ __nv_bfloat16 g_Vphi[BB * TT * HH];   // V' = V*rD [s][h] hi/lo
__device__ __nv_bfloat16 g_Vplo[BB * TT * HH];
__device__ __nv_bfloat16 g_Phi[(size_t)BB * TT * TT];  // P = exp2(S), hi (64MB)
__device__ __nv_bfloat16 g_Plo[(size_t)BB * TT * TT];  // lo (64MB)
__device__ float         g_Dp[BB][4][TT];        // colsum partials
__device__ float         g_O4[4][BB * TT * HH];  // 4-way split-s partial outputs

// ---------------------------------------------------------------------------
// Helpers (plain sm_80+ PTX, no 'a' features)
// ---------------------------------------------------------------------------
__device__ __forceinline__ uint32_t smem_u32(const void* p) {
    uint32_t r;
    asm("{ .reg .u64 t; cvta.to.shared.u64 t, %1; cvt.u32.u64 %0, t; }"
        : "=r"(r) : "l"(p));
    return r;
}
__device__ __forceinline__ uint32_t swz(uint32_t o) { return o ^ ((o >> 3) & 0x70); }

__device__ __forceinline__ void ldsm4(uint32_t (&r)[4], uint32_t addr) {
    asm volatile("ldmatrix.sync.aligned.m8n8.x4.shared.b16 {%0,%1,%2,%3}, [%4];"
                 : "=r"(r[0]), "=r"(r[1]), "=r"(r[2]), "=r"(r[3]) : "r"(addr));
}
__device__ __forceinline__ void ldsm4t(uint32_t (&r)[4], uint32_t addr) {
    asm volatile("ldmatrix.sync.aligned.m8n8.x4.trans.shared.b16 {%0,%1,%2,%3}, [%4];"
                 : "=r"(r[0]), "=r"(r[1]), "=r"(r[2]), "=r"(r[3]) : "r"(addr));
}
__device__ __forceinline__ void mma2(float (&c)[4], const uint32_t (&a)[4],
                                     uint32_t b0, uint32_t b1) {
    asm volatile(
        "mma.sync.aligned.m16n8k16.row.col.f32.bf16.bf16.f32 "
        "{%0,%1,%2,%3}, {%4,%5,%6,%7}, {%8,%9}, {%0,%1,%2,%3};"
        : "+f"(c[0]), "+f"(c[1]), "+f"(c[2]), "+f"(c[3])
        : "r"(a[0]), "r"(a[1]), "r"(a[2]), "r"(a[3]), "r"(b0), "r"(b1));
}
__device__ __forceinline__ float ex2(float x) {
    float y;
    asm("ex2.approx.f32 %0, %1;" : "=f"(y) : "f"(x));
    return y;
}
__device__ __forceinline__ void cp16(uint32_t dst, const void* src) {
    asm volatile("cp.async.cg.shared.global [%0], [%1], 16;"
                 :: "r"(dst), "l"(src));
}
#define CP_COMMIT() asm volatile("cp.async.commit_group;" ::: "memory")
#define CP_WAIT1()  asm volatile("cp.async.wait_group 1;" ::: "memory")

// A-fragment: 16x16 bf16, row-major tile rows = mr.., k-bytes = kb..kb+31
__device__ __forceinline__ void lda(uint32_t (&a)[4], uint32_t base, int mr,
                                    int kb, int lane) {
    ldsm4(a, base + swz(((mr + (lane & 15)) << 7) + kb + ((lane >> 4) << 4)));
}
// B-fragments for TWO n8 tiles (n16 x k16) from [n][k] row-major tile
__device__ __forceinline__ void ldb4(uint32_t (&b)[4], uint32_t base, int nr,
                                     int kb, int lane) {
    int row = nr + (lane & 7) + ((lane >> 4) << 3);
    int kx  = kb + (((lane >> 3) & 1) << 4);
    ldsm4(b, base + swz((row << 7) + kx));
}
// B-fragments for TWO n8 tiles from a [k][n] row-major tile via trans ldmatrix
__device__ __forceinline__ void ldb4t(uint32_t (&b)[4], uint32_t base, int nr,
                                      int ksel, int lane) {
    int row  = ksel + (lane & 7) + (((lane >> 3) & 1) << 3);
    int colb = nr * 2 + ((lane >> 4) << 4);
    ldsm4t(b, base + swz((row << 7) + colb));
}

__device__ __forceinline__ void split_bf16(float x, __nv_bfloat16& h, __nv_bfloat16& l) {
    h = __float2bfloat16(x);
    l = __float2bfloat16(x - __bfloat162float(h));
}
// Fast pair split: hi = packed bf16(x,y); lo = packed bf16 of residuals.
// Bit-trick: H<<16 and H&0xFFFF0000 are exactly the rounded values as fp32.
__device__ __forceinline__ void splitpack2(float x, float y, uint32_t& hi, uint32_t& lo) {
    uint32_t H;
    asm("cvt.rn.bf16x2.f32 %0, %1, %2;" : "=r"(H) : "f"(y), "f"(x));
    float fx = __uint_as_float(H << 16);
    float fy = __uint_as_float(H & 0xFFFF0000u);
    uint32_t L;
    asm("cvt.rn.bf16x2.f32 %0, %1, %2;" : "=r"(L) : "f"(y - fy), "f"(x - fx));
    hi = H; lo = L;
}

// ---------------------------------------------------------------------------
// K0: split weights once into stacked [192][1024] hi/lo (Q,K,V order)
// ---------------------------------------------------------------------------
__global__ void __launch_bounds__(256) prep_w(
    const float* __restrict__ Wk,
    const float* __restrict__ Wq,
    const float* __restrict__ Wv)
{
    int i = blockIdx.x * 256 + threadIdx.x;          // < 196608
    int w = i >> 16;
    int rem = i & 65535;
    const float* src = (w == 0) ? Wq : (w == 1) ? Wk : Wv;
    __nv_bfloat16 h, l;
    split_bf16(src[rem], h, l);
    g_Whi[i] = h; g_Wlo[i] = l;
}

// ---------------------------------------------------------------------------
// K1: QKV projection, fused + pipelined. Grid 256 CTAs, 256 threads.
// A chunk prefetched in registers; W chunks cp.async double-buffered.
// smem: Ah(8K) Al(8K) Wst0(48K) Wst1(48K) = 114688
// ---------------------------------------------------------------------------
__global__ void __launch_bounds__(256) proj_mma(const float* __restrict__ A)
{
    extern __shared__ char smem[];
    char* Ah = smem;
    char* Al = smem + 8192;
    const uint32_t sb = smem_u32(smem);
    const uint32_t sAh = sb, sAl = sb + 8192;

    const int tid = threadIdx.x, wid = tid >> 5, lane = tid & 31;
    const int wm = wid >> 2, wn = wid & 3;
    const int gid = lane >> 2, tig = lane & 3;
    const int m0 = blockIdx.x * 64;

    auto issueW = [&](int ch, int st) {
        const int c0 = ch * 64;
        uint32_t base = sb + 16384 + st * 49152;
#pragma unroll
        for (int i = 0; i < 6; ++i) {
            int u = i * 256 + tid, r = u >> 3, q = u & 7;
            uint32_t off = swz(r * 128 + q * 16);
            cp16(base + off,         g_Whi + (size_t)r * CC + c0 + q * 8);
            cp16(base + 24576 + off, g_Wlo + (size_t)r * CC + c0 + q * 8);
        }
    };

    float2 aReg[8];
    auto loadA = [&](int ch) {
        const int c0 = ch * 64;
#pragma unroll
        for (int i = 0; i < 8; ++i) {
            int p = i * 256 + tid, r = p >> 5, cp = p & 31;
            aReg[i] = *(const float2*)&A[(size_t)(m0 + r) * CC + c0 + cp * 2];
        }
    };

    float acc[2][6][4];
#pragma unroll
    for (int i = 0; i < 2; ++i)
#pragma unroll
        for (int j = 0; j < 6; ++j)
#pragma unroll
            for (int k = 0; k < 4; ++k) acc[i][j][k] = 0.f;

    loadA(0);
    issueW(0, 0);
    CP_COMMIT();

    for (int ch = 0; ch < 16; ++ch) {
        // split current A chunk from registers into smem
#pragma unroll
        for (int i = 0; i < 8; ++i) {
            int p = i * 256 + tid, r = p >> 5, cp = p & 31;
            uint32_t hi, lo; splitpack2(aReg[i].x, aReg[i].y, hi, lo);
            uint32_t off = swz(r * 128 + cp * 4);
            *(uint32_t*)(Ah + off) = hi; *(uint32_t*)(Al + off) = lo;
        }
        if (ch < 15) issueW(ch + 1, (ch + 1) & 1);
        CP_COMMIT();            // (possibly empty group; FIFO retire keeps wait1 correct)
        CP_WAIT1();
        __syncthreads();
        if (ch < 15) loadA(ch + 1);   // prefetch next A chunk (latency under MMA)

        const uint32_t sWh = sb + 16384 + (ch & 1) * 49152;
        const uint32_t sWl = sWh + 24576;

#pragma unroll
        for (int ks = 0; ks < 4; ++ks) {
            const int kb = ks * 32;
            uint32_t ah0[4], ah1[4], al0[4], al1[4];
            lda(ah0, sAh, wm * 32, kb, lane);      lda(ah1, sAh, wm * 32 + 16, kb, lane);
            lda(al0, sAl, wm * 32, kb, lane);      lda(al1, sAl, wm * 32 + 16, kb, lane);
#pragma unroll
            for (int jp = 0; jp < 3; ++jp) {
                uint32_t bh[4], bl[4];
                ldb4(bh, sWh, wn * 48 + jp * 16, kb, lane);
                ldb4(bl, sWl, wn * 48 + jp * 16, kb, lane);
                mma2(acc[0][2 * jp], ah0, bh[0], bh[1]);
                mma2(acc[0][2 * jp], ah0, bl[0], bl[1]);
                mma2(acc[0][2 * jp], al0, bh[0], bh[1]);
                mma2(acc[1][2 * jp], ah1, bh[0], bh[1]);
                mma2(acc[1][2 * jp], ah1, bl[0], bl[1]);
                mma2(acc[1][2 * jp], al1, bh[0], bh[1]);
                mma2(acc[0][2 * jp + 1], ah0, bh[2], bh[3]);
                mma2(acc[0][2 * jp + 1], ah0, bl[2], bl[3]);
                mma2(acc[0][2 * jp + 1], al0, bh[2], bh[3]);
                mma2(acc[1][2 * jp + 1], ah1, bh[2], bh[3]);
                mma2(acc[1][2 * jp + 1], ah1, bl[2], bl[3]);
                mma2(acc[1][2 * jp + 1], al1, bh[2], bh[3]);
            }
        }
        __syncthreads();
    }

    // epilogue: cols 0-63 Q (x log2e), 64-127 K, 128-191 V — all split hi/lo
#pragma unroll
    for (int mf = 0; mf < 2; ++mf)
#pragma unroll
        for (int j = 0; j < 6; ++j) {
            int base = wn * 48 + j * 8;
            int reg = base >> 6;
            int col = (base & 63) + 2 * tig;
            int m = m0 + wm * 32 + mf * 16 + gid;
            uint32_t* oh = (reg == 0) ? (uint32_t*)g_Qhi
                         : (reg == 1) ? (uint32_t*)g_Khi : (uint32_t*)g_Vhi;
            uint32_t* ol = (reg == 0) ? (uint32_t*)g_Qlo
                         : (reg == 1) ? (uint32_t*)g_Klo : (uint32_t*)g_Vlo;
            float sc = (reg == 0) ? 1.44269504f : 1.f;
            uint32_t hi, lo;
            splitpack2(acc[mf][j][0] * sc, acc[mf][j][1] * sc, hi, lo);
            size_t o = ((size_t)m * HH + col) >> 1;
            oh[o] = hi; ol[o] = lo;
            splitpack2(acc[mf][j][2] * sc, acc[mf][j][3] * sc, hi, lo);
            o = ((size_t)(m + 8) * HH + col) >> 1;
            oh[o] = hi; ol[o] = lo;
        }
}

// ---------------------------------------------------------------------------
// K2 (pass1): S = QK^T once; P = exp2(S) stored hi/lo to gmem; colsum D
// partials. Grid (32 s-tiles, 4 t-chunks, B), 128 threads (2m x 2n warps).
// cp.async double-buffered Q chunks. 3 CTAs/SM.
// smem: Kh/Kl(16K) Qstage0(16K) Qstage1(16K) Ps(16K) red(512B) = 66048
// ---------------------------------------------------------------------------
__global__ void __launch_bounds__(128, 3) pass1_colsum()
{
    extern __shared__ char smem[];
    char* Kh = smem;                          // 8K
    char* Kl = smem + 8192;                   // 8K
    char* Psh = smem + 49152;                 // 8K
    char* Psl = smem + 57344;                 // 8K
    float* red = (float*)(smem + 65536);      // [2][64]
    const uint32_t sb = smem_u32(smem);
    const uint32_t sKh = sb, sKl = sb + 8192;

    const int tid = threadIdx.x, wid = tid >> 5, lane = tid & 31;
    const int wm = wid >> 1, wn = wid & 1;
    const int gid = lane >> 2, tig = lane & 3;
    const int s0 = blockIdx.x * 64;
    const int ch = blockIdx.y;
    const int b  = blockIdx.z;

    {   // K tile (persistent) 64x64 hi/lo
        const __nv_bfloat16* sh = g_Khi + ((size_t)b * TT + s0) * HH;
        const __nv_bfloat16* sl = g_Klo + ((size_t)b * TT + s0) * HH;
#pragma unroll
        for (int j = 0; j < 4; ++j) {
            int u = j * 128 + tid, r = u >> 3, q = u & 7;
            uint32_t off = swz(r * 128 + q * 16);
            *(uint4*)(Kh + off) = *(const uint4*)(sh + r * HH + q * 8);
            *(uint4*)(Kl + off) = *(const uint4*)(sl + r * HH + q * 8);
        }
    }

    float csum[4][2];
#pragma unroll
    for (int i = 0; i < 4; ++i) { csum[i][0] = 0.f; csum[i][1] = 0.f; }

    const int tbase  = ch * 512;
    const int t_end  = tbase + 512;
    const int t_first = (tbase > s0) ? tbase : s0;

    auto issueQ = [&](int t0, int st) {
        const __nv_bfloat16* sh = g_Qhi + ((size_t)b * TT + t0) * HH;
        const __nv_bfloat16* sl = g_Qlo + ((size_t)b * TT + t0) * HH;
        uint32_t qb = sb + 16384 + st * 16384;
#pragma unroll
        for (int j = 0; j < 4; ++j) {
            int u = j * 128 + tid, r = u >> 3, q = u & 7;
            uint32_t off = swz(r * 128 + q * 16);
            cp16(qb + off,        sh + r * HH + q * 8);
            cp16(qb + 8192 + off, sl + r * HH + q * 8);
        }
    };

    if (t_first < t_end) issueQ(t_first, 0);
    CP_COMMIT();
    int stage = 0;

    for (int t0 = t_first; t0 < t_end; t0 += 64) {
        if (t0 + 64 < t_end) issueQ(t0 + 64, stage ^ 1);
        CP_COMMIT();
        CP_WAIT1();
        __syncthreads();

        const uint32_t sQh = sb + 16384 + stage * 16384;
        const uint32_t sQl = sQh + 8192;

        float acc[2][4][4];
#pragma unroll
        for (int i = 0; i < 2; ++i)
#pragma unroll
            for (int j = 0; j < 4; ++j)
#pragma unroll
                for (int k = 0; k < 4; ++k) acc[i][j][k] = 0.f;

#pragma unroll
        for (int ks = 0; ks < 4; ++ks) {
            const int kb = ks * 32;
            uint32_t ah0[4], ah1[4], al0[4], al1[4];
            lda(ah0, sQh, wm * 32, kb, lane);      lda(ah1, sQh, wm * 32 + 16, kb, lane);
            lda(al0, sQl, wm * 32, kb, lane);      lda(al1, sQl, wm * 32 + 16, kb, lane);
#pragma unroll
            for (int jp = 0; jp < 2; ++jp) {
                uint32_t bh[4], bl[4];
                ldb4(bh, sKh, wn * 32 + jp * 16, kb, lane);
                ldb4(bl, sKl, wn * 32 + jp * 16, kb, lane);
                mma2(acc[0][2 * jp], ah0, bh[0], bh[1]);
                mma2(acc[0][2 * jp], ah0, bl[0], bl[1]);
                mma2(acc[0][2 * jp], al0, bh[0], bh[1]);
                mma2(acc[1][2 * jp], ah1, bh[0], bh[1]);
                mma2(acc[1][2 * jp], ah1, bl[0], bl[1]);
                mma2(acc[1][2 * jp], al1, bh[0], bh[1]);
                mma2(acc[0][2 * jp + 1], ah0, bh[2], bh[3]);
                mma2(acc[0][2 * jp + 1], ah0, bl[2], bl[3]);
                mma2(acc[0][2 * jp + 1], al0, bh[2], bh[3]);
                mma2(acc[1][2 * jp + 1], ah1, bh[2], bh[3]);
                mma2(acc[1][2 * jp + 1], ah1, bl[2], bl[3]);
                mma2(acc[1][2 * jp + 1], al1, bh[2], bh[3]);
            }
        }

        // exp2 + (mask only on diagonal tile) -> e; colsums
        float e[2][4][4];
        if (t0 >= s0 + 64) {
#pragma unroll
            for (int mf = 0; mf < 2; ++mf)
#pragma unroll
                for (int nf = 0; nf < 4; ++nf) {
                    e[mf][nf][0] = ex2(acc[mf][nf][0]);
                    e[mf][nf][1] = ex2(acc[mf][nf][1]);
                    e[mf][nf][2] = ex2(acc[mf][nf][2]);
                    e[mf][nf][3] = ex2(acc[mf][nf][3]);
                }
        } else {
#pragma unroll
            for (int mf = 0; mf < 2; ++mf) {
                int r0 = t0 + wm * 32 + mf * 16 + gid;
                int r1 = r0 + 8;
#pragma unroll
                for (int nf = 0; nf < 4; ++nf) {
                    int c = s0 + wn * 32 + nf * 8 + 2 * tig;
                    e[mf][nf][0] = (r0 >= c)     ? ex2(acc[mf][nf][0]) : 0.f;
                    e[mf][nf][1] = (r0 >= c + 1) ? ex2(acc[mf][nf][1]) : 0.f;
                    e[mf][nf][2] = (r1 >= c)     ? ex2(acc[mf][nf][2]) : 0.f;
                    e[mf][nf][3] = (r1 >= c + 1) ? ex2(acc[mf][nf][3]) : 0.f;
                }
            }
        }
#pragma unroll
        for (int mf = 0; mf < 2; ++mf)
#pragma unroll
            for (int nf = 0; nf < 4; ++nf) {
                csum[nf][0] += e[mf][nf][0] + e[mf][nf][2];
                csum[nf][1] += e[mf][nf][1] + e[mf][nf][3];
            }

        // stage P hi/lo into swizzled smem tile
        {
            int rloc = wm * 32 + gid;
#pragma unroll
            for (int mf = 0; mf < 2; ++mf)
#pragma unroll
                for (int nf = 0; nf < 4; ++nf) {
                    int c = wn * 32 + nf * 8 + 2 * tig;
                    uint32_t hi, lo;
                    splitpack2(e[mf][nf][0], e[mf][nf][1], hi, lo);
                    uint32_t off = swz((rloc + mf * 16) * 128 + c * 2);
                    *(uint32_t*)(Psh + off) = hi; *(uint32_t*)(Psl + off) = lo;
                    splitpack2(e[mf][nf][2], e[mf][nf][3], hi, lo);
                    off = swz((rloc + mf * 16 + 8) * 128 + c * 2);
                    *(uint32_t*)(Psh + off) = hi; *(uint32_t*)(Psl + off) = lo;
                }
        }
        __syncthreads();

        // coalesced copy-out to gmem
        {
            __nv_bfloat16* ph = g_Phi + ((size_t)b * TT + t0) * TT + s0;
            __nv_bfloat16* pl = g_Plo + ((size_t)b * TT + t0) * TT + s0;
#pragma unroll
            for (int j = 0; j < 4; ++j) {
                int u = j * 128 + tid, r = u >> 3, q = u & 7;
                uint32_t off = swz(r * 128 + q * 16);
                *(uint4*)(ph + (size_t)r * TT + q * 8) = *(const uint4*)(Psh + off);
                *(uint4*)(pl + (size_t)r * TT + q * 8) = *(const uint4*)(Psl + off);
            }
        }
        stage ^= 1;
    }

    __syncthreads();
#pragma unroll
    for (int nf = 0; nf < 4; ++nf)
#pragma unroll
        for (int d = 0; d < 2; ++d) {
            float v = csum[nf][d];
            v += __shfl_xor_sync(0xffffffffu, v, 4);
            v += __shfl_xor_sync(0xffffffffu, v, 8);
            v += __shfl_xor_sync(0xffffffffu, v, 16);
            if (lane < 4)
                red[wm * 64 + wn * 32 + nf * 8 + 2 * lane + d] = v;
        }
    __syncthreads();
    if (tid < 64)
        g_Dp[b][ch][s0 + tid] = red[tid] + red[64 + tid];
}

// ---------------------------------------------------------------------------
// K3: V' = V * rD, split hi/lo (folds the column normalizer into V)
// ---------------------------------------------------------------------------
__global__ void __launch_bounds__(256) vscale()
{
    int p = blockIdx.x * 256 + threadIdx.x;        // pair index < BB*TT*32
    int row = p >> 5;                              // b*TT + s
    int b = row >> 11, s = row & 2047;
    float d = g_Dp[b][0][s] + g_Dp[b][1][s] + g_Dp[b][2][s] + g_Dp[b][3][s];
    float rd = 1.f / d;
    uint32_t H = ((const uint32_t*)g_Vhi)[p];
    uint32_t L = ((const uint32_t*)g_Vlo)[p];
    __nv_bfloat162 h2 = *(__nv_bfloat162*)&H;
    __nv_bfloat162 l2 = *(__nv_bfloat162*)&L;
    float v0 = (__bfloat162float(h2.x) + __bfloat162float(l2.x)) * rd;
    float v1 = (__bfloat162float(h2.y) + __bfloat162float(l2.y)) * rd;
    uint32_t oh, ol; splitpack2(v0, v1, oh, ol);
    ((uint32_t*)g_Vphi)[p] = oh;
    ((uint32_t*)g_Vplo)[p] = ol;
}

// ---------------------------------------------------------------------------
// K4 (pass2): pure GEMM O += P V'. Grid (32 t-tiles, 4 s-splits, B).
// 128 threads (2m x 2n warps, warp tile 32x32 over t x h, k = s full 64).
// cp.async double-buffered P+V tiles (32KB/stage x 2). 3 CTAs/SM.
// ---------------------------------------------------------------------------
__global__ void __launch_bounds__(128, 3) pass2_pv()
{
    extern __shared__ char smem[];
    const uint32_t sb = smem_u32(smem);

    const int tid = threadIdx.x, wid = tid >> 5, lane = tid & 31;
    const int wm = wid >> 1, wn = wid & 1;
    const int gid = lane >> 2, tig = lane & 3;
    const int ti = 31 - blockIdx.x;             // heavy tiles first
    const int q4 = blockIdx.y;
    const int b  = blockIdx.z;
    const int t0 = ti * 64;
    const int nS = ti + 1;

    auto issue = [&](int si, int st) {
        const int s0 = si * 64;
        const __nv_bfloat16* ph = g_Phi + ((size_t)b * TT + t0) * TT + s0;
        const __nv_bfloat16* pl = g_Plo + ((size_t)b * TT + t0) * TT + s0;
        const __nv_bfloat16* vh = g_Vphi + ((size_t)b * TT + s0) * HH;
        const __nv_bfloat16* vl = g_Vplo + ((size_t)b * TT + s0) * HH;
        uint32_t base = sb + st * 32768;
#pragma unroll
        for (int j = 0; j < 4; ++j) {
            int u = j * 128 + tid, r = u >> 3, q = u & 7;
            uint32_t off = swz(r * 128 + q * 16);
            cp16(base + off,         ph + (size_t)r * TT + q * 8);
            cp16(base + 8192 + off,  pl + (size_t)r * TT + q * 8);
            cp16(base + 16384 + off, vh + r * HH + q * 8);
            cp16(base + 24576 + off, vl + r * HH + q * 8);
        }
    };

    float O[2][4][4];
#pragma unroll
    for (int i = 0; i < 2; ++i)
#pragma unroll
        for (int j = 0; j < 4; ++j)
#pragma unroll
            for (int k = 0; k < 4; ++k) O[i][j][k] = 0.f;

    if (q4 < nS) issue(q4, 0);
    CP_COMMIT();
    int stage = 0;

    for (int si = q4; si < nS; si += 4) {
        if (si + 4 < nS) issue(si + 4, stage ^ 1);
        CP_COMMIT();
        CP_WAIT1();
        __syncthreads();

        const uint32_t sPh = sb + stage * 32768;
        const uint32_t sPl = sPh + 8192;
        const uint32_t sVh = sPh + 16384;
        const uint32_t sVl = sPh + 24576;

#pragma unroll
        for (int ks = 0; ks < 4; ++ks) {
            const int kb = ks * 32;
            uint32_t ah0[4], ah1[4], al0[4], al1[4];
            lda(ah0, sPh, wm * 32, kb, lane);      lda(ah1, sPh, wm * 32 + 16, kb, lane);
            lda(al0, sPl, wm * 32, kb, lane);      lda(al1, sPl, wm * 32 + 16, kb, lane);
#pragma unroll
            for (int jp = 0; jp < 2; ++jp) {
                uint32_t bh[4], bl[4];
                ldb4t(bh, sVh, wn * 32 + jp * 16, ks * 16, lane);
                ldb4t(bl, sVl, wn * 32 + jp * 16, ks * 16, lane);
                mma2(O[0][2 * jp], ah0, bh[0], bh[1]);
                mma2(O[0][2 * jp], ah0, bl[0], bl[1]);
                mma2(O[0][2 * jp], al0, bh[0], bh[1]);
                mma2(O[1][2 * jp], ah1, bh[0], bh[1]);
                mma2(O[1][2 * jp], ah1, bl[0], bl[1]);
                mma2(O[1][2 * jp], al1, bh[0], bh[1]);
                mma2(O[0][2 * jp + 1], ah0, bh[2], bh[3]);
                mma2(O[0][2 * jp + 1], ah0, bl[2], bl[3]);
                mma2(O[0][2 * jp + 1], al0, bh[2], bh[3]);
                mma2(O[1][2 * jp + 1], ah1, bh[2], bh[3]);
                mma2(O[1][2 * jp + 1], ah1, bl[2], bl[3]);
                mma2(O[1][2 * jp + 1], al1, bh[2], bh[3]);
            }
        }
        __syncthreads();
        stage ^= 1;
    }

    // epilogue: each warp owns rows (wm*32..+31) x cols (wn*32..+31)
    float* Ob = g_O4[q4] + ((size_t)b * TT + t0) * HH;
    if (q4 < nS) {
#pragma unroll
        for (int mf = 0; mf < 2; ++mf)
#pragma unroll
            for (int nh = 0; nh < 4; ++nh) {
                int r = wm * 32 + mf * 16 + gid;
                int c = wn * 32 + nh * 8 + 2 * tig;
                *(float2*)&Ob[(size_t)r * HH + c] =
                    make_float2(O[mf][nh][0], O[mf][nh][1]);
                *(float2*)&Ob[(size_t)(r + 8) * HH + c] =
                    make_float2(O[mf][nh][2], O[mf][nh][3]);
            }
    } else {
        for (int i = tid; i < 64 * HH; i += 128) Ob[i] = 0.f;
    }
}

// ---------------------------------------------------------------------------
// K6: final reduce of the 4 s-split partials (float4 vectorized)
// ---------------------------------------------------------------------------
__global__ void __launch_bounds__(256) oreduce(float* __restrict__ out)
{
    int i = blockIdx.x * 256 + threadIdx.x;    // float4 index < BB*TT*HH/4
    float4 a = ((const float4*)g_O4[0])[i];
    float4 c = ((const float4*)g_O4[1])[i];
    float4 d = ((const float4*)g_O4[2])[i];
    float4 e = ((const float4*)g_O4[3])[i];
    ((float4*)out)[i] = make_float4(a.x + c.x + d.x + e.x,
                                    a.y + c.y + d.y + e.y,
                                    a.z + c.z + d.z + e.z,
                                    a.w + c.w + d.w + e.w);
}

// ---------------------------------------------------------------------------
// Launch
// ---------------------------------------------------------------------------
extern "C" void kernel_launch(void* const* d_in, const int* in_sizes, int n_in,
                              void* d_out, int out_size)
{
    (void)in_sizes; (void)n_in; (void)out_size;
    const float* idx = (const float*)d_in[0];
    const float* Wk  = (const float*)d_in[1];
    const float* Wq  = (const float*)d_in[2];
    const float* Wv  = (const float*)d_in[3];
    float* out = (float*)d_out;

    cudaFuncSetAttribute(proj_mma,     cudaFuncAttributeMaxDynamicSharedMemorySize, 114688);
    cudaFuncSetAttribute(pass1_colsum, cudaFuncAttributeMaxDynamicSharedMemorySize, 66048);
    cudaFuncSetAttribute(pass2_pv,     cudaFuncAttributeMaxDynamicSharedMemorySize, 65536);

    prep_w<<<768, 256>>>(Wk, Wq, Wv);
    proj_mma<<<256, 256, 114688>>>(idx);
    pass1_colsum<<<dim3(32, 4, BB), 128, 66048>>>();
    vscale<<<(BB * TT * HH / 2) / 256, 256>>>();
    pass2_pv<<<dim3(32, 4, BB), 128, 65536>>>();
    oreduce<<<(BB * TT * HH / 4) / 256, 256>>>(out);
}